// round 1
// baseline (speedup 1.0000x reference)
#include <cuda_runtime.h>
#include <math.h>

#define B 2
#define T 2048
#define C 1024
#define H 16
#define HD 64
#define M_TOT (B*T)   // 4096

// Scratch (no cudaMalloc allowed): 4 x 16 MB
__device__ float g_q[M_TOT*C];
__device__ float g_k[M_TOT*C];
__device__ float g_v[M_TOT*C];
__device__ float g_att[M_TOT*C];

// ---------------------------------------------------------------------------
// GEMM: Y = X @ W^T.  X: (M_TOT, C) row-major, W: (C, C) row-major.
// Both operands are K-contiguous -> coalesced float4 global loads.
// Tiles: 64x64x16, 256 threads, 4x4 accumulators per thread.
// smem stored K-major (transposed) so the inner loop reads contiguous float4.
// xsel: 0 -> Xext, 1 -> g_att.   ysel: 0/1/2 -> g_q/g_k/g_v, 3 -> Yext.
// ---------------------------------------------------------------------------
#define GBM 64
#define GBN 64
#define GBK 16

__global__ void __launch_bounds__(256) gemm_xwt(const float* __restrict__ Xext,
                                                const float* __restrict__ W,
                                                float* __restrict__ Yext,
                                                int xsel, int ysel) {
    const int N = C, K = C;
    const float* X = (xsel == 0) ? Xext : g_att;
    float* Y = (ysel == 0) ? g_q : (ysel == 1) ? g_k : (ysel == 2) ? g_v : Yext;

    __shared__ float As[GBK][GBM];
    __shared__ float Bs[GBK][GBN];

    int tid = threadIdx.x;
    int tx = tid & 15, ty = tid >> 4;
    int m0 = blockIdx.y * GBM, n0 = blockIdx.x * GBN;
    int lr = tid >> 2;          // 0..63 : tile row loaded by this thread
    int lc = (tid & 3) << 2;    // 0,4,8,12 : k offset (float4)

    float acc[4][4];
    #pragma unroll
    for (int i = 0; i < 4; i++)
        #pragma unroll
        for (int j = 0; j < 4; j++) acc[i][j] = 0.f;

    for (int k0 = 0; k0 < K; k0 += GBK) {
        float4 a = *(const float4*)&X[(size_t)(m0 + lr) * K + k0 + lc];
        float4 b = *(const float4*)&W[(size_t)(n0 + lr) * K + k0 + lc];
        As[lc + 0][lr] = a.x; As[lc + 1][lr] = a.y;
        As[lc + 2][lr] = a.z; As[lc + 3][lr] = a.w;
        Bs[lc + 0][lr] = b.x; Bs[lc + 1][lr] = b.y;
        Bs[lc + 2][lr] = b.z; Bs[lc + 3][lr] = b.w;
        __syncthreads();

        #pragma unroll
        for (int kk = 0; kk < GBK; kk++) {
            float4 av = *(const float4*)&As[kk][ty << 2];
            float4 bv = *(const float4*)&Bs[kk][tx << 2];
            float ar[4] = {av.x, av.y, av.z, av.w};
            float br[4] = {bv.x, bv.y, bv.z, bv.w};
            #pragma unroll
            for (int i = 0; i < 4; i++)
                #pragma unroll
                for (int j = 0; j < 4; j++)
                    acc[i][j] += ar[i] * br[j];
        }
        __syncthreads();
    }

    #pragma unroll
    for (int i = 0; i < 4; i++) {
        float4 o = {acc[i][0], acc[i][1], acc[i][2], acc[i][3]};
        *(float4*)&Y[(size_t)(m0 + (ty << 2) + i) * N + n0 + (tx << 2)] = o;
    }
}

// ---------------------------------------------------------------------------
// RoPE (interleaved pairs): applies in-place to g_q (sel=0) or g_k (sel=1).
// cos/sin: (T, HD/2).
// ---------------------------------------------------------------------------
__global__ void rope_kernel(const float* __restrict__ cosp,
                            const float* __restrict__ sinp, int sel) {
    float* t = (sel == 0) ? g_q : g_k;
    int idx = blockIdx.x * blockDim.x + threadIdx.x;   // B*T*H*HD/2 = 2^21
    int d  = idx & 31;            // 0..HD/2-1
    int h  = (idx >> 5) & 15;     // head
    int tp = (idx >> 9) & (T - 1);// position
    int b  = idx >> 20;           // batch
    size_t base = ((size_t)(b * T + tp)) * C + h * HD + 2 * d;
    float t0 = t[base], t1 = t[base + 1];
    float cc = cosp[tp * (HD / 2) + d];
    float ss = sinp[tp * (HD / 2) + d];
    t[base]     = t0 * cc - t1 * ss;
    t[base + 1] = t0 * ss + t1 * cc;
}

// ---------------------------------------------------------------------------
// Causal flash attention, fp32. Grid: (T/128, B*H). 128 threads, 1 query
// row per thread; q-row + output accumulator live in registers; K/V tiles
// (32 x 64) staged in smem (all lanes read the same address -> broadcast,
// conflict-free). Online softmax with rare-branch max-rescale.
// ---------------------------------------------------------------------------
#define ABM 128
#define ABN 32

__global__ void __launch_bounds__(ABM) attn_kernel() {
    __shared__ float Ks[ABN][HD];
    __shared__ float Vs[ABN][HD];

    int tid = threadIdx.x;
    int bh = blockIdx.y;
    int b = bh >> 4, h = bh & 15;
    int row = blockIdx.x * ABM + tid;

    size_t qoff = ((size_t)(b * T + row)) * C + h * HD;
    float qr[HD];
    #pragma unroll
    for (int c = 0; c < HD; c += 4) {
        float4 v = *(const float4*)&g_q[qoff + c];
        qr[c] = v.x; qr[c + 1] = v.y; qr[c + 2] = v.z; qr[c + 3] = v.w;
    }

    float m = -INFINITY, l = 0.f;
    float acc[HD];
    #pragma unroll
    for (int c = 0; c < HD; c++) acc[c] = 0.f;

    int nTiles = (blockIdx.x + 1) * (ABM / ABN);
    for (int t = 0; t < nTiles; t++) {
        // cooperative K/V tile load: 32 rows x 64 floats, float4-coalesced
        #pragma unroll
        for (int i = tid; i < ABN * HD / 4; i += ABM) {
            int s  = i >> 4;          // i / (HD/4)
            int c4 = (i & 15) << 2;
            int kg = t * ABN + s;
            size_t goff = ((size_t)(b * T + kg)) * C + h * HD + c4;
            *(float4*)&Ks[s][c4] = *(const float4*)&g_k[goff];
            *(float4*)&Vs[s][c4] = *(const float4*)&g_v[goff];
        }
        __syncthreads();

        #pragma unroll 4
        for (int s = 0; s < ABN; s++) {
            int kg = t * ABN + s;
            if (kg <= row) {
                float d0 = 0.f, d1 = 0.f, d2 = 0.f, d3 = 0.f;
                #pragma unroll
                for (int c = 0; c < HD; c += 4) {
                    float4 kv = *(const float4*)&Ks[s][c];
                    d0 += qr[c]     * kv.x;
                    d1 += qr[c + 1] * kv.y;
                    d2 += qr[c + 2] * kv.z;
                    d3 += qr[c + 3] * kv.w;
                }
                float sc = ((d0 + d1) + (d2 + d3)) * 0.125f;  // 1/sqrt(64)
                if (sc > m) {
                    float corr = __expf(m - sc);   // exp(-inf)=0 on first key
                    l *= corr;
                    #pragma unroll
                    for (int c = 0; c < HD; c++) acc[c] *= corr;
                    m = sc;
                }
                float p = __expf(sc - m);
                l += p;
                #pragma unroll
                for (int c = 0; c < HD; c += 4) {
                    float4 vv = *(const float4*)&Vs[s][c];
                    acc[c]     += p * vv.x;
                    acc[c + 1] += p * vv.y;
                    acc[c + 2] += p * vv.z;
                    acc[c + 3] += p * vv.w;
                }
            }
        }
        __syncthreads();
    }

    float inv = 1.f / l;
    size_t ooff = ((size_t)(b * T + row)) * C + h * HD;
    #pragma unroll
    for (int c = 0; c < HD; c += 4) {
        float4 o = {acc[c] * inv, acc[c + 1] * inv,
                    acc[c + 2] * inv, acc[c + 3] * inv};
        *(float4*)&g_att[ooff + c] = o;
    }
}

// ---------------------------------------------------------------------------
extern "C" void kernel_launch(void* const* d_in, const int* in_sizes, int n_in,
                              void* d_out, int out_size) {
    const float* x    = (const float*)d_in[0];
    const float* Wq   = (const float*)d_in[1];
    const float* Wk   = (const float*)d_in[2];
    const float* Wv   = (const float*)d_in[3];
    const float* Wo   = (const float*)d_in[4];
    const float* cosp = (const float*)d_in[5];
    const float* sinp = (const float*)d_in[6];
    float* out = (float*)d_out;

    dim3 gg(C / GBN, M_TOT / GBM);
    gemm_xwt<<<gg, 256>>>(x, Wq, nullptr, 0, 0);
    gemm_xwt<<<gg, 256>>>(x, Wk, nullptr, 0, 1);
    gemm_xwt<<<gg, 256>>>(x, Wv, nullptr, 0, 2);

    int rope_total = B * T * H * (HD / 2);
    rope_kernel<<<rope_total / 256, 256>>>(cosp, sinp, 0);
    rope_kernel<<<rope_total / 256, 256>>>(cosp, sinp, 1);

    dim3 ga(T / ABM, B * H);
    attn_kernel<<<ga, ABM>>>();

    gemm_xwt<<<gg, 256>>>(nullptr, Wo, out, 1, 3);
}

// round 2
// speedup vs baseline: 1.7169x; 1.7169x over previous
#include <cuda_runtime.h>
#include <math.h>
#include <stdint.h>

#define B 2
#define T 2048
#define C 1024
#define H 16
#define HD 64
#define M_TOT (B*T)   // 4096

// Scratch (no cudaMalloc allowed): 4 x 16 MB
__device__ float g_q[M_TOT*C];
__device__ float g_k[M_TOT*C];
__device__ float g_v[M_TOT*C];
__device__ float g_att[M_TOT*C];

// ---------------------------------------------------------------------------
// Tensor-core GEMM: Y = X @ W^T using mma.sync m16n8k8 tf32 with 3xTF32 split
// (a_hi*b_hi + a_lo*b_hi + a_hi*b_lo) for ~fp32 accuracy.
// X: (M_TOT, C) row-major. W: (C, C) row-major = B(K,N) col-major, so W rows
// load directly as the col-major B operand.
// Block tile: 128x64x16, 256 threads (8 warps as 4x2), warp tile 32x32.
// hi/lo split is done once at the global->smem stage.
// ---------------------------------------------------------------------------
#define BM 128
#define BN 64
#define BK 16
#define KP (BK + 4)   // padded stride -> conflict-free fragment LDS

__device__ __forceinline__ uint32_t f2tf32(float x) {
    uint32_t r;
    asm("cvt.rna.tf32.f32 %0, %1;" : "=r"(r) : "f"(x));
    return r;
}

__device__ __forceinline__ void mma_tf32(float* d, const uint32_t* a,
                                         const uint32_t* b) {
    asm volatile(
        "mma.sync.aligned.m16n8k8.row.col.f32.tf32.tf32.f32 "
        "{%0,%1,%2,%3}, {%4,%5,%6,%7}, {%8,%9}, {%0,%1,%2,%3};"
        : "+f"(d[0]), "+f"(d[1]), "+f"(d[2]), "+f"(d[3])
        : "r"(a[0]), "r"(a[1]), "r"(a[2]), "r"(a[3]), "r"(b[0]), "r"(b[1]));
}

__global__ void __launch_bounds__(256) gemm_xwt(const float* __restrict__ Xext,
                                                const float* __restrict__ W,
                                                float* __restrict__ Yext,
                                                int xsel, int ysel) {
    const int N = C, K = C;
    const float* X = (xsel == 0) ? Xext : g_att;
    float* Y = (ysel == 0) ? g_q : (ysel == 1) ? g_k : (ysel == 2) ? g_v : Yext;

    __shared__ uint32_t Ah[BM][KP], Al[BM][KP];
    __shared__ uint32_t Bh[BN][KP], Bl[BN][KP];

    const int tid  = threadIdx.x;
    const int lane = tid & 31;
    const int warp = tid >> 5;
    const int warpM = warp >> 1;       // 0..3
    const int warpN = warp & 1;        // 0..1
    const int grp = lane >> 2;         // 0..7
    const int tg  = lane & 3;          // 0..3

    const int m0 = blockIdx.y * BM;
    const int n0 = blockIdx.x * BN;

    float acc[2][4][4];
    #pragma unroll
    for (int mt = 0; mt < 2; mt++)
        #pragma unroll
        for (int nt = 0; nt < 4; nt++)
            #pragma unroll
            for (int i = 0; i < 4; i++) acc[mt][nt][i] = 0.f;

    // global-load index mapping (float4 granularity)
    // A: 128 rows x 4 float4 = 512 float4 -> 2 per thread
    const int arow0 = tid >> 1;               // using idx = tid, tid+256
    const int akq0  = (tid & 1) << 1;         // float4 pairs: kq = akq0, akq0+1? 
    // simpler: idx-based below.

    for (int k0 = 0; k0 < K; k0 += BK) {
        // ---- load global into regs ----
        float4 a0, a1, b0;
        {
            int idx = tid;              // A float4 #1
            int r = idx >> 2, kq = idx & 3;
            a0 = *(const float4*)&X[(size_t)(m0 + r) * K + k0 + kq * 4];
            idx = tid + 256;            // A float4 #2
            r = idx >> 2; kq = idx & 3;
            a1 = *(const float4*)&X[(size_t)(m0 + r) * K + k0 + kq * 4];
            int br = tid >> 2, bkq = tid & 3;   // B: 64 rows x 4 f4 = 256
            b0 = *(const float4*)&W[(size_t)(n0 + br) * K + k0 + bkq * 4];
        }
        __syncthreads();   // previous iteration's compute done
        // ---- split + store to smem ----
        {
            int idx = tid;
            int r = idx >> 2, kk = (idx & 3) * 4;
            float v[4] = {a0.x, a0.y, a0.z, a0.w};
            #pragma unroll
            for (int j = 0; j < 4; j++) {
                uint32_t hi = f2tf32(v[j]);
                Ah[r][kk + j] = hi;
                Al[r][kk + j] = f2tf32(v[j] - __uint_as_float(hi));
            }
            idx = tid + 256;
            r = idx >> 2; kk = (idx & 3) * 4;
            float w2[4] = {a1.x, a1.y, a1.z, a1.w};
            #pragma unroll
            for (int j = 0; j < 4; j++) {
                uint32_t hi = f2tf32(w2[j]);
                Ah[r][kk + j] = hi;
                Al[r][kk + j] = f2tf32(w2[j] - __uint_as_float(hi));
            }
            int br = tid >> 2, bkk = (tid & 3) * 4;
            float w3[4] = {b0.x, b0.y, b0.z, b0.w};
            #pragma unroll
            for (int j = 0; j < 4; j++) {
                uint32_t hi = f2tf32(w3[j]);
                Bh[br][bkk + j] = hi;
                Bl[br][bkk + j] = f2tf32(w3[j] - __uint_as_float(hi));
            }
        }
        __syncthreads();

        // ---- compute: 2 k-steps of 8 ----
        #pragma unroll
        for (int ks = 0; ks < BK; ks += 8) {
            uint32_t ah[2][4], al[2][4], bh[4][2], bl[4][2];
            #pragma unroll
            for (int mt = 0; mt < 2; mt++) {
                int rb = warpM * 32 + mt * 16;
                ah[mt][0] = Ah[rb + grp][ks + tg];
                ah[mt][1] = Ah[rb + grp + 8][ks + tg];
                ah[mt][2] = Ah[rb + grp][ks + tg + 4];
                ah[mt][3] = Ah[rb + grp + 8][ks + tg + 4];
                al[mt][0] = Al[rb + grp][ks + tg];
                al[mt][1] = Al[rb + grp + 8][ks + tg];
                al[mt][2] = Al[rb + grp][ks + tg + 4];
                al[mt][3] = Al[rb + grp + 8][ks + tg + 4];
            }
            #pragma unroll
            for (int nt = 0; nt < 4; nt++) {
                int cb = warpN * 32 + nt * 8;
                bh[nt][0] = Bh[cb + grp][ks + tg];
                bh[nt][1] = Bh[cb + grp][ks + tg + 4];
                bl[nt][0] = Bl[cb + grp][ks + tg];
                bl[nt][1] = Bl[cb + grp][ks + tg + 4];
            }
            #pragma unroll
            for (int mt = 0; mt < 2; mt++)
                #pragma unroll
                for (int nt = 0; nt < 4; nt++) {
                    mma_tf32(acc[mt][nt], ah[mt], bh[nt]);
                    mma_tf32(acc[mt][nt], al[mt], bh[nt]);
                    mma_tf32(acc[mt][nt], ah[mt], bl[nt]);
                }
        }
    }

    // ---- epilogue: 64-bit stores ----
    #pragma unroll
    for (int mt = 0; mt < 2; mt++) {
        #pragma unroll
        for (int nt = 0; nt < 4; nt++) {
            int row = m0 + warpM * 32 + mt * 16 + grp;
            int col = n0 + warpN * 32 + nt * 8 + tg * 2;
            float2 lo = {acc[mt][nt][0], acc[mt][nt][1]};
            float2 hi = {acc[mt][nt][2], acc[mt][nt][3]};
            *(float2*)&Y[(size_t)row * N + col] = lo;
            *(float2*)&Y[(size_t)(row + 8) * N + col] = hi;
        }
    }
}

// ---------------------------------------------------------------------------
// RoPE (interleaved pairs): applies in-place to g_q (sel=0) or g_k (sel=1).
// ---------------------------------------------------------------------------
__global__ void rope_kernel(const float* __restrict__ cosp,
                            const float* __restrict__ sinp, int sel) {
    float* t = (sel == 0) ? g_q : g_k;
    int idx = blockIdx.x * blockDim.x + threadIdx.x;
    int d  = idx & 31;
    int h  = (idx >> 5) & 15;
    int tp = (idx >> 9) & (T - 1);
    int b  = idx >> 20;
    size_t base = ((size_t)(b * T + tp)) * C + h * HD + 2 * d;
    float t0 = t[base], t1 = t[base + 1];
    float cc = cosp[tp * (HD / 2) + d];
    float ss = sinp[tp * (HD / 2) + d];
    t[base]     = t0 * cc - t1 * ss;
    t[base + 1] = t0 * ss + t1 * cc;
}

// ---------------------------------------------------------------------------
// Causal flash attention, fp32 scalar (unchanged from round 1).
// ---------------------------------------------------------------------------
#define ABM 128
#define ABN 32

__global__ void __launch_bounds__(ABM) attn_kernel() {
    __shared__ float Ks[ABN][HD];
    __shared__ float Vs[ABN][HD];

    int tid = threadIdx.x;
    int bh = blockIdx.y;
    int b = bh >> 4, h = bh & 15;
    int row = blockIdx.x * ABM + tid;

    size_t qoff = ((size_t)(b * T + row)) * C + h * HD;
    float qr[HD];
    #pragma unroll
    for (int c = 0; c < HD; c += 4) {
        float4 v = *(const float4*)&g_q[qoff + c];
        qr[c] = v.x; qr[c + 1] = v.y; qr[c + 2] = v.z; qr[c + 3] = v.w;
    }

    float m = -INFINITY, l = 0.f;
    float acc[HD];
    #pragma unroll
    for (int c = 0; c < HD; c++) acc[c] = 0.f;

    int nTiles = (blockIdx.x + 1) * (ABM / ABN);
    for (int t = 0; t < nTiles; t++) {
        #pragma unroll
        for (int i = tid; i < ABN * HD / 4; i += ABM) {
            int s  = i >> 4;
            int c4 = (i & 15) << 2;
            int kg = t * ABN + s;
            size_t goff = ((size_t)(b * T + kg)) * C + h * HD + c4;
            *(float4*)&Ks[s][c4] = *(const float4*)&g_k[goff];
            *(float4*)&Vs[s][c4] = *(const float4*)&g_v[goff];
        }
        __syncthreads();

        #pragma unroll 4
        for (int s = 0; s < ABN; s++) {
            int kg = t * ABN + s;
            if (kg <= row) {
                float d0 = 0.f, d1 = 0.f, d2 = 0.f, d3 = 0.f;
                #pragma unroll
                for (int c = 0; c < HD; c += 4) {
                    float4 kv = *(const float4*)&Ks[s][c];
                    d0 += qr[c]     * kv.x;
                    d1 += qr[c + 1] * kv.y;
                    d2 += qr[c + 2] * kv.z;
                    d3 += qr[c + 3] * kv.w;
                }
                float sc = ((d0 + d1) + (d2 + d3)) * 0.125f;
                if (sc > m) {
                    float corr = __expf(m - sc);
                    l *= corr;
                    #pragma unroll
                    for (int c = 0; c < HD; c++) acc[c] *= corr;
                    m = sc;
                }
                float p = __expf(sc - m);
                l += p;
                #pragma unroll
                for (int c = 0; c < HD; c += 4) {
                    float4 vv = *(const float4*)&Vs[s][c];
                    acc[c]     += p * vv.x;
                    acc[c + 1] += p * vv.y;
                    acc[c + 2] += p * vv.z;
                    acc[c + 3] += p * vv.w;
                }
            }
        }
        __syncthreads();
    }

    float inv = 1.f / l;
    size_t ooff = ((size_t)(b * T + row)) * C + h * HD;
    #pragma unroll
    for (int c = 0; c < HD; c += 4) {
        float4 o = {acc[c] * inv, acc[c + 1] * inv,
                    acc[c + 2] * inv, acc[c + 3] * inv};
        *(float4*)&g_att[ooff + c] = o;
    }
}

// ---------------------------------------------------------------------------
extern "C" void kernel_launch(void* const* d_in, const int* in_sizes, int n_in,
                              void* d_out, int out_size) {
    const float* x    = (const float*)d_in[0];
    const float* Wq   = (const float*)d_in[1];
    const float* Wk   = (const float*)d_in[2];
    const float* Wv   = (const float*)d_in[3];
    const float* Wo   = (const float*)d_in[4];
    const float* cosp = (const float*)d_in[5];
    const float* sinp = (const float*)d_in[6];
    float* out = (float*)d_out;

    dim3 gg(C / BN, M_TOT / BM);
    gemm_xwt<<<gg, 256>>>(x, Wq, nullptr, 0, 0);
    gemm_xwt<<<gg, 256>>>(x, Wk, nullptr, 0, 1);
    gemm_xwt<<<gg, 256>>>(x, Wv, nullptr, 0, 2);

    int rope_total = B * T * H * (HD / 2);
    rope_kernel<<<rope_total / 256, 256>>>(cosp, sinp, 0);
    rope_kernel<<<rope_total / 256, 256>>>(cosp, sinp, 1);

    dim3 ga(T / ABM, B * H);
    attn_kernel<<<ga, ABM>>>();

    gemm_xwt<<<gg, 256>>>(nullptr, Wo, out, 1, 3);
}

// round 3
// speedup vs baseline: 2.3839x; 1.3885x over previous
#include <cuda_runtime.h>
#include <math.h>
#include <stdint.h>

#define B 2
#define T 2048
#define C 1024
#define H 16
#define HD 64
#define M_TOT (B*T)   // 4096

// Scratch (no cudaMalloc allowed): 4 x 16 MB
__device__ float g_q[M_TOT*C];
__device__ float g_k[M_TOT*C];
__device__ float g_v[M_TOT*C];
__device__ float g_att[M_TOT*C];

// ---------------------------------------------------------------------------
// common mma helpers (mappings validated by round-2 GEMM @ rel_err 1.6e-5)
// ---------------------------------------------------------------------------
__device__ __forceinline__ uint32_t f2tf32(float x) {
    uint32_t r;
    asm("cvt.rna.tf32.f32 %0, %1;" : "=r"(r) : "f"(x));
    return r;
}

__device__ __forceinline__ void mma_tf32(float* d, const uint32_t* a,
                                         const uint32_t* b) {
    asm volatile(
        "mma.sync.aligned.m16n8k8.row.col.f32.tf32.tf32.f32 "
        "{%0,%1,%2,%3}, {%4,%5,%6,%7}, {%8,%9}, {%0,%1,%2,%3};"
        : "+f"(d[0]), "+f"(d[1]), "+f"(d[2]), "+f"(d[3])
        : "r"(a[0]), "r"(a[1]), "r"(a[2]), "r"(a[3]), "r"(b[0]), "r"(b[1]));
}

// ---------------------------------------------------------------------------
// Tensor-core GEMM: Y = X @ W^T, 3xTF32 split (unchanged from round 2).
// ---------------------------------------------------------------------------
#define BM 128
#define BN 64
#define BK 16
#define KP (BK + 4)

__global__ void __launch_bounds__(256) gemm_xwt(const float* __restrict__ Xext,
                                                const float* __restrict__ W,
                                                float* __restrict__ Yext,
                                                int xsel, int ysel) {
    const int N = C, K = C;
    const float* X = (xsel == 0) ? Xext : g_att;
    float* Y = (ysel == 0) ? g_q : (ysel == 1) ? g_k : (ysel == 2) ? g_v : Yext;

    __shared__ uint32_t Ah[BM][KP], Al[BM][KP];
    __shared__ uint32_t Bh[BN][KP], Bl[BN][KP];

    const int tid  = threadIdx.x;
    const int lane = tid & 31;
    const int warp = tid >> 5;
    const int warpM = warp >> 1;
    const int warpN = warp & 1;
    const int grp = lane >> 2;
    const int tg  = lane & 3;

    const int m0 = blockIdx.y * BM;
    const int n0 = blockIdx.x * BN;

    float acc[2][4][4];
    #pragma unroll
    for (int mt = 0; mt < 2; mt++)
        #pragma unroll
        for (int nt = 0; nt < 4; nt++)
            #pragma unroll
            for (int i = 0; i < 4; i++) acc[mt][nt][i] = 0.f;

    for (int k0 = 0; k0 < K; k0 += BK) {
        float4 a0, a1, b0;
        {
            int idx = tid;
            int r = idx >> 2, kq = idx & 3;
            a0 = *(const float4*)&X[(size_t)(m0 + r) * K + k0 + kq * 4];
            idx = tid + 256;
            r = idx >> 2; kq = idx & 3;
            a1 = *(const float4*)&X[(size_t)(m0 + r) * K + k0 + kq * 4];
            int br = tid >> 2, bkq = tid & 3;
            b0 = *(const float4*)&W[(size_t)(n0 + br) * K + k0 + bkq * 4];
        }
        __syncthreads();
        {
            int idx = tid;
            int r = idx >> 2, kk = (idx & 3) * 4;
            float v[4] = {a0.x, a0.y, a0.z, a0.w};
            #pragma unroll
            for (int j = 0; j < 4; j++) {
                uint32_t hi = f2tf32(v[j]);
                Ah[r][kk + j] = hi;
                Al[r][kk + j] = f2tf32(v[j] - __uint_as_float(hi));
            }
            idx = tid + 256;
            r = idx >> 2; kk = (idx & 3) * 4;
            float w2[4] = {a1.x, a1.y, a1.z, a1.w};
            #pragma unroll
            for (int j = 0; j < 4; j++) {
                uint32_t hi = f2tf32(w2[j]);
                Ah[r][kk + j] = hi;
                Al[r][kk + j] = f2tf32(w2[j] - __uint_as_float(hi));
            }
            int br = tid >> 2, bkk = (tid & 3) * 4;
            float w3[4] = {b0.x, b0.y, b0.z, b0.w};
            #pragma unroll
            for (int j = 0; j < 4; j++) {
                uint32_t hi = f2tf32(w3[j]);
                Bh[br][bkk + j] = hi;
                Bl[br][bkk + j] = f2tf32(w3[j] - __uint_as_float(hi));
            }
        }
        __syncthreads();

        #pragma unroll
        for (int ks = 0; ks < BK; ks += 8) {
            uint32_t ah[2][4], al[2][4], bh[4][2], bl[4][2];
            #pragma unroll
            for (int mt = 0; mt < 2; mt++) {
                int rb = warpM * 32 + mt * 16;
                ah[mt][0] = Ah[rb + grp][ks + tg];
                ah[mt][1] = Ah[rb + grp + 8][ks + tg];
                ah[mt][2] = Ah[rb + grp][ks + tg + 4];
                ah[mt][3] = Ah[rb + grp + 8][ks + tg + 4];
                al[mt][0] = Al[rb + grp][ks + tg];
                al[mt][1] = Al[rb + grp + 8][ks + tg];
                al[mt][2] = Al[rb + grp][ks + tg + 4];
                al[mt][3] = Al[rb + grp + 8][ks + tg + 4];
            }
            #pragma unroll
            for (int nt = 0; nt < 4; nt++) {
                int cb = warpN * 32 + nt * 8;
                bh[nt][0] = Bh[cb + grp][ks + tg];
                bh[nt][1] = Bh[cb + grp][ks + tg + 4];
                bl[nt][0] = Bl[cb + grp][ks + tg];
                bl[nt][1] = Bl[cb + grp][ks + tg + 4];
            }
            #pragma unroll
            for (int mt = 0; mt < 2; mt++)
                #pragma unroll
                for (int nt = 0; nt < 4; nt++) {
                    mma_tf32(acc[mt][nt], ah[mt], bh[nt]);
                    mma_tf32(acc[mt][nt], al[mt], bh[nt]);
                    mma_tf32(acc[mt][nt], ah[mt], bl[nt]);
                }
        }
    }

    #pragma unroll
    for (int mt = 0; mt < 2; mt++) {
        #pragma unroll
        for (int nt = 0; nt < 4; nt++) {
            int row = m0 + warpM * 32 + mt * 16 + grp;
            int col = n0 + warpN * 32 + nt * 8 + tg * 2;
            float2 lo = {acc[mt][nt][0], acc[mt][nt][1]};
            float2 hi = {acc[mt][nt][2], acc[mt][nt][3]};
            *(float2*)&Y[(size_t)row * N + col] = lo;
            *(float2*)&Y[(size_t)(row + 8) * N + col] = hi;
        }
    }
}

// ---------------------------------------------------------------------------
// RoPE (unchanged)
// ---------------------------------------------------------------------------
__global__ void rope_kernel(const float* __restrict__ cosp,
                            const float* __restrict__ sinp, int sel) {
    float* t = (sel == 0) ? g_q : g_k;
    int idx = blockIdx.x * blockDim.x + threadIdx.x;
    int d  = idx & 31;
    int h  = (idx >> 5) & 15;
    int tp = (idx >> 9) & (T - 1);
    int b  = idx >> 20;
    size_t base = ((size_t)(b * T + tp)) * C + h * HD + 2 * d;
    float t0 = t[base], t1 = t[base + 1];
    float cc = cosp[tp * (HD / 2) + d];
    float ss = sinp[tp * (HD / 2) + d];
    t[base]     = t0 * cc - t1 * ss;
    t[base + 1] = t0 * ss + t1 * cc;
}

// ---------------------------------------------------------------------------
// Tensor-core causal flash attention, 3xTF32 (fp32-accurate).
// Block: 64 q-rows x 1 head; 4 warps x 16 rows. Key tile KB=32.
// K smem stride 68, V stride 72 -> all fragment LDS conflict-free.
// ---------------------------------------------------------------------------
#define QB 64
#define KB 32
#define KSP 68
#define VSP 72

__global__ void __launch_bounds__(128, 2) attn_kernel() {
    __shared__ float Ksh[KB][KSP], Ksl[KB][KSP];
    __shared__ float Vsh[KB][VSP], Vsl[KB][VSP];

    const int tid  = threadIdx.x;
    const int lane = tid & 31;
    const int warp = tid >> 5;
    const int grp  = lane >> 2;
    const int tg   = lane & 3;
    const int bh   = blockIdx.y;
    const int b    = bh >> 4, h = bh & 15;
    const int q0   = blockIdx.x * QB;
    const int r0   = q0 + warp * 16;

    // ---- Q fragments, register-resident hi/lo ----
    uint32_t qh[8][4], ql[8][4];
    {
        const float* Qb = g_q + ((size_t)(b * T + r0)) * C + h * HD;
        #pragma unroll
        for (int ks = 0; ks < 8; ks++) {
            float v[4];
            v[0] = Qb[(size_t)grp * C + ks * 8 + tg];
            v[1] = Qb[(size_t)(grp + 8) * C + ks * 8 + tg];
            v[2] = Qb[(size_t)grp * C + ks * 8 + tg + 4];
            v[3] = Qb[(size_t)(grp + 8) * C + ks * 8 + tg + 4];
            #pragma unroll
            for (int j = 0; j < 4; j++) {
                uint32_t hi = f2tf32(v[j]);
                qh[ks][j] = hi;
                ql[ks][j] = f2tf32(v[j] - __uint_as_float(hi));
            }
        }
    }

    float out[8][4];
    #pragma unroll
    for (int i = 0; i < 8; i++)
        #pragma unroll
        for (int j = 0; j < 4; j++) out[i][j] = 0.f;
    float m0v = -1e30f, m1v = -1e30f, l0 = 0.f, l1 = 0.f;

    const int nIter = 2 * (blockIdx.x + 1);

    // prefetch tile 0
    float4 pk[4], pv[4];
    {
        #pragma unroll
        for (int i = 0; i < 4; i++) {
            int idx = tid + i * 128;
            int row = idx >> 4, c4 = (idx & 15) << 2;
            size_t off = ((size_t)(b * T + row)) * C + h * HD + c4;
            pk[i] = *(const float4*)&g_k[off];
            pv[i] = *(const float4*)&g_v[off];
        }
    }

    for (int t = 0; t < nIter; t++) {
        const int k0 = t * KB;
        __syncthreads();
        // store hi/lo split tiles
        #pragma unroll
        for (int i = 0; i < 4; i++) {
            int idx = tid + i * 128;
            int row = idx >> 4, c4 = (idx & 15) << 2;
            float kvv[4] = {pk[i].x, pk[i].y, pk[i].z, pk[i].w};
            float vvv[4] = {pv[i].x, pv[i].y, pv[i].z, pv[i].w};
            float4 khf, klf, vhf, vlf;
            float* kh = (float*)&khf; float* kl = (float*)&klf;
            float* vh = (float*)&vhf; float* vl = (float*)&vlf;
            #pragma unroll
            for (int j = 0; j < 4; j++) {
                uint32_t hi = f2tf32(kvv[j]);
                kh[j] = __uint_as_float(hi);
                kl[j] = __uint_as_float(f2tf32(kvv[j] - kh[j]));
                uint32_t hv = f2tf32(vvv[j]);
                vh[j] = __uint_as_float(hv);
                vl[j] = __uint_as_float(f2tf32(vvv[j] - vh[j]));
            }
            *(float4*)&Ksh[row][c4] = khf;
            *(float4*)&Ksl[row][c4] = klf;
            *(float4*)&Vsh[row][c4] = vhf;
            *(float4*)&Vsl[row][c4] = vlf;
        }
        __syncthreads();
        // prefetch next tile
        if (t + 1 < nIter) {
            int kn = (t + 1) * KB;
            #pragma unroll
            for (int i = 0; i < 4; i++) {
                int idx = tid + i * 128;
                int row = idx >> 4, c4 = (idx & 15) << 2;
                size_t off = ((size_t)(b * T + kn + row)) * C + h * HD + c4;
                pk[i] = *(const float4*)&g_k[off];
                pv[i] = *(const float4*)&g_v[off];
            }
        }

        if (k0 > r0 + 15) continue;   // warp-uniform: whole tile masked

        // ---- S = Q K^T (16 x 32), 3xTF32 ----
        float s[4][4];
        #pragma unroll
        for (int nt = 0; nt < 4; nt++)
            #pragma unroll
            for (int j = 0; j < 4; j++) s[nt][j] = 0.f;

        #pragma unroll
        for (int nt = 0; nt < 4; nt++) {
            #pragma unroll
            for (int ks = 0; ks < 8; ks++) {
                uint32_t bh2[2], bl2[2];
                bh2[0] = __float_as_uint(Ksh[nt * 8 + grp][ks * 8 + tg]);
                bh2[1] = __float_as_uint(Ksh[nt * 8 + grp][ks * 8 + tg + 4]);
                bl2[0] = __float_as_uint(Ksl[nt * 8 + grp][ks * 8 + tg]);
                bl2[1] = __float_as_uint(Ksl[nt * 8 + grp][ks * 8 + tg + 4]);
                mma_tf32(s[nt], qh[ks], bh2);
                mma_tf32(s[nt], ql[ks], bh2);
                mma_tf32(s[nt], qh[ks], bl2);
            }
        }

        // ---- scale + causal mask ----
        const int row0 = r0 + grp, row1 = r0 + grp + 8;
        if (k0 + KB - 1 <= r0) {       // fully unmasked tile (all warp rows)
            #pragma unroll
            for (int nt = 0; nt < 4; nt++)
                #pragma unroll
                for (int j = 0; j < 4; j++) s[nt][j] *= 0.125f;
        } else {
            #pragma unroll
            for (int nt = 0; nt < 4; nt++) {
                int col = k0 + nt * 8 + 2 * tg;
                s[nt][0] = (col     <= row0) ? s[nt][0] * 0.125f : -1e30f;
                s[nt][1] = (col + 1 <= row0) ? s[nt][1] * 0.125f : -1e30f;
                s[nt][2] = (col     <= row1) ? s[nt][2] * 0.125f : -1e30f;
                s[nt][3] = (col + 1 <= row1) ? s[nt][3] * 0.125f : -1e30f;
            }
        }

        // ---- online softmax ----
        float mx0 = s[0][0], mx1 = s[0][2];
        #pragma unroll
        for (int nt = 0; nt < 4; nt++) {
            mx0 = fmaxf(mx0, fmaxf(s[nt][0], s[nt][1]));
            mx1 = fmaxf(mx1, fmaxf(s[nt][2], s[nt][3]));
        }
        mx0 = fmaxf(mx0, __shfl_xor_sync(0xffffffffu, mx0, 1));
        mx0 = fmaxf(mx0, __shfl_xor_sync(0xffffffffu, mx0, 2));
        mx1 = fmaxf(mx1, __shfl_xor_sync(0xffffffffu, mx1, 1));
        mx1 = fmaxf(mx1, __shfl_xor_sync(0xffffffffu, mx1, 2));
        float nm0 = fmaxf(m0v, mx0), nm1 = fmaxf(m1v, mx1);
        float c0 = __expf(m0v - nm0), c1 = __expf(m1v - nm1);

        float sum0 = 0.f, sum1 = 0.f;
        #pragma unroll
        for (int nt = 0; nt < 4; nt++) {
            s[nt][0] = __expf(s[nt][0] - nm0);
            s[nt][1] = __expf(s[nt][1] - nm0);
            s[nt][2] = __expf(s[nt][2] - nm1);
            s[nt][3] = __expf(s[nt][3] - nm1);
            sum0 += s[nt][0] + s[nt][1];
            sum1 += s[nt][2] + s[nt][3];
        }
        sum0 += __shfl_xor_sync(0xffffffffu, sum0, 1);
        sum0 += __shfl_xor_sync(0xffffffffu, sum0, 2);
        sum1 += __shfl_xor_sync(0xffffffffu, sum1, 1);
        sum1 += __shfl_xor_sync(0xffffffffu, sum1, 2);
        l0 = l0 * c0 + sum0;
        l1 = l1 * c1 + sum1;
        m0v = nm0; m1v = nm1;

        #pragma unroll
        for (int i = 0; i < 8; i++) {
            out[i][0] *= c0; out[i][1] *= c0;
            out[i][2] *= c1; out[i][3] *= c1;
        }

        // ---- PV accumulate: P via intra-quad shuffle C->A remap ----
        const int src1 = (lane & ~3) | (tg >> 1);
        const int src2 = src1 + 2;
        const bool odd = tg & 1;
        #pragma unroll
        for (int ks = 0; ks < 4; ks++) {
            float w0 = __shfl_sync(0xffffffffu, s[ks][0], src1);
            float w1 = __shfl_sync(0xffffffffu, s[ks][1], src1);
            float w2 = __shfl_sync(0xffffffffu, s[ks][2], src1);
            float w3 = __shfl_sync(0xffffffffu, s[ks][3], src1);
            float x0 = __shfl_sync(0xffffffffu, s[ks][0], src2);
            float x1 = __shfl_sync(0xffffffffu, s[ks][1], src2);
            float x2 = __shfl_sync(0xffffffffu, s[ks][2], src2);
            float x3 = __shfl_sync(0xffffffffu, s[ks][3], src2);
            float a0 = odd ? w1 : w0;   // P[grp  ][ks*8+tg]
            float a1 = odd ? w3 : w2;   // P[grp+8][ks*8+tg]
            float a2 = odd ? x1 : x0;   // P[grp  ][ks*8+tg+4]
            float a3 = odd ? x3 : x2;   // P[grp+8][ks*8+tg+4]
            uint32_t pah[4], pal[4];
            float av[4] = {a0, a1, a2, a3};
            #pragma unroll
            for (int j = 0; j < 4; j++) {
                uint32_t hi = f2tf32(av[j]);
                pah[j] = hi;
                pal[j] = f2tf32(av[j] - __uint_as_float(hi));
            }
            #pragma unroll
            for (int ntv = 0; ntv < 8; ntv++) {
                uint32_t bh2[2], bl2[2];
                bh2[0] = __float_as_uint(Vsh[ks * 8 + tg][ntv * 8 + grp]);
                bh2[1] = __float_as_uint(Vsh[ks * 8 + tg + 4][ntv * 8 + grp]);
                bl2[0] = __float_as_uint(Vsl[ks * 8 + tg][ntv * 8 + grp]);
                bl2[1] = __float_as_uint(Vsl[ks * 8 + tg + 4][ntv * 8 + grp]);
                mma_tf32(out[ntv], pah, bh2);
                mma_tf32(out[ntv], pal, bh2);
                mma_tf32(out[ntv], pah, bl2);
            }
        }
    }

    // ---- normalize + store ----
    float inv0 = 1.f / l0, inv1 = 1.f / l1;
    float* Ob = g_att + ((size_t)(b * T + r0)) * C + h * HD;
    #pragma unroll
    for (int ntv = 0; ntv < 8; ntv++) {
        int col = ntv * 8 + 2 * tg;
        float2 lo = {out[ntv][0] * inv0, out[ntv][1] * inv0};
        float2 hi = {out[ntv][2] * inv1, out[ntv][3] * inv1};
        *(float2*)&Ob[(size_t)grp * C + col] = lo;
        *(float2*)&Ob[(size_t)(grp + 8) * C + col] = hi;
    }
}

// ---------------------------------------------------------------------------
extern "C" void kernel_launch(void* const* d_in, const int* in_sizes, int n_in,
                              void* d_out, int out_size) {
    const float* x    = (const float*)d_in[0];
    const float* Wq   = (const float*)d_in[1];
    const float* Wk   = (const float*)d_in[2];
    const float* Wv   = (const float*)d_in[3];
    const float* Wo   = (const float*)d_in[4];
    const float* cosp = (const float*)d_in[5];
    const float* sinp = (const float*)d_in[6];
    float* out = (float*)d_out;

    dim3 gg(C / BN, M_TOT / BM);
    gemm_xwt<<<gg, 256>>>(x, Wq, nullptr, 0, 0);
    gemm_xwt<<<gg, 256>>>(x, Wk, nullptr, 0, 1);
    gemm_xwt<<<gg, 256>>>(x, Wv, nullptr, 0, 2);

    int rope_total = B * T * H * (HD / 2);
    rope_kernel<<<rope_total / 256, 256>>>(cosp, sinp, 0);
    rope_kernel<<<rope_total / 256, 256>>>(cosp, sinp, 1);

    dim3 ga(T / QB, B * H);
    attn_kernel<<<ga, 128>>>();

    gemm_xwt<<<gg, 256>>>(nullptr, Wo, out, 1, 3);
}

// round 4
// speedup vs baseline: 2.7880x; 1.1695x over previous
#include <cuda_runtime.h>
#include <math.h>
#include <stdint.h>

#define B 2
#define T 2048
#define C 1024
#define H 16
#define HD 64
#define M_TOT (B*T)   // 4096

// ---------------- pre-split scratch (tf32 hi/lo stored as float) -----------
__device__ float g_xh[M_TOT*C], g_xl[M_TOT*C];
__device__ float g_wqh[C*C], g_wql[C*C];
__device__ float g_wkh[C*C], g_wkl[C*C];
__device__ float g_wvh[C*C], g_wvl[C*C];
__device__ float g_woh[C*C], g_wol[C*C];
__device__ float g_qh[M_TOT*C], g_ql[M_TOT*C];
__device__ float g_kh[M_TOT*C], g_kl[M_TOT*C];
__device__ float g_vh[M_TOT*C], g_vl[M_TOT*C];
__device__ float g_ah[M_TOT*C], g_al[M_TOT*C];

__device__ __forceinline__ uint32_t f2tf32(float x) {
    uint32_t r;
    asm("cvt.rna.tf32.f32 %0, %1;" : "=r"(r) : "f"(x));
    return r;
}

__device__ __forceinline__ void mma_tf32(float* d, const uint32_t* a,
                                         const uint32_t* b) {
    asm volatile(
        "mma.sync.aligned.m16n8k8.row.col.f32.tf32.tf32.f32 "
        "{%0,%1,%2,%3}, {%4,%5,%6,%7}, {%8,%9}, {%0,%1,%2,%3};"
        : "+f"(d[0]), "+f"(d[1]), "+f"(d[2]), "+f"(d[3])
        : "r"(a[0]), "r"(a[1]), "r"(a[2]), "r"(a[3]), "r"(b[0]), "r"(b[1]));
}

__device__ __forceinline__ void split2(float v, float& h, float& l) {
    uint32_t hu = f2tf32(v);
    h = __uint_as_float(hu);
    l = __uint_as_float(f2tf32(v - h));
}

// ---------------------------------------------------------------------------
// split kernel: src -> (hi, lo), float4-granular
// ---------------------------------------------------------------------------
__global__ void split_kernel(const float4* __restrict__ src,
                             float4* __restrict__ dh,
                             float4* __restrict__ dl, int n4) {
    int i = blockIdx.x * blockDim.x + threadIdx.x;
    if (i >= n4) return;
    float4 v = src[i];
    float4 h, l;
    split2(v.x, h.x, l.x);
    split2(v.y, h.y, l.y);
    split2(v.z, h.z, l.z);
    split2(v.w, h.w, l.w);
    dh[i] = h;
    dl[i] = l;
}

// ---------------------------------------------------------------------------
// Fused QKV GEMM (pre-split operands), RoPE + split in epilogue.
// Block tile 128x128x16, 256 threads, warp grid 2x4, warp tile 64x32.
// blockIdx.x: 0..23 -> nsel = x>>3 (0=q,1=k,2=v), col block = x&7.
// ---------------------------------------------------------------------------
#define BM 128
#define BN 128
#define BK 16
#define KP 20

__global__ void __launch_bounds__(256, 2) qkv_gemm(const float* __restrict__ cosp,
                                                   const float* __restrict__ sinp) {
    const int tid = threadIdx.x, lane = tid & 31, warp = tid >> 5;
    const int warpM = warp >> 2, warpN = warp & 3;
    const int grp = lane >> 2, tg = lane & 3;
    const int m0 = blockIdx.y * BM;
    const int nsel = blockIdx.x >> 3;
    const int n0c = (blockIdx.x & 7) * BN;

    const float* WH = (nsel == 0) ? g_wqh : (nsel == 1) ? g_wkh : g_wvh;
    const float* WL = (nsel == 0) ? g_wql : (nsel == 1) ? g_wkl : g_wvl;
    float* DH = (nsel == 0) ? g_qh : (nsel == 1) ? g_kh : g_vh;
    float* DL = (nsel == 0) ? g_ql : (nsel == 1) ? g_kl : g_vl;

    __shared__ float Ah[BM][KP], Al[BM][KP], Bh[BN][KP], Bl[BN][KP];

    float acc[4][4][4];
    #pragma unroll
    for (int mt = 0; mt < 4; mt++)
        #pragma unroll
        for (int nt = 0; nt < 4; nt++)
            #pragma unroll
            for (int i = 0; i < 4; i++) acc[mt][nt][i] = 0.f;

    const int lrow = tid >> 2;          // 0..63
    const int lkq  = (tid & 3) << 2;    // 0,4,8,12

    for (int k0 = 0; k0 < C; k0 += BK) {
        float4 xh0 = *(const float4*)&g_xh[(size_t)(m0 + lrow) * C + k0 + lkq];
        float4 xh1 = *(const float4*)&g_xh[(size_t)(m0 + lrow + 64) * C + k0 + lkq];
        float4 xl0 = *(const float4*)&g_xl[(size_t)(m0 + lrow) * C + k0 + lkq];
        float4 xl1 = *(const float4*)&g_xl[(size_t)(m0 + lrow + 64) * C + k0 + lkq];
        float4 wh0 = *(const float4*)&WH[(size_t)(n0c + lrow) * C + k0 + lkq];
        float4 wh1 = *(const float4*)&WH[(size_t)(n0c + lrow + 64) * C + k0 + lkq];
        float4 wl0 = *(const float4*)&WL[(size_t)(n0c + lrow) * C + k0 + lkq];
        float4 wl1 = *(const float4*)&WL[(size_t)(n0c + lrow + 64) * C + k0 + lkq];
        __syncthreads();
        *(float4*)&Ah[lrow][lkq]      = xh0;
        *(float4*)&Ah[lrow + 64][lkq] = xh1;
        *(float4*)&Al[lrow][lkq]      = xl0;
        *(float4*)&Al[lrow + 64][lkq] = xl1;
        *(float4*)&Bh[lrow][lkq]      = wh0;
        *(float4*)&Bh[lrow + 64][lkq] = wh1;
        *(float4*)&Bl[lrow][lkq]      = wl0;
        *(float4*)&Bl[lrow + 64][lkq] = wl1;
        __syncthreads();

        #pragma unroll
        for (int ks = 0; ks < BK; ks += 8) {
            uint32_t ah[4][4], al[4][4];
            #pragma unroll
            for (int mt = 0; mt < 4; mt++) {
                int rb = warpM * 64 + mt * 16;
                ah[mt][0] = __float_as_uint(Ah[rb + grp][ks + tg]);
                ah[mt][1] = __float_as_uint(Ah[rb + grp + 8][ks + tg]);
                ah[mt][2] = __float_as_uint(Ah[rb + grp][ks + tg + 4]);
                ah[mt][3] = __float_as_uint(Ah[rb + grp + 8][ks + tg + 4]);
                al[mt][0] = __float_as_uint(Al[rb + grp][ks + tg]);
                al[mt][1] = __float_as_uint(Al[rb + grp + 8][ks + tg]);
                al[mt][2] = __float_as_uint(Al[rb + grp][ks + tg + 4]);
                al[mt][3] = __float_as_uint(Al[rb + grp + 8][ks + tg + 4]);
            }
            #pragma unroll
            for (int nt = 0; nt < 4; nt++) {
                int cb = warpN * 32 + nt * 8;
                uint32_t bh2[2], bl2[2];
                bh2[0] = __float_as_uint(Bh[cb + grp][ks + tg]);
                bh2[1] = __float_as_uint(Bh[cb + grp][ks + tg + 4]);
                bl2[0] = __float_as_uint(Bl[cb + grp][ks + tg]);
                bl2[1] = __float_as_uint(Bl[cb + grp][ks + tg + 4]);
                #pragma unroll
                for (int mt = 0; mt < 4; mt++) {
                    mma_tf32(acc[mt][nt], ah[mt], bh2);
                    mma_tf32(acc[mt][nt], al[mt], bh2);
                    mma_tf32(acc[mt][nt], ah[mt], bl2);
                }
            }
        }
    }

    // epilogue: rope (q,k) + split + store
    #pragma unroll
    for (int mt = 0; mt < 4; mt++) {
        int rowA = m0 + warpM * 64 + mt * 16 + grp;
        int rowB = rowA + 8;
        #pragma unroll
        for (int nt = 0; nt < 4; nt++) {
            int c = n0c + warpN * 32 + nt * 8 + 2 * tg;
            float a0 = acc[mt][nt][0], a1 = acc[mt][nt][1];
            float a2 = acc[mt][nt][2], a3 = acc[mt][nt][3];
            if (nsel < 2) {
                int d = (c & 63) >> 1;
                int t0 = rowA & (T - 1), t1 = rowB & (T - 1);
                float c0 = cosp[t0 * 32 + d], s0 = sinp[t0 * 32 + d];
                float c1 = cosp[t1 * 32 + d], s1 = sinp[t1 * 32 + d];
                float o0 = a0 * c0 - a1 * s0, o1 = a0 * s0 + a1 * c0;
                float o2 = a2 * c1 - a3 * s1, o3 = a2 * s1 + a3 * c1;
                a0 = o0; a1 = o1; a2 = o2; a3 = o3;
            }
            float h0, l0v, h1, l1v, h2, l2v, h3, l3v;
            split2(a0, h0, l0v); split2(a1, h1, l1v);
            split2(a2, h2, l2v); split2(a3, h3, l3v);
            *(float2*)&DH[(size_t)rowA * C + c] = make_float2(h0, h1);
            *(float2*)&DL[(size_t)rowA * C + c] = make_float2(l0v, l1v);
            *(float2*)&DH[(size_t)rowB * C + c] = make_float2(h2, h3);
            *(float2*)&DL[(size_t)rowB * C + c] = make_float2(l2v, l3v);
        }
    }
}

// ---------------------------------------------------------------------------
// Output GEMM: out = att @ Wo^T, pre-split operands, plain float epilogue.
// ---------------------------------------------------------------------------
__global__ void __launch_bounds__(256, 2) wo_gemm(float* __restrict__ out) {
    const int tid = threadIdx.x, lane = tid & 31, warp = tid >> 5;
    const int warpM = warp >> 2, warpN = warp & 3;
    const int grp = lane >> 2, tg = lane & 3;
    const int m0 = blockIdx.y * BM;
    const int n0 = blockIdx.x * BN;

    __shared__ float Ah[BM][KP], Al[BM][KP], Bh[BN][KP], Bl[BN][KP];

    float acc[4][4][4];
    #pragma unroll
    for (int mt = 0; mt < 4; mt++)
        #pragma unroll
        for (int nt = 0; nt < 4; nt++)
            #pragma unroll
            for (int i = 0; i < 4; i++) acc[mt][nt][i] = 0.f;

    const int lrow = tid >> 2;
    const int lkq  = (tid & 3) << 2;

    for (int k0 = 0; k0 < C; k0 += BK) {
        float4 xh0 = *(const float4*)&g_ah[(size_t)(m0 + lrow) * C + k0 + lkq];
        float4 xh1 = *(const float4*)&g_ah[(size_t)(m0 + lrow + 64) * C + k0 + lkq];
        float4 xl0 = *(const float4*)&g_al[(size_t)(m0 + lrow) * C + k0 + lkq];
        float4 xl1 = *(const float4*)&g_al[(size_t)(m0 + lrow + 64) * C + k0 + lkq];
        float4 wh0 = *(const float4*)&g_woh[(size_t)(n0 + lrow) * C + k0 + lkq];
        float4 wh1 = *(const float4*)&g_woh[(size_t)(n0 + lrow + 64) * C + k0 + lkq];
        float4 wl0 = *(const float4*)&g_wol[(size_t)(n0 + lrow) * C + k0 + lkq];
        float4 wl1 = *(const float4*)&g_wol[(size_t)(n0 + lrow + 64) * C + k0 + lkq];
        __syncthreads();
        *(float4*)&Ah[lrow][lkq]      = xh0;
        *(float4*)&Ah[lrow + 64][lkq] = xh1;
        *(float4*)&Al[lrow][lkq]      = xl0;
        *(float4*)&Al[lrow + 64][lkq] = xl1;
        *(float4*)&Bh[lrow][lkq]      = wh0;
        *(float4*)&Bh[lrow + 64][lkq] = wh1;
        *(float4*)&Bl[lrow][lkq]      = wl0;
        *(float4*)&Bl[lrow + 64][lkq] = wl1;
        __syncthreads();

        #pragma unroll
        for (int ks = 0; ks < BK; ks += 8) {
            uint32_t ah[4][4], al[4][4];
            #pragma unroll
            for (int mt = 0; mt < 4; mt++) {
                int rb = warpM * 64 + mt * 16;
                ah[mt][0] = __float_as_uint(Ah[rb + grp][ks + tg]);
                ah[mt][1] = __float_as_uint(Ah[rb + grp + 8][ks + tg]);
                ah[mt][2] = __float_as_uint(Ah[rb + grp][ks + tg + 4]);
                ah[mt][3] = __float_as_uint(Ah[rb + grp + 8][ks + tg + 4]);
                al[mt][0] = __float_as_uint(Al[rb + grp][ks + tg]);
                al[mt][1] = __float_as_uint(Al[rb + grp + 8][ks + tg]);
                al[mt][2] = __float_as_uint(Al[rb + grp][ks + tg + 4]);
                al[mt][3] = __float_as_uint(Al[rb + grp + 8][ks + tg + 4]);
            }
            #pragma unroll
            for (int nt = 0; nt < 4; nt++) {
                int cb = warpN * 32 + nt * 8;
                uint32_t bh2[2], bl2[2];
                bh2[0] = __float_as_uint(Bh[cb + grp][ks + tg]);
                bh2[1] = __float_as_uint(Bh[cb + grp][ks + tg + 4]);
                bl2[0] = __float_as_uint(Bl[cb + grp][ks + tg]);
                bl2[1] = __float_as_uint(Bl[cb + grp][ks + tg + 4]);
                #pragma unroll
                for (int mt = 0; mt < 4; mt++) {
                    mma_tf32(acc[mt][nt], ah[mt], bh2);
                    mma_tf32(acc[mt][nt], al[mt], bh2);
                    mma_tf32(acc[mt][nt], ah[mt], bl2);
                }
            }
        }
    }

    #pragma unroll
    for (int mt = 0; mt < 4; mt++) {
        int rowA = m0 + warpM * 64 + mt * 16 + grp;
        #pragma unroll
        for (int nt = 0; nt < 4; nt++) {
            int c = n0 + warpN * 32 + nt * 8 + 2 * tg;
            *(float2*)&out[(size_t)rowA * C + c] =
                make_float2(acc[mt][nt][0], acc[mt][nt][1]);
            *(float2*)&out[(size_t)(rowA + 8) * C + c] =
                make_float2(acc[mt][nt][2], acc[mt][nt][3]);
        }
    }
}

// ---------------------------------------------------------------------------
// Tensor-core causal flash attention, 3xTF32, pre-split K/V/Q inputs,
// pre-split att output. Block: 64 q-rows x 1 head; 4 warps x 16 rows.
// ---------------------------------------------------------------------------
#define QB 64
#define KB 32
#define KSP 68
#define VSP 72

__global__ void __launch_bounds__(128, 2) attn_kernel() {
    __shared__ float Ksh[KB][KSP], Ksl[KB][KSP];
    __shared__ float Vsh[KB][VSP], Vsl[KB][VSP];

    const int tid  = threadIdx.x;
    const int lane = tid & 31;
    const int warp = tid >> 5;
    const int grp  = lane >> 2;
    const int tg   = lane & 3;
    const int bh   = blockIdx.y;
    const int b    = bh >> 4, h = bh & 15;
    const int q0   = blockIdx.x * QB;
    const int r0   = q0 + warp * 16;

    // Q fragments (pre-split)
    uint32_t qh[8][4], ql[8][4];
    {
        const float* QH = g_qh + ((size_t)(b * T + r0)) * C + h * HD;
        const float* QL = g_ql + ((size_t)(b * T + r0)) * C + h * HD;
        #pragma unroll
        for (int ks = 0; ks < 8; ks++) {
            qh[ks][0] = __float_as_uint(QH[(size_t)grp * C + ks * 8 + tg]);
            qh[ks][1] = __float_as_uint(QH[(size_t)(grp + 8) * C + ks * 8 + tg]);
            qh[ks][2] = __float_as_uint(QH[(size_t)grp * C + ks * 8 + tg + 4]);
            qh[ks][3] = __float_as_uint(QH[(size_t)(grp + 8) * C + ks * 8 + tg + 4]);
            ql[ks][0] = __float_as_uint(QL[(size_t)grp * C + ks * 8 + tg]);
            ql[ks][1] = __float_as_uint(QL[(size_t)(grp + 8) * C + ks * 8 + tg]);
            ql[ks][2] = __float_as_uint(QL[(size_t)grp * C + ks * 8 + tg + 4]);
            ql[ks][3] = __float_as_uint(QL[(size_t)(grp + 8) * C + ks * 8 + tg + 4]);
        }
    }

    float out[8][4];
    #pragma unroll
    for (int i = 0; i < 8; i++)
        #pragma unroll
        for (int j = 0; j < 4; j++) out[i][j] = 0.f;
    float m0v = -1e30f, m1v = -1e30f, l0 = 0.f, l1 = 0.f;

    const int nIter = 2 * (blockIdx.x + 1);

    for (int t = 0; t < nIter; t++) {
        const int k0 = t * KB;
        __syncthreads();
        #pragma unroll
        for (int i = 0; i < 4; i++) {
            int idx = tid + i * 128;
            int row = idx >> 4, c4 = (idx & 15) << 2;
            size_t off = ((size_t)(b * T + k0 + row)) * C + h * HD + c4;
            float4 a = *(const float4*)&g_kh[off];
            float4 bb = *(const float4*)&g_kl[off];
            float4 cc = *(const float4*)&g_vh[off];
            float4 dd = *(const float4*)&g_vl[off];
            *(float4*)&Ksh[row][c4] = a;
            *(float4*)&Ksl[row][c4] = bb;
            *(float4*)&Vsh[row][c4] = cc;
            *(float4*)&Vsl[row][c4] = dd;
        }
        __syncthreads();

        if (k0 > r0 + 15) continue;   // warp-uniform: whole tile masked

        // ---- S = Q K^T ----
        float s[4][4];
        #pragma unroll
        for (int nt = 0; nt < 4; nt++)
            #pragma unroll
            for (int j = 0; j < 4; j++) s[nt][j] = 0.f;

        #pragma unroll
        for (int nt = 0; nt < 4; nt++) {
            #pragma unroll
            for (int ks = 0; ks < 8; ks++) {
                uint32_t bh2[2], bl2[2];
                bh2[0] = __float_as_uint(Ksh[nt * 8 + grp][ks * 8 + tg]);
                bh2[1] = __float_as_uint(Ksh[nt * 8 + grp][ks * 8 + tg + 4]);
                bl2[0] = __float_as_uint(Ksl[nt * 8 + grp][ks * 8 + tg]);
                bl2[1] = __float_as_uint(Ksl[nt * 8 + grp][ks * 8 + tg + 4]);
                mma_tf32(s[nt], qh[ks], bh2);
                mma_tf32(s[nt], ql[ks], bh2);
                mma_tf32(s[nt], qh[ks], bl2);
            }
        }

        // ---- scale + causal mask ----
        const int row0 = r0 + grp, row1 = r0 + grp + 8;
        if (k0 + KB - 1 <= r0) {
            #pragma unroll
            for (int nt = 0; nt < 4; nt++)
                #pragma unroll
                for (int j = 0; j < 4; j++) s[nt][j] *= 0.125f;
        } else {
            #pragma unroll
            for (int nt = 0; nt < 4; nt++) {
                int col = k0 + nt * 8 + 2 * tg;
                s[nt][0] = (col     <= row0) ? s[nt][0] * 0.125f : -1e30f;
                s[nt][1] = (col + 1 <= row0) ? s[nt][1] * 0.125f : -1e30f;
                s[nt][2] = (col     <= row1) ? s[nt][2] * 0.125f : -1e30f;
                s[nt][3] = (col + 1 <= row1) ? s[nt][3] * 0.125f : -1e30f;
            }
        }

        // ---- online softmax ----
        float mx0 = s[0][0], mx1 = s[0][2];
        #pragma unroll
        for (int nt = 0; nt < 4; nt++) {
            mx0 = fmaxf(mx0, fmaxf(s[nt][0], s[nt][1]));
            mx1 = fmaxf(mx1, fmaxf(s[nt][2], s[nt][3]));
        }
        mx0 = fmaxf(mx0, __shfl_xor_sync(0xffffffffu, mx0, 1));
        mx0 = fmaxf(mx0, __shfl_xor_sync(0xffffffffu, mx0, 2));
        mx1 = fmaxf(mx1, __shfl_xor_sync(0xffffffffu, mx1, 1));
        mx1 = fmaxf(mx1, __shfl_xor_sync(0xffffffffu, mx1, 2));
        float nm0 = fmaxf(m0v, mx0), nm1 = fmaxf(m1v, mx1);
        float c0 = __expf(m0v - nm0), c1 = __expf(m1v - nm1);

        float sum0 = 0.f, sum1 = 0.f;
        #pragma unroll
        for (int nt = 0; nt < 4; nt++) {
            s[nt][0] = __expf(s[nt][0] - nm0);
            s[nt][1] = __expf(s[nt][1] - nm0);
            s[nt][2] = __expf(s[nt][2] - nm1);
            s[nt][3] = __expf(s[nt][3] - nm1);
            sum0 += s[nt][0] + s[nt][1];
            sum1 += s[nt][2] + s[nt][3];
        }
        sum0 += __shfl_xor_sync(0xffffffffu, sum0, 1);
        sum0 += __shfl_xor_sync(0xffffffffu, sum0, 2);
        sum1 += __shfl_xor_sync(0xffffffffu, sum1, 1);
        sum1 += __shfl_xor_sync(0xffffffffu, sum1, 2);
        l0 = l0 * c0 + sum0;
        l1 = l1 * c1 + sum1;
        m0v = nm0; m1v = nm1;

        #pragma unroll
        for (int i = 0; i < 8; i++) {
            out[i][0] *= c0; out[i][1] *= c0;
            out[i][2] *= c1; out[i][3] *= c1;
        }

        // ---- PV: P via intra-quad shuffle C->A remap ----
        const int src1 = (lane & ~3) | (tg >> 1);
        const int src2 = src1 + 2;
        const bool odd = tg & 1;
        #pragma unroll
        for (int ks = 0; ks < 4; ks++) {
            float w0 = __shfl_sync(0xffffffffu, s[ks][0], src1);
            float w1 = __shfl_sync(0xffffffffu, s[ks][1], src1);
            float w2 = __shfl_sync(0xffffffffu, s[ks][2], src1);
            float w3 = __shfl_sync(0xffffffffu, s[ks][3], src1);
            float x0 = __shfl_sync(0xffffffffu, s[ks][0], src2);
            float x1 = __shfl_sync(0xffffffffu, s[ks][1], src2);
            float x2 = __shfl_sync(0xffffffffu, s[ks][2], src2);
            float x3 = __shfl_sync(0xffffffffu, s[ks][3], src2);
            float a0 = odd ? w1 : w0;
            float a1 = odd ? w3 : w2;
            float a2 = odd ? x1 : x0;
            float a3 = odd ? x3 : x2;
            uint32_t pah[4], pal[4];
            float av[4] = {a0, a1, a2, a3};
            #pragma unroll
            for (int j = 0; j < 4; j++) {
                uint32_t hi = f2tf32(av[j]);
                pah[j] = hi;
                pal[j] = f2tf32(av[j] - __uint_as_float(hi));
            }
            #pragma unroll
            for (int ntv = 0; ntv < 8; ntv++) {
                uint32_t bh2[2], bl2[2];
                bh2[0] = __float_as_uint(Vsh[ks * 8 + tg][ntv * 8 + grp]);
                bh2[1] = __float_as_uint(Vsh[ks * 8 + tg + 4][ntv * 8 + grp]);
                bl2[0] = __float_as_uint(Vsl[ks * 8 + tg][ntv * 8 + grp]);
                bl2[1] = __float_as_uint(Vsl[ks * 8 + tg + 4][ntv * 8 + grp]);
                mma_tf32(out[ntv], pah, bh2);
                mma_tf32(out[ntv], pal, bh2);
                mma_tf32(out[ntv], pah, bl2);
            }
        }
    }

    // ---- normalize + split + store ----
    float inv0 = 1.f / l0, inv1 = 1.f / l1;
    size_t rA = ((size_t)(b * T + r0 + grp)) * C + h * HD;
    size_t rB = ((size_t)(b * T + r0 + grp + 8)) * C + h * HD;
    #pragma unroll
    for (int ntv = 0; ntv < 8; ntv++) {
        int col = ntv * 8 + 2 * tg;
        float v0 = out[ntv][0] * inv0, v1 = out[ntv][1] * inv0;
        float v2 = out[ntv][2] * inv1, v3 = out[ntv][3] * inv1;
        float h0, l0x, h1, l1x, h2, l2x, h3, l3x;
        split2(v0, h0, l0x); split2(v1, h1, l1x);
        split2(v2, h2, l2x); split2(v3, h3, l3x);
        *(float2*)&g_ah[rA + col] = make_float2(h0, h1);
        *(float2*)&g_al[rA + col] = make_float2(l0x, l1x);
        *(float2*)&g_ah[rB + col] = make_float2(h2, h3);
        *(float2*)&g_al[rB + col] = make_float2(l2x, l3x);
    }
}

// ---------------------------------------------------------------------------
extern "C" void kernel_launch(void* const* d_in, const int* in_sizes, int n_in,
                              void* d_out, int out_size) {
    const float* x    = (const float*)d_in[0];
    const float* Wq   = (const float*)d_in[1];
    const float* Wk   = (const float*)d_in[2];
    const float* Wv   = (const float*)d_in[3];
    const float* Wo   = (const float*)d_in[4];
    const float* cosp = (const float*)d_in[5];
    const float* sinp = (const float*)d_in[6];
    float* out = (float*)d_out;

    float *xh, *xl, *wqh, *wql, *wkh, *wkl, *wvh, *wvl, *woh, *wol;
    cudaGetSymbolAddress((void**)&xh,  g_xh);
    cudaGetSymbolAddress((void**)&xl,  g_xl);
    cudaGetSymbolAddress((void**)&wqh, g_wqh);
    cudaGetSymbolAddress((void**)&wql, g_wql);
    cudaGetSymbolAddress((void**)&wkh, g_wkh);
    cudaGetSymbolAddress((void**)&wkl, g_wkl);
    cudaGetSymbolAddress((void**)&wvh, g_wvh);
    cudaGetSymbolAddress((void**)&wvl, g_wvl);
    cudaGetSymbolAddress((void**)&woh, g_woh);
    cudaGetSymbolAddress((void**)&wol, g_wol);

    int nx4 = M_TOT * C / 4;   // 1M float4
    int nw4 = C * C / 4;       // 256K float4
    split_kernel<<<nx4 / 256, 256>>>((const float4*)x,  (float4*)xh,  (float4*)xl,  nx4);
    split_kernel<<<nw4 / 256, 256>>>((const float4*)Wq, (float4*)wqh, (float4*)wql, nw4);
    split_kernel<<<nw4 / 256, 256>>>((const float4*)Wk, (float4*)wkh, (float4*)wkl, nw4);
    split_kernel<<<nw4 / 256, 256>>>((const float4*)Wv, (float4*)wvh, (float4*)wvl, nw4);
    split_kernel<<<nw4 / 256, 256>>>((const float4*)Wo, (float4*)woh, (float4*)wol, nw4);

    qkv_gemm<<<dim3(24, M_TOT / BM), 256>>>(cosp, sinp);

    attn_kernel<<<dim3(T / QB, B * H), 128>>>();

    wo_gemm<<<dim3(C / BN, M_TOT / BM), 256>>>(out);
}

// round 6
// speedup vs baseline: 3.9987x; 1.4342x over previous
#include <cuda_runtime.h>
#include <cuda_bf16.h>
#include <math.h>
#include <stdint.h>

#define B 2
#define T 2048
#define C 1024
#define H 16
#define HD 64
#define M_TOT (B*T)   // 4096
#define C2 (C/2)      // packed bf16x2 words per row

// ---------------- packed bf16x2 split inputs -------------------------------
__device__ __align__(16) uint32_t g_xh[M_TOT*C2], g_xl[M_TOT*C2];
__device__ __align__(16) uint32_t g_wqh[C*C2], g_wql[C*C2];
__device__ __align__(16) uint32_t g_wkh[C*C2], g_wkl[C*C2];
__device__ __align__(16) uint32_t g_wvh[C*C2], g_wvl[C*C2];
__device__ __align__(16) uint32_t g_woh[C*C2], g_wol[C*C2];
// ---------------- tf32-split float intermediates (round-4 attention IO) ----
__device__ __align__(16) float g_qhf[M_TOT*C], g_qlf[M_TOT*C];
__device__ __align__(16) float g_khf[M_TOT*C], g_klf[M_TOT*C];
__device__ __align__(16) float g_vhf[M_TOT*C], g_vlf[M_TOT*C];
// ---------------- packed bf16x2 attention output ---------------------------
__device__ __align__(16) uint32_t g_ah[M_TOT*C2], g_al[M_TOT*C2];

// ---------------------------------------------------------------------------
// helpers
// ---------------------------------------------------------------------------
__device__ __forceinline__ uint32_t f2tf32(float x) {
    uint32_t r;
    asm("cvt.rna.tf32.f32 %0, %1;" : "=r"(r) : "f"(x));
    return r;
}
__device__ __forceinline__ void split2(float v, float& h, float& l) {
    uint32_t hu = f2tf32(v);
    h = __uint_as_float(hu);
    l = __uint_as_float(f2tf32(v - h));
}
__device__ __forceinline__ void mma_tf32(float* d, const uint32_t* a,
                                         const uint32_t* b) {
    asm volatile(
        "mma.sync.aligned.m16n8k8.row.col.f32.tf32.tf32.f32 "
        "{%0,%1,%2,%3}, {%4,%5,%6,%7}, {%8,%9}, {%0,%1,%2,%3};"
        : "+f"(d[0]), "+f"(d[1]), "+f"(d[2]), "+f"(d[3])
        : "r"(a[0]), "r"(a[1]), "r"(a[2]), "r"(a[3]), "r"(b[0]), "r"(b[1]));
}
__device__ __forceinline__ void mma_bf16(float* d, const uint32_t* a,
                                         const uint32_t* b) {
    asm volatile(
        "mma.sync.aligned.m16n8k16.row.col.f32.bf16.bf16.f32 "
        "{%0,%1,%2,%3}, {%4,%5,%6,%7}, {%8,%9}, {%0,%1,%2,%3};"
        : "+f"(d[0]), "+f"(d[1]), "+f"(d[2]), "+f"(d[3])
        : "r"(a[0]), "r"(a[1]), "r"(a[2]), "r"(a[3]), "r"(b[0]), "r"(b[1]));
}
__device__ __forceinline__ uint32_t packbf2(float x, float y) {
    __nv_bfloat162 t = __floats2bfloat162_rn(x, y);
    return *reinterpret_cast<uint32_t*>(&t);
}
__device__ __forceinline__ void splitpair(float x, float y,
                                          uint32_t& hw, uint32_t& lw) {
    __nv_bfloat16 hx = __float2bfloat16(x);
    __nv_bfloat16 hy = __float2bfloat16(y);
    float rx = x - __bfloat162float(hx);
    float ry = y - __bfloat162float(hy);
    __nv_bfloat162 hp = {hx, hy};
    hw = *reinterpret_cast<uint32_t*>(&hp);
    lw = packbf2(rx, ry);
}

// ---------------------------------------------------------------------------
// split kernel: float4 -> 2 packed hi words + 2 packed lo words
// ---------------------------------------------------------------------------
__global__ void split_kernel(const float4* __restrict__ src,
                             uint2* __restrict__ dh,
                             uint2* __restrict__ dl, int n4) {
    int i = blockIdx.x * blockDim.x + threadIdx.x;
    if (i >= n4) return;
    float4 v = src[i];
    uint2 h, l;
    splitpair(v.x, v.y, h.x, l.x);
    splitpair(v.z, v.w, h.y, l.y);
    dh[i] = h;
    dl[i] = l;
}

// ---------------------------------------------------------------------------
// Fused QKV GEMM, bf16 3-term split core. Epilogue: RoPE (q,k) + tf32 split,
// float stores (round-4 attention input format).
// Block 128x128x32elems, 256 threads, warp grid 2x4, warp tile 64x32.
// ---------------------------------------------------------------------------
#define BM 128
#define BN 128
#define KW 16            // words per tile row (32 K elems)
#define KP 20            // padded word stride

__global__ void __launch_bounds__(256, 2) qkv_gemm(const float* __restrict__ cosp,
                                                   const float* __restrict__ sinp) {
    const int tid = threadIdx.x, lane = tid & 31, warp = tid >> 5;
    const int warpM = warp >> 2, warpN = warp & 3;
    const int grp = lane >> 2, tg = lane & 3;
    const int m0 = blockIdx.y * BM;
    const int nsel = blockIdx.x >> 3;
    const int n0c = (blockIdx.x & 7) * BN;

    const uint32_t* WH = (nsel == 0) ? g_wqh : (nsel == 1) ? g_wkh : g_wvh;
    const uint32_t* WL = (nsel == 0) ? g_wql : (nsel == 1) ? g_wkl : g_wvl;
    float* DH = (nsel == 0) ? g_qhf : (nsel == 1) ? g_khf : g_vhf;
    float* DL = (nsel == 0) ? g_qlf : (nsel == 1) ? g_klf : g_vlf;

    __shared__ uint32_t Ah[BM][KP], Al[BM][KP], Bh[BN][KP], Bl[BN][KP];

    float acc[4][4][4];
    #pragma unroll
    for (int mt = 0; mt < 4; mt++)
        #pragma unroll
        for (int nt = 0; nt < 4; nt++)
            #pragma unroll
            for (int i = 0; i < 4; i++) acc[mt][nt][i] = 0.f;

    const int lrow = tid >> 2;
    const int lwq  = (tid & 3) << 2;

    for (int k0w = 0; k0w < C2; k0w += KW) {
        uint4 xh0 = *(const uint4*)&g_xh[(size_t)(m0 + lrow) * C2 + k0w + lwq];
        uint4 xh1 = *(const uint4*)&g_xh[(size_t)(m0 + lrow + 64) * C2 + k0w + lwq];
        uint4 xl0 = *(const uint4*)&g_xl[(size_t)(m0 + lrow) * C2 + k0w + lwq];
        uint4 xl1 = *(const uint4*)&g_xl[(size_t)(m0 + lrow + 64) * C2 + k0w + lwq];
        uint4 wh0 = *(const uint4*)&WH[(size_t)(n0c + lrow) * C2 + k0w + lwq];
        uint4 wh1 = *(const uint4*)&WH[(size_t)(n0c + lrow + 64) * C2 + k0w + lwq];
        uint4 wl0 = *(const uint4*)&WL[(size_t)(n0c + lrow) * C2 + k0w + lwq];
        uint4 wl1 = *(const uint4*)&WL[(size_t)(n0c + lrow + 64) * C2 + k0w + lwq];
        __syncthreads();
        *(uint4*)&Ah[lrow][lwq]      = xh0;
        *(uint4*)&Ah[lrow + 64][lwq] = xh1;
        *(uint4*)&Al[lrow][lwq]      = xl0;
        *(uint4*)&Al[lrow + 64][lwq] = xl1;
        *(uint4*)&Bh[lrow][lwq]      = wh0;
        *(uint4*)&Bh[lrow + 64][lwq] = wh1;
        *(uint4*)&Bl[lrow][lwq]      = wl0;
        *(uint4*)&Bl[lrow + 64][lwq] = wl1;
        __syncthreads();

        #pragma unroll
        for (int s8 = 0; s8 < KW; s8 += 8) {
            uint32_t ah[4][4], al[4][4];
            #pragma unroll
            for (int mt = 0; mt < 4; mt++) {
                int rb = warpM * 64 + mt * 16;
                ah[mt][0] = Ah[rb + grp][s8 + tg];
                ah[mt][1] = Ah[rb + grp + 8][s8 + tg];
                ah[mt][2] = Ah[rb + grp][s8 + tg + 4];
                ah[mt][3] = Ah[rb + grp + 8][s8 + tg + 4];
                al[mt][0] = Al[rb + grp][s8 + tg];
                al[mt][1] = Al[rb + grp + 8][s8 + tg];
                al[mt][2] = Al[rb + grp][s8 + tg + 4];
                al[mt][3] = Al[rb + grp + 8][s8 + tg + 4];
            }
            #pragma unroll
            for (int nt = 0; nt < 4; nt++) {
                int cb = warpN * 32 + nt * 8;
                uint32_t bh2[2], bl2[2];
                bh2[0] = Bh[cb + grp][s8 + tg];
                bh2[1] = Bh[cb + grp][s8 + tg + 4];
                bl2[0] = Bl[cb + grp][s8 + tg];
                bl2[1] = Bl[cb + grp][s8 + tg + 4];
                #pragma unroll
                for (int mt = 0; mt < 4; mt++) {
                    mma_bf16(acc[mt][nt], ah[mt], bh2);
                    mma_bf16(acc[mt][nt], al[mt], bh2);
                    mma_bf16(acc[mt][nt], ah[mt], bl2);
                }
            }
        }
    }

    // epilogue: identical to round-4 (rope + tf32 split, float stores)
    #pragma unroll
    for (int mt = 0; mt < 4; mt++) {
        int rowA = m0 + warpM * 64 + mt * 16 + grp;
        int rowB = rowA + 8;
        #pragma unroll
        for (int nt = 0; nt < 4; nt++) {
            int c = n0c + warpN * 32 + nt * 8 + 2 * tg;
            float a0 = acc[mt][nt][0], a1 = acc[mt][nt][1];
            float a2 = acc[mt][nt][2], a3 = acc[mt][nt][3];
            if (nsel < 2) {
                int d = (c & 63) >> 1;
                int t0 = rowA & (T - 1), t1 = rowB & (T - 1);
                float c0 = cosp[t0 * 32 + d], s0 = sinp[t0 * 32 + d];
                float c1 = cosp[t1 * 32 + d], s1 = sinp[t1 * 32 + d];
                float o0 = a0 * c0 - a1 * s0, o1 = a0 * s0 + a1 * c0;
                float o2 = a2 * c1 - a3 * s1, o3 = a2 * s1 + a3 * c1;
                a0 = o0; a1 = o1; a2 = o2; a3 = o3;
            }
            float h0, l0v, h1, l1v, h2, l2v, h3, l3v;
            split2(a0, h0, l0v); split2(a1, h1, l1v);
            split2(a2, h2, l2v); split2(a3, h3, l3v);
            *(float2*)&DH[(size_t)rowA * C + c] = make_float2(h0, h1);
            *(float2*)&DL[(size_t)rowA * C + c] = make_float2(l0v, l1v);
            *(float2*)&DH[(size_t)rowB * C + c] = make_float2(h2, h3);
            *(float2*)&DL[(size_t)rowB * C + c] = make_float2(l2v, l3v);
        }
    }
}

// ---------------------------------------------------------------------------
// Output GEMM: out = att @ Wo^T, bf16 3-term split core, fp32 epilogue.
// ---------------------------------------------------------------------------
__global__ void __launch_bounds__(256, 2) wo_gemm(float* __restrict__ out) {
    const int tid = threadIdx.x, lane = tid & 31, warp = tid >> 5;
    const int warpM = warp >> 2, warpN = warp & 3;
    const int grp = lane >> 2, tg = lane & 3;
    const int m0 = blockIdx.y * BM;
    const int n0 = blockIdx.x * BN;

    __shared__ uint32_t Ah[BM][KP], Al[BM][KP], Bh[BN][KP], Bl[BN][KP];

    float acc[4][4][4];
    #pragma unroll
    for (int mt = 0; mt < 4; mt++)
        #pragma unroll
        for (int nt = 0; nt < 4; nt++)
            #pragma unroll
            for (int i = 0; i < 4; i++) acc[mt][nt][i] = 0.f;

    const int lrow = tid >> 2;
    const int lwq  = (tid & 3) << 2;

    for (int k0w = 0; k0w < C2; k0w += KW) {
        uint4 xh0 = *(const uint4*)&g_ah[(size_t)(m0 + lrow) * C2 + k0w + lwq];
        uint4 xh1 = *(const uint4*)&g_ah[(size_t)(m0 + lrow + 64) * C2 + k0w + lwq];
        uint4 xl0 = *(const uint4*)&g_al[(size_t)(m0 + lrow) * C2 + k0w + lwq];
        uint4 xl1 = *(const uint4*)&g_al[(size_t)(m0 + lrow + 64) * C2 + k0w + lwq];
        uint4 wh0 = *(const uint4*)&g_woh[(size_t)(n0 + lrow) * C2 + k0w + lwq];
        uint4 wh1 = *(const uint4*)&g_woh[(size_t)(n0 + lrow + 64) * C2 + k0w + lwq];
        uint4 wl0 = *(const uint4*)&g_wol[(size_t)(n0 + lrow) * C2 + k0w + lwq];
        uint4 wl1 = *(const uint4*)&g_wol[(size_t)(n0 + lrow + 64) * C2 + k0w + lwq];
        __syncthreads();
        *(uint4*)&Ah[lrow][lwq]      = xh0;
        *(uint4*)&Ah[lrow + 64][lwq] = xh1;
        *(uint4*)&Al[lrow][lwq]      = xl0;
        *(uint4*)&Al[lrow + 64][lwq] = xl1;
        *(uint4*)&Bh[lrow][lwq]      = wh0;
        *(uint4*)&Bh[lrow + 64][lwq] = wh1;
        *(uint4*)&Bl[lrow][lwq]      = wl0;
        *(uint4*)&Bl[lrow + 64][lwq] = wl1;
        __syncthreads();

        #pragma unroll
        for (int s8 = 0; s8 < KW; s8 += 8) {
            uint32_t ah[4][4], al[4][4];
            #pragma unroll
            for (int mt = 0; mt < 4; mt++) {
                int rb = warpM * 64 + mt * 16;
                ah[mt][0] = Ah[rb + grp][s8 + tg];
                ah[mt][1] = Ah[rb + grp + 8][s8 + tg];
                ah[mt][2] = Ah[rb + grp][s8 + tg + 4];
                ah[mt][3] = Ah[rb + grp + 8][s8 + tg + 4];
                al[mt][0] = Al[rb + grp][s8 + tg];
                al[mt][1] = Al[rb + grp + 8][s8 + tg];
                al[mt][2] = Al[rb + grp][s8 + tg + 4];
                al[mt][3] = Al[rb + grp + 8][s8 + tg + 4];
            }
            #pragma unroll
            for (int nt = 0; nt < 4; nt++) {
                int cb = warpN * 32 + nt * 8;
                uint32_t bh2[2], bl2[2];
                bh2[0] = Bh[cb + grp][s8 + tg];
                bh2[1] = Bh[cb + grp][s8 + tg + 4];
                bl2[0] = Bl[cb + grp][s8 + tg];
                bl2[1] = Bl[cb + grp][s8 + tg + 4];
                #pragma unroll
                for (int mt = 0; mt < 4; mt++) {
                    mma_bf16(acc[mt][nt], ah[mt], bh2);
                    mma_bf16(acc[mt][nt], al[mt], bh2);
                    mma_bf16(acc[mt][nt], ah[mt], bl2);
                }
            }
        }
    }

    #pragma unroll
    for (int mt = 0; mt < 4; mt++) {
        int rowA = m0 + warpM * 64 + mt * 16 + grp;
        #pragma unroll
        for (int nt = 0; nt < 4; nt++) {
            int c = n0 + warpN * 32 + nt * 8 + 2 * tg;
            *(float2*)&out[(size_t)rowA * C + c] =
                make_float2(acc[mt][nt][0], acc[mt][nt][1]);
            *(float2*)&out[(size_t)(rowA + 8) * C + c] =
                make_float2(acc[mt][nt][2], acc[mt][nt][3]);
        }
    }
}

// ---------------------------------------------------------------------------
// Tensor-core causal flash attention, 3xTF32 — ROUND-4 KERNEL (validated),
// only the final store changed to packed bf16-split words.
// ---------------------------------------------------------------------------
#define QB 64
#define KB 32
#define KSP 68
#define VSP 72

__global__ void __launch_bounds__(128, 2) attn_kernel() {
    __shared__ float Ksh[KB][KSP], Ksl[KB][KSP];
    __shared__ float Vsh[KB][VSP], Vsl[KB][VSP];

    const int tid  = threadIdx.x;
    const int lane = tid & 31;
    const int warp = tid >> 5;
    const int grp  = lane >> 2;
    const int tg   = lane & 3;
    const int bh   = blockIdx.y;
    const int b    = bh >> 4, h = bh & 15;
    const int q0   = blockIdx.x * QB;
    const int r0   = q0 + warp * 16;

    uint32_t qh[8][4], ql[8][4];
    {
        const float* QH = g_qhf + ((size_t)(b * T + r0)) * C + h * HD;
        const float* QL = g_qlf + ((size_t)(b * T + r0)) * C + h * HD;
        #pragma unroll
        for (int ks = 0; ks < 8; ks++) {
            qh[ks][0] = __float_as_uint(QH[(size_t)grp * C + ks * 8 + tg]);
            qh[ks][1] = __float_as_uint(QH[(size_t)(grp + 8) * C + ks * 8 + tg]);
            qh[ks][2] = __float_as_uint(QH[(size_t)grp * C + ks * 8 + tg + 4]);
            qh[ks][3] = __float_as_uint(QH[(size_t)(grp + 8) * C + ks * 8 + tg + 4]);
            ql[ks][0] = __float_as_uint(QL[(size_t)grp * C + ks * 8 + tg]);
            ql[ks][1] = __float_as_uint(QL[(size_t)(grp + 8) * C + ks * 8 + tg]);
            ql[ks][2] = __float_as_uint(QL[(size_t)grp * C + ks * 8 + tg + 4]);
            ql[ks][3] = __float_as_uint(QL[(size_t)(grp + 8) * C + ks * 8 + tg + 4]);
        }
    }

    float out[8][4];
    #pragma unroll
    for (int i = 0; i < 8; i++)
        #pragma unroll
        for (int j = 0; j < 4; j++) out[i][j] = 0.f;
    float m0v = -1e30f, m1v = -1e30f, l0 = 0.f, l1 = 0.f;

    const int nIter = 2 * (blockIdx.x + 1);

    for (int t = 0; t < nIter; t++) {
        const int k0 = t * KB;
        __syncthreads();
        #pragma unroll
        for (int i = 0; i < 4; i++) {
            int idx = tid + i * 128;
            int row = idx >> 4, c4 = (idx & 15) << 2;
            size_t off = ((size_t)(b * T + k0 + row)) * C + h * HD + c4;
            float4 a = *(const float4*)&g_khf[off];
            float4 bb = *(const float4*)&g_klf[off];
            float4 cc = *(const float4*)&g_vhf[off];
            float4 dd = *(const float4*)&g_vlf[off];
            *(float4*)&Ksh[row][c4] = a;
            *(float4*)&Ksl[row][c4] = bb;
            *(float4*)&Vsh[row][c4] = cc;
            *(float4*)&Vsl[row][c4] = dd;
        }
        __syncthreads();

        if (k0 > r0 + 15) continue;

        float s[4][4];
        #pragma unroll
        for (int nt = 0; nt < 4; nt++)
            #pragma unroll
            for (int j = 0; j < 4; j++) s[nt][j] = 0.f;

        #pragma unroll
        for (int nt = 0; nt < 4; nt++) {
            #pragma unroll
            for (int ks = 0; ks < 8; ks++) {
                uint32_t bh2[2], bl2[2];
                bh2[0] = __float_as_uint(Ksh[nt * 8 + grp][ks * 8 + tg]);
                bh2[1] = __float_as_uint(Ksh[nt * 8 + grp][ks * 8 + tg + 4]);
                bl2[0] = __float_as_uint(Ksl[nt * 8 + grp][ks * 8 + tg]);
                bl2[1] = __float_as_uint(Ksl[nt * 8 + grp][ks * 8 + tg + 4]);
                mma_tf32(s[nt], qh[ks], bh2);
                mma_tf32(s[nt], ql[ks], bh2);
                mma_tf32(s[nt], qh[ks], bl2);
            }
        }

        const int row0 = r0 + grp, row1 = r0 + grp + 8;
        if (k0 + KB - 1 <= r0) {
            #pragma unroll
            for (int nt = 0; nt < 4; nt++)
                #pragma unroll
                for (int j = 0; j < 4; j++) s[nt][j] *= 0.125f;
        } else {
            #pragma unroll
            for (int nt = 0; nt < 4; nt++) {
                int col = k0 + nt * 8 + 2 * tg;
                s[nt][0] = (col     <= row0) ? s[nt][0] * 0.125f : -1e30f;
                s[nt][1] = (col + 1 <= row0) ? s[nt][1] * 0.125f : -1e30f;
                s[nt][2] = (col     <= row1) ? s[nt][2] * 0.125f : -1e30f;
                s[nt][3] = (col + 1 <= row1) ? s[nt][3] * 0.125f : -1e30f;
            }
        }

        float mx0 = s[0][0], mx1 = s[0][2];
        #pragma unroll
        for (int nt = 0; nt < 4; nt++) {
            mx0 = fmaxf(mx0, fmaxf(s[nt][0], s[nt][1]));
            mx1 = fmaxf(mx1, fmaxf(s[nt][2], s[nt][3]));
        }
        mx0 = fmaxf(mx0, __shfl_xor_sync(0xffffffffu, mx0, 1));
        mx0 = fmaxf(mx0, __shfl_xor_sync(0xffffffffu, mx0, 2));
        mx1 = fmaxf(mx1, __shfl_xor_sync(0xffffffffu, mx1, 1));
        mx1 = fmaxf(mx1, __shfl_xor_sync(0xffffffffu, mx1, 2));
        float nm0 = fmaxf(m0v, mx0), nm1 = fmaxf(m1v, mx1);
        float c0 = __expf(m0v - nm0), c1 = __expf(m1v - nm1);

        float sum0 = 0.f, sum1 = 0.f;
        #pragma unroll
        for (int nt = 0; nt < 4; nt++) {
            s[nt][0] = __expf(s[nt][0] - nm0);
            s[nt][1] = __expf(s[nt][1] - nm0);
            s[nt][2] = __expf(s[nt][2] - nm1);
            s[nt][3] = __expf(s[nt][3] - nm1);
            sum0 += s[nt][0] + s[nt][1];
            sum1 += s[nt][2] + s[nt][3];
        }
        sum0 += __shfl_xor_sync(0xffffffffu, sum0, 1);
        sum0 += __shfl_xor_sync(0xffffffffu, sum0, 2);
        sum1 += __shfl_xor_sync(0xffffffffu, sum1, 1);
        sum1 += __shfl_xor_sync(0xffffffffu, sum1, 2);
        l0 = l0 * c0 + sum0;
        l1 = l1 * c1 + sum1;
        m0v = nm0; m1v = nm1;

        #pragma unroll
        for (int i = 0; i < 8; i++) {
            out[i][0] *= c0; out[i][1] *= c0;
            out[i][2] *= c1; out[i][3] *= c1;
        }

        const int src1 = (lane & ~3) | (tg >> 1);
        const int src2 = src1 + 2;
        const bool odd = tg & 1;
        #pragma unroll
        for (int ks = 0; ks < 4; ks++) {
            float w0 = __shfl_sync(0xffffffffu, s[ks][0], src1);
            float w1 = __shfl_sync(0xffffffffu, s[ks][1], src1);
            float w2 = __shfl_sync(0xffffffffu, s[ks][2], src1);
            float w3 = __shfl_sync(0xffffffffu, s[ks][3], src1);
            float x0 = __shfl_sync(0xffffffffu, s[ks][0], src2);
            float x1 = __shfl_sync(0xffffffffu, s[ks][1], src2);
            float x2 = __shfl_sync(0xffffffffu, s[ks][2], src2);
            float x3 = __shfl_sync(0xffffffffu, s[ks][3], src2);
            float a0 = odd ? w1 : w0;
            float a1 = odd ? w3 : w2;
            float a2 = odd ? x1 : x0;
            float a3 = odd ? x3 : x2;
            uint32_t pah[4], pal[4];
            float av[4] = {a0, a1, a2, a3};
            #pragma unroll
            for (int j = 0; j < 4; j++) {
                uint32_t hi = f2tf32(av[j]);
                pah[j] = hi;
                pal[j] = f2tf32(av[j] - __uint_as_float(hi));
            }
            #pragma unroll
            for (int ntv = 0; ntv < 8; ntv++) {
                uint32_t bh2[2], bl2[2];
                bh2[0] = __float_as_uint(Vsh[ks * 8 + tg][ntv * 8 + grp]);
                bh2[1] = __float_as_uint(Vsh[ks * 8 + tg + 4][ntv * 8 + grp]);
                bl2[0] = __float_as_uint(Vsl[ks * 8 + tg][ntv * 8 + grp]);
                bl2[1] = __float_as_uint(Vsl[ks * 8 + tg + 4][ntv * 8 + grp]);
                mma_tf32(out[ntv], pah, bh2);
                mma_tf32(out[ntv], pal, bh2);
                mma_tf32(out[ntv], pah, bl2);
            }
        }
    }

    // normalize + bf16 splitpair + packed store
    float inv0 = 1.f / l0, inv1 = 1.f / l1;
    size_t rA = ((size_t)(b * T + r0 + grp)) * C2 + h * 32;
    size_t rB = ((size_t)(b * T + r0 + grp + 8)) * C2 + h * 32;
    #pragma unroll
    for (int ntv = 0; ntv < 8; ntv++) {
        int cw = ntv * 4 + tg;      // word col; cols 2cw,2cw+1 = ntv*8+2tg(+1)
        uint32_t hw, lw;
        splitpair(out[ntv][0] * inv0, out[ntv][1] * inv0, hw, lw);
        g_ah[rA + cw] = hw;
        g_al[rA + cw] = lw;
        splitpair(out[ntv][2] * inv1, out[ntv][3] * inv1, hw, lw);
        g_ah[rB + cw] = hw;
        g_al[rB + cw] = lw;
    }
}

// ---------------------------------------------------------------------------
extern "C" void kernel_launch(void* const* d_in, const int* in_sizes, int n_in,
                              void* d_out, int out_size) {
    const float* x    = (const float*)d_in[0];
    const float* Wq   = (const float*)d_in[1];
    const float* Wk   = (const float*)d_in[2];
    const float* Wv   = (const float*)d_in[3];
    const float* Wo   = (const float*)d_in[4];
    const float* cosp = (const float*)d_in[5];
    const float* sinp = (const float*)d_in[6];
    float* out = (float*)d_out;

    void *xh, *xl, *wqh, *wql, *wkh, *wkl, *wvh, *wvl, *woh, *wol;
    cudaGetSymbolAddress(&xh,  g_xh);
    cudaGetSymbolAddress(&xl,  g_xl);
    cudaGetSymbolAddress(&wqh, g_wqh);
    cudaGetSymbolAddress(&wql, g_wql);
    cudaGetSymbolAddress(&wkh, g_wkh);
    cudaGetSymbolAddress(&wkl, g_wkl);
    cudaGetSymbolAddress(&wvh, g_wvh);
    cudaGetSymbolAddress(&wvl, g_wvl);
    cudaGetSymbolAddress(&woh, g_woh);
    cudaGetSymbolAddress(&wol, g_wol);

    int nx4 = M_TOT * C / 4;
    int nw4 = C * C / 4;
    split_kernel<<<nx4 / 256, 256>>>((const float4*)x,  (uint2*)xh,  (uint2*)xl,  nx4);
    split_kernel<<<nw4 / 256, 256>>>((const float4*)Wq, (uint2*)wqh, (uint2*)wql, nw4);
    split_kernel<<<nw4 / 256, 256>>>((const float4*)Wk, (uint2*)wkh, (uint2*)wkl, nw4);
    split_kernel<<<nw4 / 256, 256>>>((const float4*)Wv, (uint2*)wvh, (uint2*)wvl, nw4);
    split_kernel<<<nw4 / 256, 256>>>((const float4*)Wo, (uint2*)woh, (uint2*)wol, nw4);

    qkv_gemm<<<dim3(24, M_TOT / BM), 256>>>(cosp, sinp);

    attn_kernel<<<dim3(T / QB, B * H), 128>>>();

    wo_gemm<<<dim3(C / BN, M_TOT / BM), 256>>>(out);
}

// round 8
// speedup vs baseline: 4.3450x; 1.0866x over previous
#include <cuda_runtime.h>
#include <cuda_bf16.h>
#include <math.h>
#include <stdint.h>

#define B 2
#define T 2048
#define C 1024
#define H 16
#define HD 64
#define M_TOT (B*T)   // 4096
#define C2 (C/2)      // packed bf16x2 words per row

// ---------------- packed bf16x2 split inputs -------------------------------
__device__ __align__(16) uint32_t g_xh[M_TOT*C2], g_xl[M_TOT*C2];
__device__ __align__(16) uint32_t g_wqh[C*C2], g_wql[C*C2];
__device__ __align__(16) uint32_t g_wkh[C*C2], g_wkl[C*C2];
__device__ __align__(16) uint32_t g_wvh[C*C2], g_wvl[C*C2];
__device__ __align__(16) uint32_t g_woh[C*C2], g_wol[C*C2];
// ---------------- tf32-split float intermediates (attention IO) ------------
__device__ __align__(16) float g_qhf[M_TOT*C], g_qlf[M_TOT*C];
__device__ __align__(16) float g_khf[M_TOT*C], g_klf[M_TOT*C];
__device__ __align__(16) float g_vhf[M_TOT*C], g_vlf[M_TOT*C];
// ---------------- packed bf16x2 attention output ---------------------------
__device__ __align__(16) uint32_t g_ah[M_TOT*C2], g_al[M_TOT*C2];

// ---------------------------------------------------------------------------
// helpers
// ---------------------------------------------------------------------------
__device__ __forceinline__ uint32_t f2tf32(float x) {
    uint32_t r;
    asm("cvt.rna.tf32.f32 %0, %1;" : "=r"(r) : "f"(x));
    return r;
}
__device__ __forceinline__ void split2(float v, float& h, float& l) {
    uint32_t hu = f2tf32(v);
    h = __uint_as_float(hu);
    l = __uint_as_float(f2tf32(v - h));
}
__device__ __forceinline__ void mma_tf32(float* d, const uint32_t* a,
                                         const uint32_t* b) {
    asm volatile(
        "mma.sync.aligned.m16n8k8.row.col.f32.tf32.tf32.f32 "
        "{%0,%1,%2,%3}, {%4,%5,%6,%7}, {%8,%9}, {%0,%1,%2,%3};"
        : "+f"(d[0]), "+f"(d[1]), "+f"(d[2]), "+f"(d[3])
        : "r"(a[0]), "r"(a[1]), "r"(a[2]), "r"(a[3]), "r"(b[0]), "r"(b[1]));
}
__device__ __forceinline__ void mma_bf16(float* d, const uint32_t* a,
                                         const uint32_t* b) {
    asm volatile(
        "mma.sync.aligned.m16n8k16.row.col.f32.bf16.bf16.f32 "
        "{%0,%1,%2,%3}, {%4,%5,%6,%7}, {%8,%9}, {%0,%1,%2,%3};"
        : "+f"(d[0]), "+f"(d[1]), "+f"(d[2]), "+f"(d[3])
        : "r"(a[0]), "r"(a[1]), "r"(a[2]), "r"(a[3]), "r"(b[0]), "r"(b[1]));
}
__device__ __forceinline__ uint32_t packbf2(float x, float y) {
    __nv_bfloat162 t = __floats2bfloat162_rn(x, y);
    return *reinterpret_cast<uint32_t*>(&t);
}
__device__ __forceinline__ void splitpair(float x, float y,
                                          uint32_t& hw, uint32_t& lw) {
    __nv_bfloat16 hx = __float2bfloat16(x);
    __nv_bfloat16 hy = __float2bfloat16(y);
    float rx = x - __bfloat162float(hx);
    float ry = y - __bfloat162float(hy);
    __nv_bfloat162 hp = {hx, hy};
    hw = *reinterpret_cast<uint32_t*>(&hp);
    lw = packbf2(rx, ry);
}
__device__ __forceinline__ void cp16(uint32_t saddr, const void* gptr) {
    asm volatile("cp.async.cg.shared.global [%0], [%1], 16;\n"
                 :: "r"(saddr), "l"(gptr));
}
#define CP_COMMIT() asm volatile("cp.async.commit_group;\n" ::)
#define CP_WAIT0()  asm volatile("cp.async.wait_group 0;\n" ::)

// ---------------------------------------------------------------------------
// split kernel: float4 -> 2 packed hi words + 2 packed lo words
// ---------------------------------------------------------------------------
__global__ void split_kernel(const float4* __restrict__ src,
                             uint2* __restrict__ dh,
                             uint2* __restrict__ dl, int n4) {
    int i = blockIdx.x * blockDim.x + threadIdx.x;
    if (i >= n4) return;
    float4 v = src[i];
    uint2 h, l;
    splitpair(v.x, v.y, h.x, l.x);
    splitpair(v.z, v.w, h.y, l.y);
    dh[i] = h;
    dl[i] = l;
}

// ---------------------------------------------------------------------------
// Fused QKV GEMM, bf16 3-term split core, cp.async double-buffered.
// Per-stage smem layout (words): Ah[128*20] @0, Al @2560, Bh @5120, Bl @7680.
// ---------------------------------------------------------------------------
#define BM 128
#define BN 128
#define KW 16
#define KP 20
#define GSTAGE 10240            // words per stage
#define NKIT (C2/KW)            // 32 k-iterations

__global__ void __launch_bounds__(256, 2) qkv_gemm(const float* __restrict__ cosp,
                                                   const float* __restrict__ sinp) {
    extern __shared__ uint32_t sm[];
    const int tid = threadIdx.x, lane = tid & 31, warp = tid >> 5;
    const int warpM = warp >> 2, warpN = warp & 3;
    const int grp = lane >> 2, tg = lane & 3;
    const int m0 = blockIdx.y * BM;
    const int nsel = blockIdx.x >> 3;
    const int n0c = (blockIdx.x & 7) * BN;

    const uint32_t* WH = (nsel == 0) ? g_wqh : (nsel == 1) ? g_wkh : g_wvh;
    const uint32_t* WL = (nsel == 0) ? g_wql : (nsel == 1) ? g_wkl : g_wvl;
    float* DH = (nsel == 0) ? g_qhf : (nsel == 1) ? g_khf : g_vhf;
    float* DL = (nsel == 0) ? g_qlf : (nsel == 1) ? g_klf : g_vlf;

    const int lrow = tid >> 2;
    const int lwq  = (tid & 3) << 2;
    const uint32_t sb = (uint32_t)__cvta_generic_to_shared(sm);

    float acc[4][4][4];
    #pragma unroll
    for (int mt = 0; mt < 4; mt++)
        #pragma unroll
        for (int nt = 0; nt < 4; nt++)
            #pragma unroll
            for (int i = 0; i < 4; i++) acc[mt][nt][i] = 0.f;

    // stage-issue: 8 x 16B cp.async per thread
    #define QKV_ISSUE(stg, k0w) do {                                          \
        uint32_t base_ = sb + (stg) * (GSTAGE * 4);                           \
        size_t rA0_ = (size_t)(m0 + lrow) * C2 + (k0w) + lwq;                 \
        size_t rA1_ = (size_t)(m0 + lrow + 64) * C2 + (k0w) + lwq;            \
        size_t rB0_ = (size_t)(n0c + lrow) * C2 + (k0w) + lwq;                \
        size_t rB1_ = (size_t)(n0c + lrow + 64) * C2 + (k0w) + lwq;           \
        uint32_t dA0_ = base_ + (lrow * KP + lwq) * 4;                        \
        uint32_t dA1_ = base_ + ((lrow + 64) * KP + lwq) * 4;                 \
        cp16(dA0_, &g_xh[rA0_]);  cp16(dA1_, &g_xh[rA1_]);                    \
        cp16(dA0_ + 2560 * 4, &g_xl[rA0_]);                                   \
        cp16(dA1_ + 2560 * 4, &g_xl[rA1_]);                                   \
        uint32_t dB0_ = base_ + (5120 + lrow * KP + lwq) * 4;                 \
        uint32_t dB1_ = base_ + (5120 + (lrow + 64) * KP + lwq) * 4;          \
        cp16(dB0_, &WH[rB0_]);  cp16(dB1_, &WH[rB1_]);                        \
        cp16(dB0_ + 2560 * 4, &WL[rB0_]);                                     \
        cp16(dB1_ + 2560 * 4, &WL[rB1_]);                                     \
        CP_COMMIT();                                                          \
    } while (0)

    QKV_ISSUE(0, 0);

    for (int it = 0; it < NKIT; it++) {
        CP_WAIT0();
        __syncthreads();
        if (it + 1 < NKIT) QKV_ISSUE((it + 1) & 1, (it + 1) * KW);

        const uint32_t* Ah = sm + (it & 1) * GSTAGE;
        const uint32_t* Al = Ah + 2560;
        const uint32_t* Bh = Ah + 5120;
        const uint32_t* Bl = Ah + 7680;

        #pragma unroll
        for (int s8 = 0; s8 < KW; s8 += 8) {
            uint32_t ah[4][4], al[4][4];
            #pragma unroll
            for (int mt = 0; mt < 4; mt++) {
                int rb = warpM * 64 + mt * 16;
                ah[mt][0] = Ah[(rb + grp) * KP + s8 + tg];
                ah[mt][1] = Ah[(rb + grp + 8) * KP + s8 + tg];
                ah[mt][2] = Ah[(rb + grp) * KP + s8 + tg + 4];
                ah[mt][3] = Ah[(rb + grp + 8) * KP + s8 + tg + 4];
                al[mt][0] = Al[(rb + grp) * KP + s8 + tg];
                al[mt][1] = Al[(rb + grp + 8) * KP + s8 + tg];
                al[mt][2] = Al[(rb + grp) * KP + s8 + tg + 4];
                al[mt][3] = Al[(rb + grp + 8) * KP + s8 + tg + 4];
            }
            #pragma unroll
            for (int nt = 0; nt < 4; nt++) {
                int cb = warpN * 32 + nt * 8;
                uint32_t bh2[2], bl2[2];
                bh2[0] = Bh[(cb + grp) * KP + s8 + tg];
                bh2[1] = Bh[(cb + grp) * KP + s8 + tg + 4];
                bl2[0] = Bl[(cb + grp) * KP + s8 + tg];
                bl2[1] = Bl[(cb + grp) * KP + s8 + tg + 4];
                #pragma unroll
                for (int mt = 0; mt < 4; mt++) {
                    mma_bf16(acc[mt][nt], ah[mt], bh2);
                    mma_bf16(acc[mt][nt], al[mt], bh2);
                    mma_bf16(acc[mt][nt], ah[mt], bl2);
                }
            }
        }
    }

    // epilogue (validated round 6): rope + tf32 split, float stores
    #pragma unroll
    for (int mt = 0; mt < 4; mt++) {
        int rowA = m0 + warpM * 64 + mt * 16 + grp;
        int rowB = rowA + 8;
        #pragma unroll
        for (int nt = 0; nt < 4; nt++) {
            int c = n0c + warpN * 32 + nt * 8 + 2 * tg;
            float a0 = acc[mt][nt][0], a1 = acc[mt][nt][1];
            float a2 = acc[mt][nt][2], a3 = acc[mt][nt][3];
            if (nsel < 2) {
                int d = (c & 63) >> 1;
                int t0 = rowA & (T - 1), t1 = rowB & (T - 1);
                float c0 = cosp[t0 * 32 + d], s0 = sinp[t0 * 32 + d];
                float c1 = cosp[t1 * 32 + d], s1 = sinp[t1 * 32 + d];
                float o0 = a0 * c0 - a1 * s0, o1 = a0 * s0 + a1 * c0;
                float o2 = a2 * c1 - a3 * s1, o3 = a2 * s1 + a3 * c1;
                a0 = o0; a1 = o1; a2 = o2; a3 = o3;
            }
            float h0, l0v, h1, l1v, h2, l2v, h3, l3v;
            split2(a0, h0, l0v); split2(a1, h1, l1v);
            split2(a2, h2, l2v); split2(a3, h3, l3v);
            *(float2*)&DH[(size_t)rowA * C + c] = make_float2(h0, h1);
            *(float2*)&DL[(size_t)rowA * C + c] = make_float2(l0v, l1v);
            *(float2*)&DH[(size_t)rowB * C + c] = make_float2(h2, h3);
            *(float2*)&DL[(size_t)rowB * C + c] = make_float2(l2v, l3v);
        }
    }
}

// ---------------------------------------------------------------------------
// Output GEMM: out = att @ Wo^T, bf16 3-term split, cp.async double-buffered.
// ---------------------------------------------------------------------------
__global__ void __launch_bounds__(256, 2) wo_gemm(float* __restrict__ out) {
    extern __shared__ uint32_t sm[];
    const int tid = threadIdx.x, lane = tid & 31, warp = tid >> 5;
    const int warpM = warp >> 2, warpN = warp & 3;
    const int grp = lane >> 2, tg = lane & 3;
    const int m0 = blockIdx.y * BM;
    const int n0 = blockIdx.x * BN;

    const int lrow = tid >> 2;
    const int lwq  = (tid & 3) << 2;
    const uint32_t sb = (uint32_t)__cvta_generic_to_shared(sm);

    float acc[4][4][4];
    #pragma unroll
    for (int mt = 0; mt < 4; mt++)
        #pragma unroll
        for (int nt = 0; nt < 4; nt++)
            #pragma unroll
            for (int i = 0; i < 4; i++) acc[mt][nt][i] = 0.f;

    #define WO_ISSUE(stg, k0w) do {                                           \
        uint32_t base_ = sb + (stg) * (GSTAGE * 4);                           \
        size_t rA0_ = (size_t)(m0 + lrow) * C2 + (k0w) + lwq;                 \
        size_t rA1_ = (size_t)(m0 + lrow + 64) * C2 + (k0w) + lwq;            \
        size_t rB0_ = (size_t)(n0 + lrow) * C2 + (k0w) + lwq;                 \
        size_t rB1_ = (size_t)(n0 + lrow + 64) * C2 + (k0w) + lwq;            \
        uint32_t dA0_ = base_ + (lrow * KP + lwq) * 4;                        \
        uint32_t dA1_ = base_ + ((lrow + 64) * KP + lwq) * 4;                 \
        cp16(dA0_, &g_ah[rA0_]);  cp16(dA1_, &g_ah[rA1_]);                    \
        cp16(dA0_ + 2560 * 4, &g_al[rA0_]);                                   \
        cp16(dA1_ + 2560 * 4, &g_al[rA1_]);                                   \
        uint32_t dB0_ = base_ + (5120 + lrow * KP + lwq) * 4;                 \
        uint32_t dB1_ = base_ + (5120 + (lrow + 64) * KP + lwq) * 4;          \
        cp16(dB0_, &g_woh[rB0_]);  cp16(dB1_, &g_woh[rB1_]);                  \
        cp16(dB0_ + 2560 * 4, &g_wol[rB0_]);                                  \
        cp16(dB1_ + 2560 * 4, &g_wol[rB1_]);                                  \
        CP_COMMIT();                                                          \
    } while (0)

    WO_ISSUE(0, 0);

    for (int it = 0; it < NKIT; it++) {
        CP_WAIT0();
        __syncthreads();
        if (it + 1 < NKIT) WO_ISSUE((it + 1) & 1, (it + 1) * KW);

        const uint32_t* Ah = sm + (it & 1) * GSTAGE;
        const uint32_t* Al = Ah + 2560;
        const uint32_t* Bh = Ah + 5120;
        const uint32_t* Bl = Ah + 7680;

        #pragma unroll
        for (int s8 = 0; s8 < KW; s8 += 8) {
            uint32_t ah[4][4], al[4][4];
            #pragma unroll
            for (int mt = 0; mt < 4; mt++) {
                int rb = warpM * 64 + mt * 16;
                ah[mt][0] = Ah[(rb + grp) * KP + s8 + tg];
                ah[mt][1] = Ah[(rb + grp + 8) * KP + s8 + tg];
                ah[mt][2] = Ah[(rb + grp) * KP + s8 + tg + 4];
                ah[mt][3] = Ah[(rb + grp + 8) * KP + s8 + tg + 4];
                al[mt][0] = Al[(rb + grp) * KP + s8 + tg];
                al[mt][1] = Al[(rb + grp + 8) * KP + s8 + tg];
                al[mt][2] = Al[(rb + grp) * KP + s8 + tg + 4];
                al[mt][3] = Al[(rb + grp + 8) * KP + s8 + tg + 4];
            }
            #pragma unroll
            for (int nt = 0; nt < 4; nt++) {
                int cb = warpN * 32 + nt * 8;
                uint32_t bh2[2], bl2[2];
                bh2[0] = Bh[(cb + grp) * KP + s8 + tg];
                bh2[1] = Bh[(cb + grp) * KP + s8 + tg + 4];
                bl2[0] = Bl[(cb + grp) * KP + s8 + tg];
                bl2[1] = Bl[(cb + grp) * KP + s8 + tg + 4];
                #pragma unroll
                for (int mt = 0; mt < 4; mt++) {
                    mma_bf16(acc[mt][nt], ah[mt], bh2);
                    mma_bf16(acc[mt][nt], al[mt], bh2);
                    mma_bf16(acc[mt][nt], ah[mt], bl2);
                }
            }
        }
    }

    #pragma unroll
    for (int mt = 0; mt < 4; mt++) {
        int rowA = m0 + warpM * 64 + mt * 16 + grp;
        #pragma unroll
        for (int nt = 0; nt < 4; nt++) {
            int c = n0 + warpN * 32 + nt * 8 + 2 * tg;
            *(float2*)&out[(size_t)rowA * C + c] =
                make_float2(acc[mt][nt][0], acc[mt][nt][1]);
            *(float2*)&out[(size_t)(rowA + 8) * C + c] =
                make_float2(acc[mt][nt][2], acc[mt][nt][3]);
        }
    }
}

// ---------------------------------------------------------------------------
// Tensor-core causal flash attention, 3xTF32 (validated), cp.async
// double-buffered K/V tiles. Per-stage float layout:
//   Kh[32*68] @0, Kl @2176, Vh[32*72] @4352, Vl @6656; stage = 8960 floats.
// ---------------------------------------------------------------------------
#define QB 64
#define KB 32
#define KSP 68
#define VSP 72
#define ASTAGE 8960

__global__ void __launch_bounds__(128, 2) attn_kernel() {
    extern __shared__ float smf[];

    const int tid  = threadIdx.x;
    const int lane = tid & 31;
    const int warp = tid >> 5;
    const int grp  = lane >> 2;
    const int tg   = lane & 3;
    const int bh   = blockIdx.y;
    const int b    = bh >> 4, h = bh & 15;
    const int q0   = blockIdx.x * QB;
    const int r0   = q0 + warp * 16;
    const uint32_t sb = (uint32_t)__cvta_generic_to_shared(smf);

    uint32_t qh[8][4], ql[8][4];
    {
        const float* QH = g_qhf + ((size_t)(b * T + r0)) * C + h * HD;
        const float* QL = g_qlf + ((size_t)(b * T + r0)) * C + h * HD;
        #pragma unroll
        for (int ks = 0; ks < 8; ks++) {
            qh[ks][0] = __float_as_uint(QH[(size_t)grp * C + ks * 8 + tg]);
            qh[ks][1] = __float_as_uint(QH[(size_t)(grp + 8) * C + ks * 8 + tg]);
            qh[ks][2] = __float_as_uint(QH[(size_t)grp * C + ks * 8 + tg + 4]);
            qh[ks][3] = __float_as_uint(QH[(size_t)(grp + 8) * C + ks * 8 + tg + 4]);
            ql[ks][0] = __float_as_uint(QL[(size_t)grp * C + ks * 8 + tg]);
            ql[ks][1] = __float_as_uint(QL[(size_t)(grp + 8) * C + ks * 8 + tg]);
            ql[ks][2] = __float_as_uint(QL[(size_t)grp * C + ks * 8 + tg + 4]);
            ql[ks][3] = __float_as_uint(QL[(size_t)(grp + 8) * C + ks * 8 + tg + 4]);
        }
    }

    float out[8][4];
    #pragma unroll
    for (int i = 0; i < 8; i++)
        #pragma unroll
        for (int j = 0; j < 4; j++) out[i][j] = 0.f;
    float m0v = -1e30f, m1v = -1e30f, l0 = 0.f, l1 = 0.f;

    const int nIter = 2 * (blockIdx.x + 1);

    #define ATT_ISSUE(stg, k0) do {                                           \
        uint32_t base_ = sb + (stg) * (ASTAGE * 4);                           \
        _Pragma("unroll")                                                     \
        for (int i_ = 0; i_ < 4; i_++) {                                      \
            int idx_ = tid + i_ * 128;                                        \
            int row_ = idx_ >> 4, c4_ = (idx_ & 15) << 2;                     \
            size_t off_ = ((size_t)(b * T + (k0) + row_)) * C + h * HD + c4_; \
            cp16(base_ + (row_ * KSP + c4_) * 4, &g_khf[off_]);               \
            cp16(base_ + (2176 + row_ * KSP + c4_) * 4, &g_klf[off_]);        \
            cp16(base_ + (4352 + row_ * VSP + c4_) * 4, &g_vhf[off_]);        \
            cp16(base_ + (6656 + row_ * VSP + c4_) * 4, &g_vlf[off_]);        \
        }                                                                     \
        CP_COMMIT();                                                          \
    } while (0)

    ATT_ISSUE(0, 0);

    for (int t = 0; t < nIter; t++) {
        const int k0 = t * KB;
        CP_WAIT0();
        __syncthreads();
        if (t + 1 < nIter) ATT_ISSUE((t + 1) & 1, (t + 1) * KB);

        if (k0 > r0 + 15) continue;

        const float* Ksh = smf + (t & 1) * ASTAGE;
        const float* Ksl = Ksh + 2176;
        const float* Vsh = Ksh + 4352;
        const float* Vsl = Ksh + 6656;

        float s[4][4];
        #pragma unroll
        for (int nt = 0; nt < 4; nt++)
            #pragma unroll
            for (int j = 0; j < 4; j++) s[nt][j] = 0.f;

        #pragma unroll
        for (int nt = 0; nt < 4; nt++) {
            #pragma unroll
            for (int ks = 0; ks < 8; ks++) {
                uint32_t bh2[2], bl2[2];
                bh2[0] = __float_as_uint(Ksh[(nt * 8 + grp) * KSP + ks * 8 + tg]);
                bh2[1] = __float_as_uint(Ksh[(nt * 8 + grp) * KSP + ks * 8 + tg + 4]);
                bl2[0] = __float_as_uint(Ksl[(nt * 8 + grp) * KSP + ks * 8 + tg]);
                bl2[1] = __float_as_uint(Ksl[(nt * 8 + grp) * KSP + ks * 8 + tg + 4]);
                mma_tf32(s[nt], qh[ks], bh2);
                mma_tf32(s[nt], ql[ks], bh2);
                mma_tf32(s[nt], qh[ks], bl2);
            }
        }

        const int row0 = r0 + grp, row1 = r0 + grp + 8;
        if (k0 + KB - 1 <= r0) {
            #pragma unroll
            for (int nt = 0; nt < 4; nt++)
                #pragma unroll
                for (int j = 0; j < 4; j++) s[nt][j] *= 0.125f;
        } else {
            #pragma unroll
            for (int nt = 0; nt < 4; nt++) {
                int col = k0 + nt * 8 + 2 * tg;
                s[nt][0] = (col     <= row0) ? s[nt][0] * 0.125f : -1e30f;
                s[nt][1] = (col + 1 <= row0) ? s[nt][1] * 0.125f : -1e30f;
                s[nt][2] = (col     <= row1) ? s[nt][2] * 0.125f : -1e30f;
                s[nt][3] = (col + 1 <= row1) ? s[nt][3] * 0.125f : -1e30f;
            }
        }

        float mx0 = s[0][0], mx1 = s[0][2];
        #pragma unroll
        for (int nt = 0; nt < 4; nt++) {
            mx0 = fmaxf(mx0, fmaxf(s[nt][0], s[nt][1]));
            mx1 = fmaxf(mx1, fmaxf(s[nt][2], s[nt][3]));
        }
        mx0 = fmaxf(mx0, __shfl_xor_sync(0xffffffffu, mx0, 1));
        mx0 = fmaxf(mx0, __shfl_xor_sync(0xffffffffu, mx0, 2));
        mx1 = fmaxf(mx1, __shfl_xor_sync(0xffffffffu, mx1, 1));
        mx1 = fmaxf(mx1, __shfl_xor_sync(0xffffffffu, mx1, 2));
        float nm0 = fmaxf(m0v, mx0), nm1 = fmaxf(m1v, mx1);
        float c0 = __expf(m0v - nm0), c1 = __expf(m1v - nm1);

        float sum0 = 0.f, sum1 = 0.f;
        #pragma unroll
        for (int nt = 0; nt < 4; nt++) {
            s[nt][0] = __expf(s[nt][0] - nm0);
            s[nt][1] = __expf(s[nt][1] - nm0);
            s[nt][2] = __expf(s[nt][2] - nm1);
            s[nt][3] = __expf(s[nt][3] - nm1);
            sum0 += s[nt][0] + s[nt][1];
            sum1 += s[nt][2] + s[nt][3];
        }
        sum0 += __shfl_xor_sync(0xffffffffu, sum0, 1);
        sum0 += __shfl_xor_sync(0xffffffffu, sum0, 2);
        sum1 += __shfl_xor_sync(0xffffffffu, sum1, 1);
        sum1 += __shfl_xor_sync(0xffffffffu, sum1, 2);
        l0 = l0 * c0 + sum0;
        l1 = l1 * c1 + sum1;
        m0v = nm0; m1v = nm1;

        #pragma unroll
        for (int i = 0; i < 8; i++) {
            out[i][0] *= c0; out[i][1] *= c0;
            out[i][2] *= c1; out[i][3] *= c1;
        }

        const int src1 = (lane & ~3) | (tg >> 1);
        const int src2 = src1 + 2;
        const bool odd = tg & 1;
        #pragma unroll
        for (int ks = 0; ks < 4; ks++) {
            float w0 = __shfl_sync(0xffffffffu, s[ks][0], src1);
            float w1 = __shfl_sync(0xffffffffu, s[ks][1], src1);
            float w2 = __shfl_sync(0xffffffffu, s[ks][2], src1);
            float w3 = __shfl_sync(0xffffffffu, s[ks][3], src1);
            float x0 = __shfl_sync(0xffffffffu, s[ks][0], src2);
            float x1 = __shfl_sync(0xffffffffu, s[ks][1], src2);
            float x2 = __shfl_sync(0xffffffffu, s[ks][2], src2);
            float x3 = __shfl_sync(0xffffffffu, s[ks][3], src2);
            float a0 = odd ? w1 : w0;
            float a1 = odd ? w3 : w2;
            float a2 = odd ? x1 : x0;
            float a3 = odd ? x3 : x2;
            uint32_t pah[4], pal[4];
            float av[4] = {a0, a1, a2, a3};
            #pragma unroll
            for (int j = 0; j < 4; j++) {
                uint32_t hi = f2tf32(av[j]);
                pah[j] = hi;
                pal[j] = f2tf32(av[j] - __uint_as_float(hi));
            }
            #pragma unroll
            for (int ntv = 0; ntv < 8; ntv++) {
                uint32_t bh2[2], bl2[2];
                bh2[0] = __float_as_uint(Vsh[(ks * 8 + tg) * VSP + ntv * 8 + grp]);
                bh2[1] = __float_as_uint(Vsh[(ks * 8 + tg + 4) * VSP + ntv * 8 + grp]);
                bl2[0] = __float_as_uint(Vsl[(ks * 8 + tg) * VSP + ntv * 8 + grp]);
                bl2[1] = __float_as_uint(Vsl[(ks * 8 + tg + 4) * VSP + ntv * 8 + grp]);
                mma_tf32(out[ntv], pah, bh2);
                mma_tf32(out[ntv], pal, bh2);
                mma_tf32(out[ntv], pah, bl2);
            }
        }
    }

    // normalize + bf16 splitpair + packed store (validated round 6)
    float inv0 = 1.f / l0, inv1 = 1.f / l1;
    size_t rA = ((size_t)(b * T + r0 + grp)) * C2 + h * 32;
    size_t rB = ((size_t)(b * T + r0 + grp + 8)) * C2 + h * 32;
    #pragma unroll
    for (int ntv = 0; ntv < 8; ntv++) {
        int cw = ntv * 4 + tg;
        uint32_t hw, lw;
        splitpair(out[ntv][0] * inv0, out[ntv][1] * inv0, hw, lw);
        g_ah[rA + cw] = hw;
        g_al[rA + cw] = lw;
        splitpair(out[ntv][2] * inv1, out[ntv][3] * inv1, hw, lw);
        g_ah[rB + cw] = hw;
        g_al[rB + cw] = lw;
    }
}

// ---------------------------------------------------------------------------
extern "C" void kernel_launch(void* const* d_in, const int* in_sizes, int n_in,
                              void* d_out, int out_size) {
    const float* x    = (const float*)d_in[0];
    const float* Wq   = (const float*)d_in[1];
    const float* Wk   = (const float*)d_in[2];
    const float* Wv   = (const float*)d_in[3];
    const float* Wo   = (const float*)d_in[4];
    const float* cosp = (const float*)d_in[5];
    const float* sinp = (const float*)d_in[6];
    float* out = (float*)d_out;

    static bool attr_done = false;
    if (!attr_done) {
        cudaFuncSetAttribute(qkv_gemm,
            cudaFuncAttributeMaxDynamicSharedMemorySize, 2 * GSTAGE * 4);
        cudaFuncSetAttribute(wo_gemm,
            cudaFuncAttributeMaxDynamicSharedMemorySize, 2 * GSTAGE * 4);
        cudaFuncSetAttribute(attn_kernel,
            cudaFuncAttributeMaxDynamicSharedMemorySize, 2 * ASTAGE * 4);
        attr_done = true;
    }

    void *xh, *xl, *wqh, *wql, *wkh, *wkl, *wvh, *wvl, *woh, *wol;
    cudaGetSymbolAddress(&xh,  g_xh);
    cudaGetSymbolAddress(&xl,  g_xl);
    cudaGetSymbolAddress(&wqh, g_wqh);
    cudaGetSymbolAddress(&wql, g_wql);
    cudaGetSymbolAddress(&wkh, g_wkh);
    cudaGetSymbolAddress(&wkl, g_wkl);
    cudaGetSymbolAddress(&wvh, g_wvh);
    cudaGetSymbolAddress(&wvl, g_wvl);
    cudaGetSymbolAddress(&woh, g_woh);
    cudaGetSymbolAddress(&wol, g_wol);

    int nx4 = M_TOT * C / 4;
    int nw4 = C * C / 4;
    split_kernel<<<nx4 / 256, 256>>>((const float4*)x,  (uint2*)xh,  (uint2*)xl,  nx4);
    split_kernel<<<nw4 / 256, 256>>>((const float4*)Wq, (uint2*)wqh, (uint2*)wql, nw4);
    split_kernel<<<nw4 / 256, 256>>>((const float4*)Wk, (uint2*)wkh, (uint2*)wkl, nw4);
    split_kernel<<<nw4 / 256, 256>>>((const float4*)Wv, (uint2*)wvh, (uint2*)wvl, nw4);
    split_kernel<<<nw4 / 256, 256>>>((const float4*)Wo, (uint2*)woh, (uint2*)wol, nw4);

    qkv_gemm<<<dim3(24, M_TOT / BM), 256, 2 * GSTAGE * 4>>>(cosp, sinp);

    attn_kernel<<<dim3(T / QB, B * H), 128, 2 * ASTAGE * 4>>>();

    wo_gemm<<<dim3(C / BN, M_TOT / BM), 256, 2 * GSTAGE * 4>>>(out);
}

// round 11
// speedup vs baseline: 4.9495x; 1.1391x over previous
#include <cuda_runtime.h>
#include <cuda_bf16.h>
#include <math.h>
#include <stdint.h>

#define B 2
#define T 2048
#define C 1024
#define H 16
#define HD 64
#define M_TOT (B*T)   // 4096
#define C2 (C/2)      // packed bf16x2 words per row

// ---------------- packed bf16x2 split inputs -------------------------------
__device__ __align__(16) uint32_t g_xh[M_TOT*C2], g_xl[M_TOT*C2];
__device__ __align__(16) uint32_t g_wqh[C*C2], g_wql[C*C2];
__device__ __align__(16) uint32_t g_wkh[C*C2], g_wkl[C*C2];
__device__ __align__(16) uint32_t g_wvh[C*C2], g_wvl[C*C2];
__device__ __align__(16) uint32_t g_woh[C*C2], g_wol[C*C2];
// ---------------- Q/K: packed bf16x2 split; V: tf32-split float ------------
__device__ __align__(16) uint32_t g_qh[M_TOT*C2], g_ql[M_TOT*C2];
__device__ __align__(16) uint32_t g_kh[M_TOT*C2], g_kl[M_TOT*C2];
__device__ __align__(16) float g_vhf[M_TOT*C], g_vlf[M_TOT*C];
// ---------------- packed bf16x2 attention output ---------------------------
__device__ __align__(16) uint32_t g_ah[M_TOT*C2], g_al[M_TOT*C2];

// ---------------------------------------------------------------------------
// helpers
// ---------------------------------------------------------------------------
__device__ __forceinline__ uint32_t f2tf32(float x) {
    uint32_t r;
    asm("cvt.rna.tf32.f32 %0, %1;" : "=r"(r) : "f"(x));
    return r;
}
__device__ __forceinline__ void split2(float v, float& h, float& l) {
    uint32_t hu = f2tf32(v);
    h = __uint_as_float(hu);
    l = __uint_as_float(f2tf32(v - h));
}
__device__ __forceinline__ void mma_tf32(float* d, const uint32_t* a,
                                         const uint32_t* b) {
    asm volatile(
        "mma.sync.aligned.m16n8k8.row.col.f32.tf32.tf32.f32 "
        "{%0,%1,%2,%3}, {%4,%5,%6,%7}, {%8,%9}, {%0,%1,%2,%3};"
        : "+f"(d[0]), "+f"(d[1]), "+f"(d[2]), "+f"(d[3])
        : "r"(a[0]), "r"(a[1]), "r"(a[2]), "r"(a[3]), "r"(b[0]), "r"(b[1]));
}
__device__ __forceinline__ void mma_bf16(float* d, const uint32_t* a,
                                         const uint32_t* b) {
    asm volatile(
        "mma.sync.aligned.m16n8k16.row.col.f32.bf16.bf16.f32 "
        "{%0,%1,%2,%3}, {%4,%5,%6,%7}, {%8,%9}, {%0,%1,%2,%3};"
        : "+f"(d[0]), "+f"(d[1]), "+f"(d[2]), "+f"(d[3])
        : "r"(a[0]), "r"(a[1]), "r"(a[2]), "r"(a[3]), "r"(b[0]), "r"(b[1]));
}
__device__ __forceinline__ uint32_t packbf2(float x, float y) {
    __nv_bfloat162 t = __floats2bfloat162_rn(x, y);
    return *reinterpret_cast<uint32_t*>(&t);
}
__device__ __forceinline__ void splitpair(float x, float y,
                                          uint32_t& hw, uint32_t& lw) {
    __nv_bfloat16 hx = __float2bfloat16(x);
    __nv_bfloat16 hy = __float2bfloat16(y);
    float rx = x - __bfloat162float(hx);
    float ry = y - __bfloat162float(hy);
    __nv_bfloat162 hp = {hx, hy};
    hw = *reinterpret_cast<uint32_t*>(&hp);
    lw = packbf2(rx, ry);
}
__device__ __forceinline__ void cp16(uint32_t saddr, const void* gptr) {
    asm volatile("cp.async.cg.shared.global [%0], [%1], 16;\n"
                 :: "r"(saddr), "l"(gptr));
}
#define CP_COMMIT() asm volatile("cp.async.commit_group;\n" ::)
#define CP_WAIT0()  asm volatile("cp.async.wait_group 0;\n" ::)

// ---------------------------------------------------------------------------
// split kernel: float4 -> 2 packed hi words + 2 packed lo words
// ---------------------------------------------------------------------------
__global__ void split_kernel(const float4* __restrict__ src,
                             uint2* __restrict__ dh,
                             uint2* __restrict__ dl, int n4) {
    int i = blockIdx.x * blockDim.x + threadIdx.x;
    if (i >= n4) return;
    float4 v = src[i];
    uint2 h, l;
    splitpair(v.x, v.y, h.x, l.x);
    splitpair(v.z, v.w, h.y, l.y);
    dh[i] = h;
    dl[i] = l;
}

// ---------------------------------------------------------------------------
// Fused QKV GEMM, bf16 3-term split core, cp.async double-buffered.
// Epilogue: Q/K -> RoPE + packed bf16x2 words; V -> tf32-split float stores.
// ---------------------------------------------------------------------------
#define BM 128
#define BN 128
#define KW 16
#define KP 20
#define GSTAGE 10240
#define NKIT (C2/KW)

__global__ void __launch_bounds__(256, 2) qkv_gemm(const float* __restrict__ cosp,
                                                   const float* __restrict__ sinp) {
    extern __shared__ uint32_t sm[];
    const int tid = threadIdx.x, lane = tid & 31, warp = tid >> 5;
    const int warpM = warp >> 2, warpN = warp & 3;
    const int grp = lane >> 2, tg = lane & 3;
    const int m0 = blockIdx.y * BM;
    const int nsel = blockIdx.x >> 3;
    const int n0c = (blockIdx.x & 7) * BN;

    const uint32_t* WH = (nsel == 0) ? g_wqh : (nsel == 1) ? g_wkh : g_wvh;
    const uint32_t* WL = (nsel == 0) ? g_wql : (nsel == 1) ? g_wkl : g_wvl;

    const int lrow = tid >> 2;
    const int lwq  = (tid & 3) << 2;
    const uint32_t sb = (uint32_t)__cvta_generic_to_shared(sm);

    float acc[4][4][4];
    #pragma unroll
    for (int mt = 0; mt < 4; mt++)
        #pragma unroll
        for (int nt = 0; nt < 4; nt++)
            #pragma unroll
            for (int i = 0; i < 4; i++) acc[mt][nt][i] = 0.f;

    #define QKV_ISSUE(stg, k0w) do {                                          \
        uint32_t base_ = sb + (stg) * (GSTAGE * 4);                           \
        size_t rA0_ = (size_t)(m0 + lrow) * C2 + (k0w) + lwq;                 \
        size_t rA1_ = (size_t)(m0 + lrow + 64) * C2 + (k0w) + lwq;            \
        size_t rB0_ = (size_t)(n0c + lrow) * C2 + (k0w) + lwq;                \
        size_t rB1_ = (size_t)(n0c + lrow + 64) * C2 + (k0w) + lwq;           \
        uint32_t dA0_ = base_ + (lrow * KP + lwq) * 4;                        \
        uint32_t dA1_ = base_ + ((lrow + 64) * KP + lwq) * 4;                 \
        cp16(dA0_, &g_xh[rA0_]);  cp16(dA1_, &g_xh[rA1_]);                    \
        cp16(dA0_ + 2560 * 4, &g_xl[rA0_]);                                   \
        cp16(dA1_ + 2560 * 4, &g_xl[rA1_]);                                   \
        uint32_t dB0_ = base_ + (5120 + lrow * KP + lwq) * 4;                 \
        uint32_t dB1_ = base_ + (5120 + (lrow + 64) * KP + lwq) * 4;          \
        cp16(dB0_, &WH[rB0_]);  cp16(dB1_, &WH[rB1_]);                        \
        cp16(dB0_ + 2560 * 4, &WL[rB0_]);                                     \
        cp16(dB1_ + 2560 * 4, &WL[rB1_]);                                     \
        CP_COMMIT();                                                          \
    } while (0)

    QKV_ISSUE(0, 0);

    for (int it = 0; it < NKIT; it++) {
        CP_WAIT0();
        __syncthreads();
        if (it + 1 < NKIT) QKV_ISSUE((it + 1) & 1, (it + 1) * KW);

        const uint32_t* Ah = sm + (it & 1) * GSTAGE;
        const uint32_t* Al = Ah + 2560;
        const uint32_t* Bh = Ah + 5120;
        const uint32_t* Bl = Ah + 7680;

        #pragma unroll
        for (int s8 = 0; s8 < KW; s8 += 8) {
            uint32_t ah[4][4], al[4][4];
            #pragma unroll
            for (int mt = 0; mt < 4; mt++) {
                int rb = warpM * 64 + mt * 16;
                ah[mt][0] = Ah[(rb + grp) * KP + s8 + tg];
                ah[mt][1] = Ah[(rb + grp + 8) * KP + s8 + tg];
                ah[mt][2] = Ah[(rb + grp) * KP + s8 + tg + 4];
                ah[mt][3] = Ah[(rb + grp + 8) * KP + s8 + tg + 4];
                al[mt][0] = Al[(rb + grp) * KP + s8 + tg];
                al[mt][1] = Al[(rb + grp + 8) * KP + s8 + tg];
                al[mt][2] = Al[(rb + grp) * KP + s8 + tg + 4];
                al[mt][3] = Al[(rb + grp + 8) * KP + s8 + tg + 4];
            }
            #pragma unroll
            for (int nt = 0; nt < 4; nt++) {
                int cb = warpN * 32 + nt * 8;
                uint32_t bh2[2], bl2[2];
                bh2[0] = Bh[(cb + grp) * KP + s8 + tg];
                bh2[1] = Bh[(cb + grp) * KP + s8 + tg + 4];
                bl2[0] = Bl[(cb + grp) * KP + s8 + tg];
                bl2[1] = Bl[(cb + grp) * KP + s8 + tg + 4];
                #pragma unroll
                for (int mt = 0; mt < 4; mt++) {
                    mma_bf16(acc[mt][nt], ah[mt], bh2);
                    mma_bf16(acc[mt][nt], al[mt], bh2);
                    mma_bf16(acc[mt][nt], ah[mt], bl2);
                }
            }
        }
    }

    // epilogue
    uint32_t* QKH = (nsel == 0) ? g_qh : g_kh;
    uint32_t* QKL = (nsel == 0) ? g_ql : g_kl;
    #pragma unroll
    for (int mt = 0; mt < 4; mt++) {
        int rowA = m0 + warpM * 64 + mt * 16 + grp;
        int rowB = rowA + 8;
        #pragma unroll
        for (int nt = 0; nt < 4; nt++) {
            int c = n0c + warpN * 32 + nt * 8 + 2 * tg;
            float a0 = acc[mt][nt][0], a1 = acc[mt][nt][1];
            float a2 = acc[mt][nt][2], a3 = acc[mt][nt][3];
            if (nsel < 2) {
                // RoPE + packed bf16x2 split store
                int d = (c & 63) >> 1;
                int t0 = rowA & (T - 1), t1 = rowB & (T - 1);
                float c0 = cosp[t0 * 32 + d], s0 = sinp[t0 * 32 + d];
                float c1 = cosp[t1 * 32 + d], s1 = sinp[t1 * 32 + d];
                float o0 = a0 * c0 - a1 * s0, o1 = a0 * s0 + a1 * c0;
                float o2 = a2 * c1 - a3 * s1, o3 = a2 * s1 + a3 * c1;
                uint32_t hw, lw;
                splitpair(o0, o1, hw, lw);
                QKH[(size_t)rowA * C2 + (c >> 1)] = hw;
                QKL[(size_t)rowA * C2 + (c >> 1)] = lw;
                splitpair(o2, o3, hw, lw);
                QKH[(size_t)rowB * C2 + (c >> 1)] = hw;
                QKL[(size_t)rowB * C2 + (c >> 1)] = lw;
            } else {
                // V: tf32 split float stores (validated round-8 path)
                float h0, l0v, h1, l1v, h2, l2v, h3, l3v;
                split2(a0, h0, l0v); split2(a1, h1, l1v);
                split2(a2, h2, l2v); split2(a3, h3, l3v);
                *(float2*)&g_vhf[(size_t)rowA * C + c] = make_float2(h0, h1);
                *(float2*)&g_vlf[(size_t)rowA * C + c] = make_float2(l0v, l1v);
                *(float2*)&g_vhf[(size_t)rowB * C + c] = make_float2(h2, h3);
                *(float2*)&g_vlf[(size_t)rowB * C + c] = make_float2(l2v, l3v);
            }
        }
    }
}

// ---------------------------------------------------------------------------
// Output GEMM: out = att @ Wo^T (unchanged from round 8)
// ---------------------------------------------------------------------------
__global__ void __launch_bounds__(256, 2) wo_gemm(float* __restrict__ out) {
    extern __shared__ uint32_t sm[];
    const int tid = threadIdx.x, lane = tid & 31, warp = tid >> 5;
    const int warpM = warp >> 2, warpN = warp & 3;
    const int grp = lane >> 2, tg = lane & 3;
    const int m0 = blockIdx.y * BM;
    const int n0 = blockIdx.x * BN;

    const int lrow = tid >> 2;
    const int lwq  = (tid & 3) << 2;
    const uint32_t sb = (uint32_t)__cvta_generic_to_shared(sm);

    float acc[4][4][4];
    #pragma unroll
    for (int mt = 0; mt < 4; mt++)
        #pragma unroll
        for (int nt = 0; nt < 4; nt++)
            #pragma unroll
            for (int i = 0; i < 4; i++) acc[mt][nt][i] = 0.f;

    #define WO_ISSUE(stg, k0w) do {                                           \
        uint32_t base_ = sb + (stg) * (GSTAGE * 4);                           \
        size_t rA0_ = (size_t)(m0 + lrow) * C2 + (k0w) + lwq;                 \
        size_t rA1_ = (size_t)(m0 + lrow + 64) * C2 + (k0w) + lwq;            \
        size_t rB0_ = (size_t)(n0 + lrow) * C2 + (k0w) + lwq;                 \
        size_t rB1_ = (size_t)(n0 + lrow + 64) * C2 + (k0w) + lwq;            \
        uint32_t dA0_ = base_ + (lrow * KP + lwq) * 4;                        \
        uint32_t dA1_ = base_ + ((lrow + 64) * KP + lwq) * 4;                 \
        cp16(dA0_, &g_ah[rA0_]);  cp16(dA1_, &g_ah[rA1_]);                    \
        cp16(dA0_ + 2560 * 4, &g_al[rA0_]);                                   \
        cp16(dA1_ + 2560 * 4, &g_al[rA1_]);                                   \
        uint32_t dB0_ = base_ + (5120 + lrow * KP + lwq) * 4;                 \
        uint32_t dB1_ = base_ + (5120 + (lrow + 64) * KP + lwq) * 4;          \
        cp16(dB0_, &g_woh[rB0_]);  cp16(dB1_, &g_woh[rB1_]);                  \
        cp16(dB0_ + 2560 * 4, &g_wol[rB0_]);                                  \
        cp16(dB1_ + 2560 * 4, &g_wol[rB1_]);                                  \
        CP_COMMIT();                                                          \
    } while (0)

    WO_ISSUE(0, 0);

    for (int it = 0; it < NKIT; it++) {
        CP_WAIT0();
        __syncthreads();
        if (it + 1 < NKIT) WO_ISSUE((it + 1) & 1, (it + 1) * KW);

        const uint32_t* Ah = sm + (it & 1) * GSTAGE;
        const uint32_t* Al = Ah + 2560;
        const uint32_t* Bh = Ah + 5120;
        const uint32_t* Bl = Ah + 7680;

        #pragma unroll
        for (int s8 = 0; s8 < KW; s8 += 8) {
            uint32_t ah[4][4], al[4][4];
            #pragma unroll
            for (int mt = 0; mt < 4; mt++) {
                int rb = warpM * 64 + mt * 16;
                ah[mt][0] = Ah[(rb + grp) * KP + s8 + tg];
                ah[mt][1] = Ah[(rb + grp + 8) * KP + s8 + tg];
                ah[mt][2] = Ah[(rb + grp) * KP + s8 + tg + 4];
                ah[mt][3] = Ah[(rb + grp + 8) * KP + s8 + tg + 4];
                al[mt][0] = Al[(rb + grp) * KP + s8 + tg];
                al[mt][1] = Al[(rb + grp + 8) * KP + s8 + tg];
                al[mt][2] = Al[(rb + grp) * KP + s8 + tg + 4];
                al[mt][3] = Al[(rb + grp + 8) * KP + s8 + tg + 4];
            }
            #pragma unroll
            for (int nt = 0; nt < 4; nt++) {
                int cb = warpN * 32 + nt * 8;
                uint32_t bh2[2], bl2[2];
                bh2[0] = Bh[(cb + grp) * KP + s8 + tg];
                bh2[1] = Bh[(cb + grp) * KP + s8 + tg + 4];
                bl2[0] = Bl[(cb + grp) * KP + s8 + tg];
                bl2[1] = Bl[(cb + grp) * KP + s8 + tg + 4];
                #pragma unroll
                for (int mt = 0; mt < 4; mt++) {
                    mma_bf16(acc[mt][nt], ah[mt], bh2);
                    mma_bf16(acc[mt][nt], al[mt], bh2);
                    mma_bf16(acc[mt][nt], ah[mt], bl2);
                }
            }
        }
    }

    #pragma unroll
    for (int mt = 0; mt < 4; mt++) {
        int rowA = m0 + warpM * 64 + mt * 16 + grp;
        #pragma unroll
        for (int nt = 0; nt < 4; nt++) {
            int c = n0 + warpN * 32 + nt * 8 + 2 * tg;
            *(float2*)&out[(size_t)rowA * C + c] =
                make_float2(acc[mt][nt][0], acc[mt][nt][1]);
            *(float2*)&out[(size_t)(rowA + 8) * C + c] =
                make_float2(acc[mt][nt][2], acc[mt][nt][3]);
        }
    }
}

// ---------------------------------------------------------------------------
// Causal flash attention: bf16 3-term S phase (packed Q/K), tf32 3-term PV.
// K-tile loader FIXED: 32 rows x 32 words (was 16 words -> garbage upper
// half, the NaN source in rounds 5/7/9).
// Per-stage word layout: Kh[32*36] @0, Kl @1152, Vh(float 32*72) @2304,
// Vl @4608; stage = 6912 words.
// ---------------------------------------------------------------------------
#define QB 64
#define KB 32
#define KSW 36
#define VSPW 72
#define AST_KL 1152
#define AST_VH 2304
#define AST_VL 4608
#define ASTAGE 6912

__global__ void __launch_bounds__(128, 2) attn_kernel() {
    extern __shared__ uint32_t sm[];

    const int tid  = threadIdx.x;
    const int lane = tid & 31;
    const int warp = tid >> 5;
    const int grp  = lane >> 2;
    const int tg   = lane & 3;
    const int bh   = blockIdx.y;
    const int b    = bh >> 4, h = bh & 15;
    const int qx   = gridDim.x - 1 - (int)blockIdx.x;   // heavy blocks first
    const int q0   = qx * QB;
    const int r0   = q0 + warp * 16;
    const uint32_t sb = (uint32_t)__cvta_generic_to_shared(sm);

    // Q fragments: packed bf16x2 along hd, 4 k16 steps
    uint32_t qfh[4][4], qfl[4][4];
    {
        const uint32_t* QHa = g_qh + ((size_t)(b * T + r0)) * C2 + h * 32;
        const uint32_t* QLa = g_ql + ((size_t)(b * T + r0)) * C2 + h * 32;
        #pragma unroll
        for (int ks = 0; ks < 4; ks++) {
            qfh[ks][0] = QHa[(size_t)grp * C2 + ks * 8 + tg];
            qfh[ks][1] = QHa[(size_t)(grp + 8) * C2 + ks * 8 + tg];
            qfh[ks][2] = QHa[(size_t)grp * C2 + ks * 8 + tg + 4];
            qfh[ks][3] = QHa[(size_t)(grp + 8) * C2 + ks * 8 + tg + 4];
            qfl[ks][0] = QLa[(size_t)grp * C2 + ks * 8 + tg];
            qfl[ks][1] = QLa[(size_t)(grp + 8) * C2 + ks * 8 + tg];
            qfl[ks][2] = QLa[(size_t)grp * C2 + ks * 8 + tg + 4];
            qfl[ks][3] = QLa[(size_t)(grp + 8) * C2 + ks * 8 + tg + 4];
        }
    }

    float out[8][4];
    #pragma unroll
    for (int i = 0; i < 8; i++)
        #pragma unroll
        for (int j = 0; j < 4; j++) out[i][j] = 0.f;
    float m0v = -1e30f, m1v = -1e30f, l0 = 0.f, l1 = 0.f;

    const int nIter = 2 * (qx + 1);

    // K: 32 rows x 32 words -> 256 x 16B chunks -> 2 per thread (FIXED)
    // V: 32 rows x 64 floats x 2 arrays -> 4 x 16B per thread
    #define ATT_ISSUE(stg, k0) do {                                           \
        uint32_t base_ = sb + (stg) * (ASTAGE * 4);                           \
        _Pragma("unroll")                                                     \
        for (int i_ = 0; i_ < 2; i_++) {                                      \
            int idk_ = tid + i_ * 128;                                        \
            int krow_ = idk_ >> 3, kwq_ = (idk_ & 7) << 2;                    \
            size_t koff_ = ((size_t)(b * T + (k0) + krow_)) * C2 + h * 32 + kwq_; \
            cp16(base_ + (krow_ * KSW + kwq_) * 4, &g_kh[koff_]);             \
            cp16(base_ + (AST_KL + krow_ * KSW + kwq_) * 4, &g_kl[koff_]);    \
        }                                                                     \
        _Pragma("unroll")                                                     \
        for (int i_ = 0; i_ < 4; i_++) {                                      \
            int idx_ = tid + i_ * 128;                                        \
            int rv_ = idx_ >> 4, c4_ = (idx_ & 15) << 2;                      \
            size_t voff_ = ((size_t)(b * T + (k0) + rv_)) * C + h * HD + c4_; \
            cp16(base_ + (AST_VH + rv_ * VSPW + c4_) * 4, &g_vhf[voff_]);     \
            cp16(base_ + (AST_VL + rv_ * VSPW + c4_) * 4, &g_vlf[voff_]);     \
        }                                                                     \
        CP_COMMIT();                                                          \
    } while (0)

    ATT_ISSUE(0, 0);

    for (int t = 0; t < nIter; t++) {
        const int k0 = t * KB;
        CP_WAIT0();
        __syncthreads();
        if (t + 1 < nIter) ATT_ISSUE((t + 1) & 1, (t + 1) * KB);

        if (k0 > r0 + 15) continue;

        const uint32_t* Ksh = sm + (t & 1) * ASTAGE;
        const uint32_t* Ksl = Ksh + AST_KL;
        const float* Vsh = (const float*)(Ksh + AST_VH);
        const float* Vsl = (const float*)(Ksh + AST_VL);

        // ---- S = Q K^T, bf16 3-term ----
        float s[4][4];
        #pragma unroll
        for (int nt = 0; nt < 4; nt++)
            #pragma unroll
            for (int j = 0; j < 4; j++) s[nt][j] = 0.f;

        #pragma unroll
        for (int nt = 0; nt < 4; nt++) {
            #pragma unroll
            for (int ks = 0; ks < 4; ks++) {
                uint32_t bh2[2], bl2[2];
                bh2[0] = Ksh[(nt * 8 + grp) * KSW + ks * 8 + tg];
                bh2[1] = Ksh[(nt * 8 + grp) * KSW + ks * 8 + tg + 4];
                bl2[0] = Ksl[(nt * 8 + grp) * KSW + ks * 8 + tg];
                bl2[1] = Ksl[(nt * 8 + grp) * KSW + ks * 8 + tg + 4];
                mma_bf16(s[nt], qfh[ks], bh2);
                mma_bf16(s[nt], qfl[ks], bh2);
                mma_bf16(s[nt], qfh[ks], bl2);
            }
        }

        // ---- scale + causal mask ----
        const int row0 = r0 + grp, row1 = r0 + grp + 8;
        if (k0 + KB - 1 <= r0) {
            #pragma unroll
            for (int nt = 0; nt < 4; nt++)
                #pragma unroll
                for (int j = 0; j < 4; j++) s[nt][j] *= 0.125f;
        } else {
            #pragma unroll
            for (int nt = 0; nt < 4; nt++) {
                int col = k0 + nt * 8 + 2 * tg;
                s[nt][0] = (col     <= row0) ? s[nt][0] * 0.125f : -1e30f;
                s[nt][1] = (col + 1 <= row0) ? s[nt][1] * 0.125f : -1e30f;
                s[nt][2] = (col     <= row1) ? s[nt][2] * 0.125f : -1e30f;
                s[nt][3] = (col + 1 <= row1) ? s[nt][3] * 0.125f : -1e30f;
            }
        }

        // ---- online softmax ----
        float mx0 = s[0][0], mx1 = s[0][2];
        #pragma unroll
        for (int nt = 0; nt < 4; nt++) {
            mx0 = fmaxf(mx0, fmaxf(s[nt][0], s[nt][1]));
            mx1 = fmaxf(mx1, fmaxf(s[nt][2], s[nt][3]));
        }
        mx0 = fmaxf(mx0, __shfl_xor_sync(0xffffffffu, mx0, 1));
        mx0 = fmaxf(mx0, __shfl_xor_sync(0xffffffffu, mx0, 2));
        mx1 = fmaxf(mx1, __shfl_xor_sync(0xffffffffu, mx1, 1));
        mx1 = fmaxf(mx1, __shfl_xor_sync(0xffffffffu, mx1, 2));
        float nm0 = fmaxf(m0v, mx0), nm1 = fmaxf(m1v, mx1);
        float c0 = __expf(m0v - nm0), c1 = __expf(m1v - nm1);

        float sum0 = 0.f, sum1 = 0.f;
        #pragma unroll
        for (int nt = 0; nt < 4; nt++) {
            s[nt][0] = __expf(s[nt][0] - nm0);
            s[nt][1] = __expf(s[nt][1] - nm0);
            s[nt][2] = __expf(s[nt][2] - nm1);
            s[nt][3] = __expf(s[nt][3] - nm1);
            sum0 += s[nt][0] + s[nt][1];
            sum1 += s[nt][2] + s[nt][3];
        }
        sum0 += __shfl_xor_sync(0xffffffffu, sum0, 1);
        sum0 += __shfl_xor_sync(0xffffffffu, sum0, 2);
        sum1 += __shfl_xor_sync(0xffffffffu, sum1, 1);
        sum1 += __shfl_xor_sync(0xffffffffu, sum1, 2);
        l0 = l0 * c0 + sum0;
        l1 = l1 * c1 + sum1;
        m0v = nm0; m1v = nm1;

        #pragma unroll
        for (int i = 0; i < 8; i++) {
            out[i][0] *= c0; out[i][1] *= c0;
            out[i][2] *= c1; out[i][3] *= c1;
        }

        // ---- PV: tf32 3-term (validated), shuffle C->A remap ----
        const int src1 = (lane & ~3) | (tg >> 1);
        const int src2 = src1 + 2;
        const bool odd = tg & 1;
        #pragma unroll
        for (int ks = 0; ks < 4; ks++) {
            float w0 = __shfl_sync(0xffffffffu, s[ks][0], src1);
            float w1 = __shfl_sync(0xffffffffu, s[ks][1], src1);
            float w2 = __shfl_sync(0xffffffffu, s[ks][2], src1);
            float w3 = __shfl_sync(0xffffffffu, s[ks][3], src1);
            float x0 = __shfl_sync(0xffffffffu, s[ks][0], src2);
            float x1 = __shfl_sync(0xffffffffu, s[ks][1], src2);
            float x2 = __shfl_sync(0xffffffffu, s[ks][2], src2);
            float x3 = __shfl_sync(0xffffffffu, s[ks][3], src2);
            float a0 = odd ? w1 : w0;
            float a1 = odd ? w3 : w2;
            float a2 = odd ? x1 : x0;
            float a3 = odd ? x3 : x2;
            uint32_t pah[4], pal[4];
            float av[4] = {a0, a1, a2, a3};
            #pragma unroll
            for (int j = 0; j < 4; j++) {
                uint32_t hi = f2tf32(av[j]);
                pah[j] = hi;
                pal[j] = f2tf32(av[j] - __uint_as_float(hi));
            }
            #pragma unroll
            for (int ntv = 0; ntv < 8; ntv++) {
                uint32_t bh2[2], bl2[2];
                bh2[0] = __float_as_uint(Vsh[(ks * 8 + tg) * VSPW + ntv * 8 + grp]);
                bh2[1] = __float_as_uint(Vsh[(ks * 8 + tg + 4) * VSPW + ntv * 8 + grp]);
                bl2[0] = __float_as_uint(Vsl[(ks * 8 + tg) * VSPW + ntv * 8 + grp]);
                bl2[1] = __float_as_uint(Vsl[(ks * 8 + tg + 4) * VSPW + ntv * 8 + grp]);
                mma_tf32(out[ntv], pah, bh2);
                mma_tf32(out[ntv], pal, bh2);
                mma_tf32(out[ntv], pah, bl2);
            }
        }
    }

    // normalize + bf16 splitpair + packed store
    float inv0 = 1.f / l0, inv1 = 1.f / l1;
    size_t rA = ((size_t)(b * T + r0 + grp)) * C2 + h * 32;
    size_t rB = ((size_t)(b * T + r0 + grp + 8)) * C2 + h * 32;
    #pragma unroll
    for (int ntv = 0; ntv < 8; ntv++) {
        int cw = ntv * 4 + tg;
        uint32_t hw, lw;
        splitpair(out[ntv][0] * inv0, out[ntv][1] * inv0, hw, lw);
        g_ah[rA + cw] = hw;
        g_al[rA + cw] = lw;
        splitpair(out[ntv][2] * inv1, out[ntv][3] * inv1, hw, lw);
        g_ah[rB + cw] = hw;
        g_al[rB + cw] = lw;
    }
}

// ---------------------------------------------------------------------------
extern "C" void kernel_launch(void* const* d_in, const int* in_sizes, int n_in,
                              void* d_out, int out_size) {
    const float* x    = (const float*)d_in[0];
    const float* Wq   = (const float*)d_in[1];
    const float* Wk   = (const float*)d_in[2];
    const float* Wv   = (const float*)d_in[3];
    const float* Wo   = (const float*)d_in[4];
    const float* cosp = (const float*)d_in[5];
    const float* sinp = (const float*)d_in[6];
    float* out = (float*)d_out;

    static bool attr_done = false;
    if (!attr_done) {
        cudaFuncSetAttribute(qkv_gemm,
            cudaFuncAttributeMaxDynamicSharedMemorySize, 2 * GSTAGE * 4);
        cudaFuncSetAttribute(wo_gemm,
            cudaFuncAttributeMaxDynamicSharedMemorySize, 2 * GSTAGE * 4);
        cudaFuncSetAttribute(attn_kernel,
            cudaFuncAttributeMaxDynamicSharedMemorySize, 2 * ASTAGE * 4);
        attr_done = true;
    }

    void *xh, *xl, *wqh, *wql, *wkh, *wkl, *wvh, *wvl, *woh, *wol;
    cudaGetSymbolAddress(&xh,  g_xh);
    cudaGetSymbolAddress(&xl,  g_xl);
    cudaGetSymbolAddress(&wqh, g_wqh);
    cudaGetSymbolAddress(&wql, g_wql);
    cudaGetSymbolAddress(&wkh, g_wkh);
    cudaGetSymbolAddress(&wkl, g_wkl);
    cudaGetSymbolAddress(&wvh, g_wvh);
    cudaGetSymbolAddress(&wvl, g_wvl);
    cudaGetSymbolAddress(&woh, g_woh);
    cudaGetSymbolAddress(&wol, g_wol);

    int nx4 = M_TOT * C / 4;
    int nw4 = C * C / 4;
    split_kernel<<<nx4 / 256, 256>>>((const float4*)x,  (uint2*)xh,  (uint2*)xl,  nx4);
    split_kernel<<<nw4 / 256, 256>>>((const float4*)Wq, (uint2*)wqh, (uint2*)wql, nw4);
    split_kernel<<<nw4 / 256, 256>>>((const float4*)Wk, (uint2*)wkh, (uint2*)wkl, nw4);
    split_kernel<<<nw4 / 256, 256>>>((const float4*)Wv, (uint2*)wvh, (uint2*)wvl, nw4);
    split_kernel<<<nw4 / 256, 256>>>((const float4*)Wo, (uint2*)woh, (uint2*)wol, nw4);

    qkv_gemm<<<dim3(24, M_TOT / BM), 256, 2 * GSTAGE * 4>>>(cosp, sinp);

    attn_kernel<<<dim3(T / QB, B * H), 128, 2 * ASTAGE * 4>>>();

    wo_gemm<<<dim3(C / BN, M_TOT / BM), 256, 2 * GSTAGE * 4>>>(out);
}

// round 12
// speedup vs baseline: 5.5356x; 1.1184x over previous
#include <cuda_runtime.h>
#include <cuda_bf16.h>
#include <math.h>
#include <stdint.h>

#define B 2
#define T 2048
#define C 1024
#define H 16
#define HD 64
#define M_TOT (B*T)   // 4096
#define C2 (C/2)      // packed bf16x2 words per row
#define T2 (T/2)

// ---------------- packed bf16x2 split inputs -------------------------------
__device__ __align__(16) uint32_t g_xh[M_TOT*C2], g_xl[M_TOT*C2];
__device__ __align__(16) uint32_t g_wqh[C*C2], g_wql[C*C2];
__device__ __align__(16) uint32_t g_wkh[C*C2], g_wkl[C*C2];
__device__ __align__(16) uint32_t g_wvh[C*C2], g_wvl[C*C2];
__device__ __align__(16) uint32_t g_woh[C*C2], g_wol[C*C2];
// ---------------- Q/K packed bf16x2; V transposed [b,h,hd,t] packed --------
__device__ __align__(16) uint32_t g_qh[M_TOT*C2], g_ql[M_TOT*C2];
__device__ __align__(16) uint32_t g_kh[M_TOT*C2], g_kl[M_TOT*C2];
__device__ __align__(16) uint32_t g_vth[B*H*HD*T2], g_vtl[B*H*HD*T2];
// ---------------- packed bf16x2 attention output ---------------------------
__device__ __align__(16) uint32_t g_ah[M_TOT*C2], g_al[M_TOT*C2];

// ---------------------------------------------------------------------------
// helpers
// ---------------------------------------------------------------------------
__device__ __forceinline__ void mma_bf16(float* d, const uint32_t* a,
                                         const uint32_t* b) {
    asm volatile(
        "mma.sync.aligned.m16n8k16.row.col.f32.bf16.bf16.f32 "
        "{%0,%1,%2,%3}, {%4,%5,%6,%7}, {%8,%9}, {%0,%1,%2,%3};"
        : "+f"(d[0]), "+f"(d[1]), "+f"(d[2]), "+f"(d[3])
        : "r"(a[0]), "r"(a[1]), "r"(a[2]), "r"(a[3]), "r"(b[0]), "r"(b[1]));
}
__device__ __forceinline__ uint32_t packbf2(float x, float y) {
    __nv_bfloat162 t = __floats2bfloat162_rn(x, y);
    return *reinterpret_cast<uint32_t*>(&t);
}
__device__ __forceinline__ void splitpair(float x, float y,
                                          uint32_t& hw, uint32_t& lw) {
    __nv_bfloat16 hx = __float2bfloat16(x);
    __nv_bfloat16 hy = __float2bfloat16(y);
    float rx = x - __bfloat162float(hx);
    float ry = y - __bfloat162float(hy);
    __nv_bfloat162 hp = {hx, hy};
    hw = *reinterpret_cast<uint32_t*>(&hp);
    lw = packbf2(rx, ry);
}
__device__ __forceinline__ void split1(float v, __nv_bfloat16& h,
                                       __nv_bfloat16& l) {
    h = __float2bfloat16(v);
    l = __float2bfloat16(v - __bfloat162float(h));
}
__device__ __forceinline__ void cp16(uint32_t saddr, const void* gptr) {
    asm volatile("cp.async.cg.shared.global [%0], [%1], 16;\n"
                 :: "r"(saddr), "l"(gptr));
}
#define CP_COMMIT() asm volatile("cp.async.commit_group;\n" ::)
#define CP_WAIT0()  asm volatile("cp.async.wait_group 0;\n" ::)

// ---------------------------------------------------------------------------
// split kernel: float4 -> 2 packed hi words + 2 packed lo words
// ---------------------------------------------------------------------------
__global__ void split_kernel(const float4* __restrict__ src,
                             uint2* __restrict__ dh,
                             uint2* __restrict__ dl, int n4) {
    int i = blockIdx.x * blockDim.x + threadIdx.x;
    if (i >= n4) return;
    float4 v = src[i];
    uint2 h, l;
    splitpair(v.x, v.y, h.x, l.x);
    splitpair(v.z, v.w, h.y, l.y);
    dh[i] = h;
    dl[i] = l;
}

// ---------------------------------------------------------------------------
// Fused QKV GEMM, bf16 3-term split core, cp.async double-buffered.
// Epilogue: Q/K -> RoPE + packed bf16x2; V -> transposed bf16 hi/lo scatter.
// ---------------------------------------------------------------------------
#define BM 128
#define BN 128
#define KW 16
#define KP 20
#define GSTAGE 10240
#define NKIT (C2/KW)

__global__ void __launch_bounds__(256, 2) qkv_gemm(const float* __restrict__ cosp,
                                                   const float* __restrict__ sinp) {
    extern __shared__ uint32_t sm[];
    const int tid = threadIdx.x, lane = tid & 31, warp = tid >> 5;
    const int warpM = warp >> 2, warpN = warp & 3;
    const int grp = lane >> 2, tg = lane & 3;
    const int m0 = blockIdx.y * BM;
    const int nsel = blockIdx.x >> 3;
    const int n0c = (blockIdx.x & 7) * BN;

    const uint32_t* WH = (nsel == 0) ? g_wqh : (nsel == 1) ? g_wkh : g_wvh;
    const uint32_t* WL = (nsel == 0) ? g_wql : (nsel == 1) ? g_wkl : g_wvl;

    const int lrow = tid >> 2;
    const int lwq  = (tid & 3) << 2;
    const uint32_t sb = (uint32_t)__cvta_generic_to_shared(sm);

    float acc[4][4][4];
    #pragma unroll
    for (int mt = 0; mt < 4; mt++)
        #pragma unroll
        for (int nt = 0; nt < 4; nt++)
            #pragma unroll
            for (int i = 0; i < 4; i++) acc[mt][nt][i] = 0.f;

    #define QKV_ISSUE(stg, k0w) do {                                          \
        uint32_t base_ = sb + (stg) * (GSTAGE * 4);                           \
        size_t rA0_ = (size_t)(m0 + lrow) * C2 + (k0w) + lwq;                 \
        size_t rA1_ = (size_t)(m0 + lrow + 64) * C2 + (k0w) + lwq;            \
        size_t rB0_ = (size_t)(n0c + lrow) * C2 + (k0w) + lwq;                \
        size_t rB1_ = (size_t)(n0c + lrow + 64) * C2 + (k0w) + lwq;           \
        uint32_t dA0_ = base_ + (lrow * KP + lwq) * 4;                        \
        uint32_t dA1_ = base_ + ((lrow + 64) * KP + lwq) * 4;                 \
        cp16(dA0_, &g_xh[rA0_]);  cp16(dA1_, &g_xh[rA1_]);                    \
        cp16(dA0_ + 2560 * 4, &g_xl[rA0_]);                                   \
        cp16(dA1_ + 2560 * 4, &g_xl[rA1_]);                                   \
        uint32_t dB0_ = base_ + (5120 + lrow * KP + lwq) * 4;                 \
        uint32_t dB1_ = base_ + (5120 + (lrow + 64) * KP + lwq) * 4;          \
        cp16(dB0_, &WH[rB0_]);  cp16(dB1_, &WH[rB1_]);                        \
        cp16(dB0_ + 2560 * 4, &WL[rB0_]);                                     \
        cp16(dB1_ + 2560 * 4, &WL[rB1_]);                                     \
        CP_COMMIT();                                                          \
    } while (0)

    QKV_ISSUE(0, 0);

    for (int it = 0; it < NKIT; it++) {
        CP_WAIT0();
        __syncthreads();
        if (it + 1 < NKIT) QKV_ISSUE((it + 1) & 1, (it + 1) * KW);

        const uint32_t* Ah = sm + (it & 1) * GSTAGE;
        const uint32_t* Al = Ah + 2560;
        const uint32_t* Bh = Ah + 5120;
        const uint32_t* Bl = Ah + 7680;

        #pragma unroll
        for (int s8 = 0; s8 < KW; s8 += 8) {
            uint32_t ah[4][4], al[4][4];
            #pragma unroll
            for (int mt = 0; mt < 4; mt++) {
                int rb = warpM * 64 + mt * 16;
                ah[mt][0] = Ah[(rb + grp) * KP + s8 + tg];
                ah[mt][1] = Ah[(rb + grp + 8) * KP + s8 + tg];
                ah[mt][2] = Ah[(rb + grp) * KP + s8 + tg + 4];
                ah[mt][3] = Ah[(rb + grp + 8) * KP + s8 + tg + 4];
                al[mt][0] = Al[(rb + grp) * KP + s8 + tg];
                al[mt][1] = Al[(rb + grp + 8) * KP + s8 + tg];
                al[mt][2] = Al[(rb + grp) * KP + s8 + tg + 4];
                al[mt][3] = Al[(rb + grp + 8) * KP + s8 + tg + 4];
            }
            #pragma unroll
            for (int nt = 0; nt < 4; nt++) {
                int cb = warpN * 32 + nt * 8;
                uint32_t bh2[2], bl2[2];
                bh2[0] = Bh[(cb + grp) * KP + s8 + tg];
                bh2[1] = Bh[(cb + grp) * KP + s8 + tg + 4];
                bl2[0] = Bl[(cb + grp) * KP + s8 + tg];
                bl2[1] = Bl[(cb + grp) * KP + s8 + tg + 4];
                #pragma unroll
                for (int mt = 0; mt < 4; mt++) {
                    mma_bf16(acc[mt][nt], ah[mt], bh2);
                    mma_bf16(acc[mt][nt], al[mt], bh2);
                    mma_bf16(acc[mt][nt], ah[mt], bl2);
                }
            }
        }
    }

    // epilogue
    uint32_t* QKH = (nsel == 0) ? g_qh : g_kh;
    uint32_t* QKL = (nsel == 0) ? g_ql : g_kl;
    __nv_bfloat16* VTH = (__nv_bfloat16*)g_vth;
    __nv_bfloat16* VTL = (__nv_bfloat16*)g_vtl;
    #pragma unroll
    for (int mt = 0; mt < 4; mt++) {
        int rowA = m0 + warpM * 64 + mt * 16 + grp;
        int rowB = rowA + 8;
        #pragma unroll
        for (int nt = 0; nt < 4; nt++) {
            int c = n0c + warpN * 32 + nt * 8 + 2 * tg;
            float a0 = acc[mt][nt][0], a1 = acc[mt][nt][1];
            float a2 = acc[mt][nt][2], a3 = acc[mt][nt][3];
            if (nsel < 2) {
                // RoPE + packed bf16x2 split store
                int d = (c & 63) >> 1;
                int t0 = rowA & (T - 1), t1 = rowB & (T - 1);
                float c0 = cosp[t0 * 32 + d], s0 = sinp[t0 * 32 + d];
                float c1 = cosp[t1 * 32 + d], s1 = sinp[t1 * 32 + d];
                float o0 = a0 * c0 - a1 * s0, o1 = a0 * s0 + a1 * c0;
                float o2 = a2 * c1 - a3 * s1, o3 = a2 * s1 + a3 * c1;
                uint32_t hw, lw;
                splitpair(o0, o1, hw, lw);
                QKH[(size_t)rowA * C2 + (c >> 1)] = hw;
                QKL[(size_t)rowA * C2 + (c >> 1)] = lw;
                splitpair(o2, o3, hw, lw);
                QKH[(size_t)rowB * C2 + (c >> 1)] = hw;
                QKL[(size_t)rowB * C2 + (c >> 1)] = lw;
            } else {
                // V transposed [b][h][hd][t] bf16 hi/lo scatter
                int bb = rowA >> 11;          // batch (rows 0..2047 -> 0)
                int hh = c >> 6, hd = c & 63;
                size_t base = ((size_t)(bb * H + hh) * HD + hd) * T;
                int tA = rowA & (T - 1), tB = rowB & (T - 1);
                float vals[4] = {a0, a1, a2, a3};
                size_t idxs[4] = {base + tA, base + T + tA,
                                  base + tB, base + T + tB};
                #pragma unroll
                for (int j = 0; j < 4; j++) {
                    __nv_bfloat16 hv, lv;
                    split1(vals[j], hv, lv);
                    VTH[idxs[j]] = hv;
                    VTL[idxs[j]] = lv;
                }
            }
        }
    }
}

// ---------------------------------------------------------------------------
// Output GEMM: out = att @ Wo^T (unchanged, validated)
// ---------------------------------------------------------------------------
__global__ void __launch_bounds__(256, 2) wo_gemm(float* __restrict__ out) {
    extern __shared__ uint32_t sm[];
    const int tid = threadIdx.x, lane = tid & 31, warp = tid >> 5;
    const int warpM = warp >> 2, warpN = warp & 3;
    const int grp = lane >> 2, tg = lane & 3;
    const int m0 = blockIdx.y * BM;
    const int n0 = blockIdx.x * BN;

    const int lrow = tid >> 2;
    const int lwq  = (tid & 3) << 2;
    const uint32_t sb = (uint32_t)__cvta_generic_to_shared(sm);

    float acc[4][4][4];
    #pragma unroll
    for (int mt = 0; mt < 4; mt++)
        #pragma unroll
        for (int nt = 0; nt < 4; nt++)
            #pragma unroll
            for (int i = 0; i < 4; i++) acc[mt][nt][i] = 0.f;

    #define WO_ISSUE(stg, k0w) do {                                           \
        uint32_t base_ = sb + (stg) * (GSTAGE * 4);                           \
        size_t rA0_ = (size_t)(m0 + lrow) * C2 + (k0w) + lwq;                 \
        size_t rA1_ = (size_t)(m0 + lrow + 64) * C2 + (k0w) + lwq;            \
        size_t rB0_ = (size_t)(n0 + lrow) * C2 + (k0w) + lwq;                 \
        size_t rB1_ = (size_t)(n0 + lrow + 64) * C2 + (k0w) + lwq;            \
        uint32_t dA0_ = base_ + (lrow * KP + lwq) * 4;                        \
        uint32_t dA1_ = base_ + ((lrow + 64) * KP + lwq) * 4;                 \
        cp16(dA0_, &g_ah[rA0_]);  cp16(dA1_, &g_ah[rA1_]);                    \
        cp16(dA0_ + 2560 * 4, &g_al[rA0_]);                                   \
        cp16(dA1_ + 2560 * 4, &g_al[rA1_]);                                   \
        uint32_t dB0_ = base_ + (5120 + lrow * KP + lwq) * 4;                 \
        uint32_t dB1_ = base_ + (5120 + (lrow + 64) * KP + lwq) * 4;          \
        cp16(dB0_, &g_woh[rB0_]);  cp16(dB1_, &g_woh[rB1_]);                  \
        cp16(dB0_ + 2560 * 4, &g_wol[rB0_]);                                  \
        cp16(dB1_ + 2560 * 4, &g_wol[rB1_]);                                  \
        CP_COMMIT();                                                          \
    } while (0)

    WO_ISSUE(0, 0);

    for (int it = 0; it < NKIT; it++) {
        CP_WAIT0();
        __syncthreads();
        if (it + 1 < NKIT) WO_ISSUE((it + 1) & 1, (it + 1) * KW);

        const uint32_t* Ah = sm + (it & 1) * GSTAGE;
        const uint32_t* Al = Ah + 2560;
        const uint32_t* Bh = Ah + 5120;
        const uint32_t* Bl = Ah + 7680;

        #pragma unroll
        for (int s8 = 0; s8 < KW; s8 += 8) {
            uint32_t ah[4][4], al[4][4];
            #pragma unroll
            for (int mt = 0; mt < 4; mt++) {
                int rb = warpM * 64 + mt * 16;
                ah[mt][0] = Ah[(rb + grp) * KP + s8 + tg];
                ah[mt][1] = Ah[(rb + grp + 8) * KP + s8 + tg];
                ah[mt][2] = Ah[(rb + grp) * KP + s8 + tg + 4];
                ah[mt][3] = Ah[(rb + grp + 8) * KP + s8 + tg + 4];
                al[mt][0] = Al[(rb + grp) * KP + s8 + tg];
                al[mt][1] = Al[(rb + grp + 8) * KP + s8 + tg];
                al[mt][2] = Al[(rb + grp) * KP + s8 + tg + 4];
                al[mt][3] = Al[(rb + grp + 8) * KP + s8 + tg + 4];
            }
            #pragma unroll
            for (int nt = 0; nt < 4; nt++) {
                int cb = warpN * 32 + nt * 8;
                uint32_t bh2[2], bl2[2];
                bh2[0] = Bh[(cb + grp) * KP + s8 + tg];
                bh2[1] = Bh[(cb + grp) * KP + s8 + tg + 4];
                bl2[0] = Bl[(cb + grp) * KP + s8 + tg];
                bl2[1] = Bl[(cb + grp) * KP + s8 + tg + 4];
                #pragma unroll
                for (int mt = 0; mt < 4; mt++) {
                    mma_bf16(acc[mt][nt], ah[mt], bh2);
                    mma_bf16(acc[mt][nt], al[mt], bh2);
                    mma_bf16(acc[mt][nt], ah[mt], bl2);
                }
            }
        }
    }

    #pragma unroll
    for (int mt = 0; mt < 4; mt++) {
        int rowA = m0 + warpM * 64 + mt * 16 + grp;
        #pragma unroll
        for (int nt = 0; nt < 4; nt++) {
            int c = n0 + warpN * 32 + nt * 8 + 2 * tg;
            *(float2*)&out[(size_t)rowA * C + c] =
                make_float2(acc[mt][nt][0], acc[mt][nt][1]);
            *(float2*)&out[(size_t)(rowA + 8) * C + c] =
                make_float2(acc[mt][nt][2], acc[mt][nt][3]);
        }
    }
}

// ---------------------------------------------------------------------------
// Causal flash attention: full bf16 3-term (S and PV), no shuffles.
// K smem [32 keys][36w] (packed along hd); V smem [64 hd][20w] (packed
// along key, from transposed V). K loader: 32 rows x 32 words (FIXED
// sizing, the round-11 lesson). V loader: 64 rows x 16 words.
// Stage: Kh@0 (1152w), Kl@1152, Vh@2304 (1280w), Vl@3584; total 4864w.
// ---------------------------------------------------------------------------
#define QB 64
#define KB 32
#define KSW 36
#define VSW 20
#define AST_KL 1152
#define AST_VH 2304
#define AST_VL 3584
#define ASTAGE 4864

__global__ void __launch_bounds__(128, 2) attn_kernel() {
    extern __shared__ uint32_t sm[];

    const int tid  = threadIdx.x;
    const int lane = tid & 31;
    const int warp = tid >> 5;
    const int grp  = lane >> 2;
    const int tg   = lane & 3;
    const int bh   = blockIdx.y;
    const int b    = bh >> 4, h = bh & 15;
    const int qx   = gridDim.x - 1 - (int)blockIdx.x;   // heavy blocks first
    const int q0   = qx * QB;
    const int r0   = q0 + warp * 16;
    const uint32_t sb = (uint32_t)__cvta_generic_to_shared(sm);
    const size_t vbase = ((size_t)(b * H + h)) * HD * T2;   // word base

    // Q fragments: packed bf16x2 along hd, 4 k16 steps
    uint32_t qfh[4][4], qfl[4][4];
    {
        const uint32_t* QHa = g_qh + ((size_t)(b * T + r0)) * C2 + h * 32;
        const uint32_t* QLa = g_ql + ((size_t)(b * T + r0)) * C2 + h * 32;
        #pragma unroll
        for (int ks = 0; ks < 4; ks++) {
            qfh[ks][0] = QHa[(size_t)grp * C2 + ks * 8 + tg];
            qfh[ks][1] = QHa[(size_t)(grp + 8) * C2 + ks * 8 + tg];
            qfh[ks][2] = QHa[(size_t)grp * C2 + ks * 8 + tg + 4];
            qfh[ks][3] = QHa[(size_t)(grp + 8) * C2 + ks * 8 + tg + 4];
            qfl[ks][0] = QLa[(size_t)grp * C2 + ks * 8 + tg];
            qfl[ks][1] = QLa[(size_t)(grp + 8) * C2 + ks * 8 + tg];
            qfl[ks][2] = QLa[(size_t)grp * C2 + ks * 8 + tg + 4];
            qfl[ks][3] = QLa[(size_t)(grp + 8) * C2 + ks * 8 + tg + 4];
        }
    }

    float out[8][4];
    #pragma unroll
    for (int i = 0; i < 8; i++)
        #pragma unroll
        for (int j = 0; j < 4; j++) out[i][j] = 0.f;
    float m0v = -1e30f, m1v = -1e30f, l0 = 0.f, l1 = 0.f;

    const int nIter = 2 * (qx + 1);

    // K: 32 rows x 32 words -> 2 x (128 thr x 16B)   [full coverage]
    // V: 64 rows x 16 words -> 2 x (128 thr x 16B)   [full coverage]
    #define ATT_ISSUE(stg, k0) do {                                           \
        uint32_t base_ = sb + (stg) * (ASTAGE * 4);                           \
        _Pragma("unroll")                                                     \
        for (int i_ = 0; i_ < 2; i_++) {                                      \
            int idk_ = tid + i_ * 128;                                        \
            int krow_ = idk_ >> 3, kwq_ = (idk_ & 7) << 2;                    \
            size_t koff_ = ((size_t)(b * T + (k0) + krow_)) * C2 + h * 32 + kwq_; \
            cp16(base_ + (krow_ * KSW + kwq_) * 4, &g_kh[koff_]);             \
            cp16(base_ + (AST_KL + krow_ * KSW + kwq_) * 4, &g_kl[koff_]);    \
            int hd_ = idk_ >> 2, vwq_ = (idk_ & 3) << 2;                      \
            size_t voff_ = vbase + (size_t)hd_ * T2 + ((k0) >> 1) + vwq_;     \
            cp16(base_ + (AST_VH + hd_ * VSW + vwq_) * 4, &g_vth[voff_]);     \
            cp16(base_ + (AST_VL + hd_ * VSW + vwq_) * 4, &g_vtl[voff_]);     \
        }                                                                     \
        CP_COMMIT();                                                          \
    } while (0)

    ATT_ISSUE(0, 0);

    for (int t = 0; t < nIter; t++) {
        const int k0 = t * KB;
        CP_WAIT0();
        __syncthreads();
        if (t + 1 < nIter) ATT_ISSUE((t + 1) & 1, (t + 1) * KB);

        if (k0 > r0 + 15) continue;

        const uint32_t* Ksh = sm + (t & 1) * ASTAGE;
        const uint32_t* Ksl = Ksh + AST_KL;
        const uint32_t* Vsh = Ksh + AST_VH;
        const uint32_t* Vsl = Ksh + AST_VL;

        // ---- S = Q K^T, bf16 3-term ----
        float s[4][4];
        #pragma unroll
        for (int nt = 0; nt < 4; nt++)
            #pragma unroll
            for (int j = 0; j < 4; j++) s[nt][j] = 0.f;

        #pragma unroll
        for (int nt = 0; nt < 4; nt++) {
            #pragma unroll
            for (int ks = 0; ks < 4; ks++) {
                uint32_t bh2[2], bl2[2];
                bh2[0] = Ksh[(nt * 8 + grp) * KSW + ks * 8 + tg];
                bh2[1] = Ksh[(nt * 8 + grp) * KSW + ks * 8 + tg + 4];
                bl2[0] = Ksl[(nt * 8 + grp) * KSW + ks * 8 + tg];
                bl2[1] = Ksl[(nt * 8 + grp) * KSW + ks * 8 + tg + 4];
                mma_bf16(s[nt], qfh[ks], bh2);
                mma_bf16(s[nt], qfl[ks], bh2);
                mma_bf16(s[nt], qfh[ks], bl2);
            }
        }

        // ---- scale + causal mask ----
        const int row0 = r0 + grp, row1 = r0 + grp + 8;
        if (k0 + KB - 1 <= r0) {
            #pragma unroll
            for (int nt = 0; nt < 4; nt++)
                #pragma unroll
                for (int j = 0; j < 4; j++) s[nt][j] *= 0.125f;
        } else {
            #pragma unroll
            for (int nt = 0; nt < 4; nt++) {
                int col = k0 + nt * 8 + 2 * tg;
                s[nt][0] = (col     <= row0) ? s[nt][0] * 0.125f : -1e30f;
                s[nt][1] = (col + 1 <= row0) ? s[nt][1] * 0.125f : -1e30f;
                s[nt][2] = (col     <= row1) ? s[nt][2] * 0.125f : -1e30f;
                s[nt][3] = (col + 1 <= row1) ? s[nt][3] * 0.125f : -1e30f;
            }
        }

        // ---- online softmax ----
        float mx0 = s[0][0], mx1 = s[0][2];
        #pragma unroll
        for (int nt = 0; nt < 4; nt++) {
            mx0 = fmaxf(mx0, fmaxf(s[nt][0], s[nt][1]));
            mx1 = fmaxf(mx1, fmaxf(s[nt][2], s[nt][3]));
        }
        mx0 = fmaxf(mx0, __shfl_xor_sync(0xffffffffu, mx0, 1));
        mx0 = fmaxf(mx0, __shfl_xor_sync(0xffffffffu, mx0, 2));
        mx1 = fmaxf(mx1, __shfl_xor_sync(0xffffffffu, mx1, 1));
        mx1 = fmaxf(mx1, __shfl_xor_sync(0xffffffffu, mx1, 2));
        float nm0 = fmaxf(m0v, mx0), nm1 = fmaxf(m1v, mx1);
        float c0 = __expf(m0v - nm0), c1 = __expf(m1v - nm1);

        float sum0 = 0.f, sum1 = 0.f;
        #pragma unroll
        for (int nt = 0; nt < 4; nt++) {
            s[nt][0] = __expf(s[nt][0] - nm0);
            s[nt][1] = __expf(s[nt][1] - nm0);
            s[nt][2] = __expf(s[nt][2] - nm1);
            s[nt][3] = __expf(s[nt][3] - nm1);
            sum0 += s[nt][0] + s[nt][1];
            sum1 += s[nt][2] + s[nt][3];
        }
        sum0 += __shfl_xor_sync(0xffffffffu, sum0, 1);
        sum0 += __shfl_xor_sync(0xffffffffu, sum0, 2);
        sum1 += __shfl_xor_sync(0xffffffffu, sum1, 1);
        sum1 += __shfl_xor_sync(0xffffffffu, sum1, 2);
        l0 = l0 * c0 + sum0;
        l1 = l1 * c1 + sum1;
        m0v = nm0; m1v = nm1;

        #pragma unroll
        for (int i = 0; i < 8; i++) {
            out[i][0] *= c0; out[i][1] *= c0;
            out[i][2] *= c1; out[i][3] *= c1;
        }

        // ---- PV: bf16 3-term, P C-fragments pack directly into A ----
        #pragma unroll
        for (int ks = 0; ks < 2; ks++) {     // key k16 steps
            uint32_t ph[4], pl[4];
            splitpair(s[2 * ks][0],     s[2 * ks][1],     ph[0], pl[0]);
            splitpair(s[2 * ks][2],     s[2 * ks][3],     ph[1], pl[1]);
            splitpair(s[2 * ks + 1][0], s[2 * ks + 1][1], ph[2], pl[2]);
            splitpair(s[2 * ks + 1][2], s[2 * ks + 1][3], ph[3], pl[3]);
            #pragma unroll
            for (int ntv = 0; ntv < 8; ntv++) {
                uint32_t bh2[2], bl2[2];
                bh2[0] = Vsh[(ntv * 8 + grp) * VSW + ks * 8 + tg];
                bh2[1] = Vsh[(ntv * 8 + grp) * VSW + ks * 8 + tg + 4];
                bl2[0] = Vsl[(ntv * 8 + grp) * VSW + ks * 8 + tg];
                bl2[1] = Vsl[(ntv * 8 + grp) * VSW + ks * 8 + tg + 4];
                mma_bf16(out[ntv], ph, bh2);
                mma_bf16(out[ntv], pl, bh2);
                mma_bf16(out[ntv], ph, bl2);
            }
        }
    }

    // normalize + bf16 splitpair + packed store
    float inv0 = 1.f / l0, inv1 = 1.f / l1;
    size_t rA = ((size_t)(b * T + r0 + grp)) * C2 + h * 32;
    size_t rB = ((size_t)(b * T + r0 + grp + 8)) * C2 + h * 32;
    #pragma unroll
    for (int ntv = 0; ntv < 8; ntv++) {
        int cw = ntv * 4 + tg;
        uint32_t hw, lw;
        splitpair(out[ntv][0] * inv0, out[ntv][1] * inv0, hw, lw);
        g_ah[rA + cw] = hw;
        g_al[rA + cw] = lw;
        splitpair(out[ntv][2] * inv1, out[ntv][3] * inv1, hw, lw);
        g_ah[rB + cw] = hw;
        g_al[rB + cw] = lw;
    }
}

// ---------------------------------------------------------------------------
extern "C" void kernel_launch(void* const* d_in, const int* in_sizes, int n_in,
                              void* d_out, int out_size) {
    const float* x    = (const float*)d_in[0];
    const float* Wq   = (const float*)d_in[1];
    const float* Wk   = (const float*)d_in[2];
    const float* Wv   = (const float*)d_in[3];
    const float* Wo   = (const float*)d_in[4];
    const float* cosp = (const float*)d_in[5];
    const float* sinp = (const float*)d_in[6];
    float* out = (float*)d_out;

    static bool attr_done = false;
    if (!attr_done) {
        cudaFuncSetAttribute(qkv_gemm,
            cudaFuncAttributeMaxDynamicSharedMemorySize, 2 * GSTAGE * 4);
        cudaFuncSetAttribute(wo_gemm,
            cudaFuncAttributeMaxDynamicSharedMemorySize, 2 * GSTAGE * 4);
        cudaFuncSetAttribute(attn_kernel,
            cudaFuncAttributeMaxDynamicSharedMemorySize, 2 * ASTAGE * 4);
        attr_done = true;
    }

    void *xh, *xl, *wqh, *wql, *wkh, *wkl, *wvh, *wvl, *woh, *wol;
    cudaGetSymbolAddress(&xh,  g_xh);
    cudaGetSymbolAddress(&xl,  g_xl);
    cudaGetSymbolAddress(&wqh, g_wqh);
    cudaGetSymbolAddress(&wql, g_wql);
    cudaGetSymbolAddress(&wkh, g_wkh);
    cudaGetSymbolAddress(&wkl, g_wkl);
    cudaGetSymbolAddress(&wvh, g_wvh);
    cudaGetSymbolAddress(&wvl, g_wvl);
    cudaGetSymbolAddress(&woh, g_woh);
    cudaGetSymbolAddress(&wol, g_wol);

    int nx4 = M_TOT * C / 4;
    int nw4 = C * C / 4;
    split_kernel<<<nx4 / 256, 256>>>((const float4*)x,  (uint2*)xh,  (uint2*)xl,  nx4);
    split_kernel<<<nw4 / 256, 256>>>((const float4*)Wq, (uint2*)wqh, (uint2*)wql, nw4);
    split_kernel<<<nw4 / 256, 256>>>((const float4*)Wk, (uint2*)wkh, (uint2*)wkl, nw4);
    split_kernel<<<nw4 / 256, 256>>>((const float4*)Wv, (uint2*)wvh, (uint2*)wvl, nw4);
    split_kernel<<<nw4 / 256, 256>>>((const float4*)Wo, (uint2*)woh, (uint2*)wol, nw4);

    qkv_gemm<<<dim3(24, M_TOT / BM), 256, 2 * GSTAGE * 4>>>(cosp, sinp);

    attn_kernel<<<dim3(T / QB, B * H), 128, 2 * ASTAGE * 4>>>();

    wo_gemm<<<dim3(C / BN, M_TOT / BM), 256, 2 * GSTAGE * 4>>>(out);
}

// round 13
// speedup vs baseline: 5.7859x; 1.0452x over previous
#include <cuda_runtime.h>
#include <cuda_bf16.h>
#include <math.h>
#include <stdint.h>

#define B 2
#define T 2048
#define C 1024
#define H 16
#define HD 64
#define M_TOT (B*T)   // 4096
#define C2 (C/2)      // packed bf16x2 words per row
#define T2 (T/2)

// ---------------- packed bf16x2 split inputs -------------------------------
__device__ __align__(16) uint32_t g_xh[M_TOT*C2], g_xl[M_TOT*C2];
__device__ __align__(16) uint32_t g_wqh[C*C2], g_wql[C*C2];
__device__ __align__(16) uint32_t g_wkh[C*C2], g_wkl[C*C2];
__device__ __align__(16) uint32_t g_wvh[C*C2], g_wvl[C*C2];
__device__ __align__(16) uint32_t g_woh[C*C2], g_wol[C*C2];
// ---------------- Q/K packed bf16x2; V transposed [b,h,hd,t] packed --------
__device__ __align__(16) uint32_t g_qh[M_TOT*C2], g_ql[M_TOT*C2];
__device__ __align__(16) uint32_t g_kh[M_TOT*C2], g_kl[M_TOT*C2];
__device__ __align__(16) uint32_t g_vth[B*H*HD*T2], g_vtl[B*H*HD*T2];
// ---------------- packed bf16x2 attention output ---------------------------
__device__ __align__(16) uint32_t g_ah[M_TOT*C2], g_al[M_TOT*C2];

// ---------------------------------------------------------------------------
// helpers
// ---------------------------------------------------------------------------
__device__ __forceinline__ void mma_bf16(float* d, const uint32_t* a,
                                         const uint32_t* b) {
    asm volatile(
        "mma.sync.aligned.m16n8k16.row.col.f32.bf16.bf16.f32 "
        "{%0,%1,%2,%3}, {%4,%5,%6,%7}, {%8,%9}, {%0,%1,%2,%3};"
        : "+f"(d[0]), "+f"(d[1]), "+f"(d[2]), "+f"(d[3])
        : "r"(a[0]), "r"(a[1]), "r"(a[2]), "r"(a[3]), "r"(b[0]), "r"(b[1]));
}
__device__ __forceinline__ uint32_t packbf2(float x, float y) {
    __nv_bfloat162 t = __floats2bfloat162_rn(x, y);
    return *reinterpret_cast<uint32_t*>(&t);
}
__device__ __forceinline__ void splitpair(float x, float y,
                                          uint32_t& hw, uint32_t& lw) {
    __nv_bfloat16 hx = __float2bfloat16(x);
    __nv_bfloat16 hy = __float2bfloat16(y);
    float rx = x - __bfloat162float(hx);
    float ry = y - __bfloat162float(hy);
    __nv_bfloat162 hp = {hx, hy};
    hw = *reinterpret_cast<uint32_t*>(&hp);
    lw = packbf2(rx, ry);
}
__device__ __forceinline__ void split1(float v, __nv_bfloat16& h,
                                       __nv_bfloat16& l) {
    h = __float2bfloat16(v);
    l = __float2bfloat16(v - __bfloat162float(h));
}
__device__ __forceinline__ void cp16(uint32_t saddr, const void* gptr) {
    asm volatile("cp.async.cg.shared.global [%0], [%1], 16;\n"
                 :: "r"(saddr), "l"(gptr));
}
#define CP_COMMIT() asm volatile("cp.async.commit_group;\n" ::)
#define CP_WAIT0()  asm volatile("cp.async.wait_group 0;\n" ::)

// ---------------------------------------------------------------------------
// fused split kernel: 5 tensors in one launch (grid.y selects tensor)
// ---------------------------------------------------------------------------
__global__ void split5_kernel(const float4* __restrict__ sx,
                              const float4* __restrict__ sq,
                              const float4* __restrict__ sk,
                              const float4* __restrict__ sv,
                              const float4* __restrict__ so,
                              int nx4, int nw4) {
    const float4* s;
    uint2 *dh, *dl;
    int n4;
    switch (blockIdx.y) {
        case 0:  s = sx; dh = (uint2*)g_xh;  dl = (uint2*)g_xl;  n4 = nx4; break;
        case 1:  s = sq; dh = (uint2*)g_wqh; dl = (uint2*)g_wql; n4 = nw4; break;
        case 2:  s = sk; dh = (uint2*)g_wkh; dl = (uint2*)g_wkl; n4 = nw4; break;
        case 3:  s = sv; dh = (uint2*)g_wvh; dl = (uint2*)g_wvl; n4 = nw4; break;
        default: s = so; dh = (uint2*)g_woh; dl = (uint2*)g_wol; n4 = nw4; break;
    }
    int i = blockIdx.x * blockDim.x + threadIdx.x;
    if (i >= n4) return;
    float4 v = s[i];
    uint2 h, l;
    splitpair(v.x, v.y, h.x, l.x);
    splitpair(v.z, v.w, h.y, l.y);
    dh[i] = h;
    dl[i] = l;
}

// ---------------------------------------------------------------------------
// Fused QKV GEMM, bf16 3-term split core, cp.async double-buffered.
// Epilogue: Q/K -> RoPE + packed bf16x2; V -> transposed bf16 hi/lo scatter.
// ---------------------------------------------------------------------------
#define BM 128
#define BN 128
#define KW 16
#define KP 20
#define GSTAGE 10240
#define NKIT (C2/KW)

__global__ void __launch_bounds__(256, 2) qkv_gemm(const float* __restrict__ cosp,
                                                   const float* __restrict__ sinp) {
    extern __shared__ uint32_t sm[];
    const int tid = threadIdx.x, lane = tid & 31, warp = tid >> 5;
    const int warpM = warp >> 2, warpN = warp & 3;
    const int grp = lane >> 2, tg = lane & 3;
    const int m0 = blockIdx.y * BM;
    const int nsel = blockIdx.x >> 3;
    const int n0c = (blockIdx.x & 7) * BN;

    const uint32_t* WH = (nsel == 0) ? g_wqh : (nsel == 1) ? g_wkh : g_wvh;
    const uint32_t* WL = (nsel == 0) ? g_wql : (nsel == 1) ? g_wkl : g_wvl;

    const int lrow = tid >> 2;
    const int lwq  = (tid & 3) << 2;
    const uint32_t sb = (uint32_t)__cvta_generic_to_shared(sm);

    float acc[4][4][4];
    #pragma unroll
    for (int mt = 0; mt < 4; mt++)
        #pragma unroll
        for (int nt = 0; nt < 4; nt++)
            #pragma unroll
            for (int i = 0; i < 4; i++) acc[mt][nt][i] = 0.f;

    #define QKV_ISSUE(stg, k0w) do {                                          \
        uint32_t base_ = sb + (stg) * (GSTAGE * 4);                           \
        size_t rA0_ = (size_t)(m0 + lrow) * C2 + (k0w) + lwq;                 \
        size_t rA1_ = (size_t)(m0 + lrow + 64) * C2 + (k0w) + lwq;            \
        size_t rB0_ = (size_t)(n0c + lrow) * C2 + (k0w) + lwq;                \
        size_t rB1_ = (size_t)(n0c + lrow + 64) * C2 + (k0w) + lwq;           \
        uint32_t dA0_ = base_ + (lrow * KP + lwq) * 4;                        \
        uint32_t dA1_ = base_ + ((lrow + 64) * KP + lwq) * 4;                 \
        cp16(dA0_, &g_xh[rA0_]);  cp16(dA1_, &g_xh[rA1_]);                    \
        cp16(dA0_ + 2560 * 4, &g_xl[rA0_]);                                   \
        cp16(dA1_ + 2560 * 4, &g_xl[rA1_]);                                   \
        uint32_t dB0_ = base_ + (5120 + lrow * KP + lwq) * 4;                 \
        uint32_t dB1_ = base_ + (5120 + (lrow + 64) * KP + lwq) * 4;          \
        cp16(dB0_, &WH[rB0_]);  cp16(dB1_, &WH[rB1_]);                        \
        cp16(dB0_ + 2560 * 4, &WL[rB0_]);                                     \
        cp16(dB1_ + 2560 * 4, &WL[rB1_]);                                     \
        CP_COMMIT();                                                          \
    } while (0)

    QKV_ISSUE(0, 0);

    for (int it = 0; it < NKIT; it++) {
        CP_WAIT0();
        __syncthreads();
        if (it + 1 < NKIT) QKV_ISSUE((it + 1) & 1, (it + 1) * KW);

        const uint32_t* Ah = sm + (it & 1) * GSTAGE;
        const uint32_t* Al = Ah + 2560;
        const uint32_t* Bh = Ah + 5120;
        const uint32_t* Bl = Ah + 7680;

        #pragma unroll
        for (int s8 = 0; s8 < KW; s8 += 8) {
            uint32_t ah[4][4], al[4][4];
            #pragma unroll
            for (int mt = 0; mt < 4; mt++) {
                int rb = warpM * 64 + mt * 16;
                ah[mt][0] = Ah[(rb + grp) * KP + s8 + tg];
                ah[mt][1] = Ah[(rb + grp + 8) * KP + s8 + tg];
                ah[mt][2] = Ah[(rb + grp) * KP + s8 + tg + 4];
                ah[mt][3] = Ah[(rb + grp + 8) * KP + s8 + tg + 4];
                al[mt][0] = Al[(rb + grp) * KP + s8 + tg];
                al[mt][1] = Al[(rb + grp + 8) * KP + s8 + tg];
                al[mt][2] = Al[(rb + grp) * KP + s8 + tg + 4];
                al[mt][3] = Al[(rb + grp + 8) * KP + s8 + tg + 4];
            }
            #pragma unroll
            for (int nt = 0; nt < 4; nt++) {
                int cb = warpN * 32 + nt * 8;
                uint32_t bh2[2], bl2[2];
                bh2[0] = Bh[(cb + grp) * KP + s8 + tg];
                bh2[1] = Bh[(cb + grp) * KP + s8 + tg + 4];
                bl2[0] = Bl[(cb + grp) * KP + s8 + tg];
                bl2[1] = Bl[(cb + grp) * KP + s8 + tg + 4];
                #pragma unroll
                for (int mt = 0; mt < 4; mt++) {
                    mma_bf16(acc[mt][nt], ah[mt], bh2);
                    mma_bf16(acc[mt][nt], al[mt], bh2);
                    mma_bf16(acc[mt][nt], ah[mt], bl2);
                }
            }
        }
    }

    // epilogue
    uint32_t* QKH = (nsel == 0) ? g_qh : g_kh;
    uint32_t* QKL = (nsel == 0) ? g_ql : g_kl;
    __nv_bfloat16* VTH = (__nv_bfloat16*)g_vth;
    __nv_bfloat16* VTL = (__nv_bfloat16*)g_vtl;
    #pragma unroll
    for (int mt = 0; mt < 4; mt++) {
        int rowA = m0 + warpM * 64 + mt * 16 + grp;
        int rowB = rowA + 8;
        #pragma unroll
        for (int nt = 0; nt < 4; nt++) {
            int c = n0c + warpN * 32 + nt * 8 + 2 * tg;
            float a0 = acc[mt][nt][0], a1 = acc[mt][nt][1];
            float a2 = acc[mt][nt][2], a3 = acc[mt][nt][3];
            if (nsel < 2) {
                int d = (c & 63) >> 1;
                int t0 = rowA & (T - 1), t1 = rowB & (T - 1);
                float c0 = cosp[t0 * 32 + d], s0 = sinp[t0 * 32 + d];
                float c1 = cosp[t1 * 32 + d], s1 = sinp[t1 * 32 + d];
                float o0 = a0 * c0 - a1 * s0, o1 = a0 * s0 + a1 * c0;
                float o2 = a2 * c1 - a3 * s1, o3 = a2 * s1 + a3 * c1;
                uint32_t hw, lw;
                splitpair(o0, o1, hw, lw);
                QKH[(size_t)rowA * C2 + (c >> 1)] = hw;
                QKL[(size_t)rowA * C2 + (c >> 1)] = lw;
                splitpair(o2, o3, hw, lw);
                QKH[(size_t)rowB * C2 + (c >> 1)] = hw;
                QKL[(size_t)rowB * C2 + (c >> 1)] = lw;
            } else {
                int bb = rowA >> 11;
                int hh = c >> 6, hd = c & 63;
                size_t base = ((size_t)(bb * H + hh) * HD + hd) * T;
                int tA = rowA & (T - 1), tB = rowB & (T - 1);
                float vals[4] = {a0, a1, a2, a3};
                size_t idxs[4] = {base + tA, base + T + tA,
                                  base + tB, base + T + tB};
                #pragma unroll
                for (int j = 0; j < 4; j++) {
                    __nv_bfloat16 hv, lv;
                    split1(vals[j], hv, lv);
                    VTH[idxs[j]] = hv;
                    VTL[idxs[j]] = lv;
                }
            }
        }
    }
}

// ---------------------------------------------------------------------------
// Output GEMM: out = att @ Wo^T (unchanged, validated)
// ---------------------------------------------------------------------------
__global__ void __launch_bounds__(256, 2) wo_gemm(float* __restrict__ out) {
    extern __shared__ uint32_t sm[];
    const int tid = threadIdx.x, lane = tid & 31, warp = tid >> 5;
    const int warpM = warp >> 2, warpN = warp & 3;
    const int grp = lane >> 2, tg = lane & 3;
    const int m0 = blockIdx.y * BM;
    const int n0 = blockIdx.x * BN;

    const int lrow = tid >> 2;
    const int lwq  = (tid & 3) << 2;
    const uint32_t sb = (uint32_t)__cvta_generic_to_shared(sm);

    float acc[4][4][4];
    #pragma unroll
    for (int mt = 0; mt < 4; mt++)
        #pragma unroll
        for (int nt = 0; nt < 4; nt++)
            #pragma unroll
            for (int i = 0; i < 4; i++) acc[mt][nt][i] = 0.f;

    #define WO_ISSUE(stg, k0w) do {                                           \
        uint32_t base_ = sb + (stg) * (GSTAGE * 4);                           \
        size_t rA0_ = (size_t)(m0 + lrow) * C2 + (k0w) + lwq;                 \
        size_t rA1_ = (size_t)(m0 + lrow + 64) * C2 + (k0w) + lwq;            \
        size_t rB0_ = (size_t)(n0 + lrow) * C2 + (k0w) + lwq;                 \
        size_t rB1_ = (size_t)(n0 + lrow + 64) * C2 + (k0w) + lwq;            \
        uint32_t dA0_ = base_ + (lrow * KP + lwq) * 4;                        \
        uint32_t dA1_ = base_ + ((lrow + 64) * KP + lwq) * 4;                 \
        cp16(dA0_, &g_ah[rA0_]);  cp16(dA1_, &g_ah[rA1_]);                    \
        cp16(dA0_ + 2560 * 4, &g_al[rA0_]);                                   \
        cp16(dA1_ + 2560 * 4, &g_al[rA1_]);                                   \
        uint32_t dB0_ = base_ + (5120 + lrow * KP + lwq) * 4;                 \
        uint32_t dB1_ = base_ + (5120 + (lrow + 64) * KP + lwq) * 4;          \
        cp16(dB0_, &g_woh[rB0_]);  cp16(dB1_, &g_woh[rB1_]);                  \
        cp16(dB0_ + 2560 * 4, &g_wol[rB0_]);                                  \
        cp16(dB1_ + 2560 * 4, &g_wol[rB1_]);                                  \
        CP_COMMIT();                                                          \
    } while (0)

    WO_ISSUE(0, 0);

    for (int it = 0; it < NKIT; it++) {
        CP_WAIT0();
        __syncthreads();
        if (it + 1 < NKIT) WO_ISSUE((it + 1) & 1, (it + 1) * KW);

        const uint32_t* Ah = sm + (it & 1) * GSTAGE;
        const uint32_t* Al = Ah + 2560;
        const uint32_t* Bh = Ah + 5120;
        const uint32_t* Bl = Ah + 7680;

        #pragma unroll
        for (int s8 = 0; s8 < KW; s8 += 8) {
            uint32_t ah[4][4], al[4][4];
            #pragma unroll
            for (int mt = 0; mt < 4; mt++) {
                int rb = warpM * 64 + mt * 16;
                ah[mt][0] = Ah[(rb + grp) * KP + s8 + tg];
                ah[mt][1] = Ah[(rb + grp + 8) * KP + s8 + tg];
                ah[mt][2] = Ah[(rb + grp) * KP + s8 + tg + 4];
                ah[mt][3] = Ah[(rb + grp + 8) * KP + s8 + tg + 4];
                al[mt][0] = Al[(rb + grp) * KP + s8 + tg];
                al[mt][1] = Al[(rb + grp + 8) * KP + s8 + tg];
                al[mt][2] = Al[(rb + grp) * KP + s8 + tg + 4];
                al[mt][3] = Al[(rb + grp + 8) * KP + s8 + tg + 4];
            }
            #pragma unroll
            for (int nt = 0; nt < 4; nt++) {
                int cb = warpN * 32 + nt * 8;
                uint32_t bh2[2], bl2[2];
                bh2[0] = Bh[(cb + grp) * KP + s8 + tg];
                bh2[1] = Bh[(cb + grp) * KP + s8 + tg + 4];
                bl2[0] = Bl[(cb + grp) * KP + s8 + tg];
                bl2[1] = Bl[(cb + grp) * KP + s8 + tg + 4];
                #pragma unroll
                for (int mt = 0; mt < 4; mt++) {
                    mma_bf16(acc[mt][nt], ah[mt], bh2);
                    mma_bf16(acc[mt][nt], al[mt], bh2);
                    mma_bf16(acc[mt][nt], ah[mt], bl2);
                }
            }
        }
    }

    #pragma unroll
    for (int mt = 0; mt < 4; mt++) {
        int rowA = m0 + warpM * 64 + mt * 16 + grp;
        #pragma unroll
        for (int nt = 0; nt < 4; nt++) {
            int c = n0 + warpN * 32 + nt * 8 + 2 * tg;
            *(float2*)&out[(size_t)rowA * C + c] =
                make_float2(acc[mt][nt][0], acc[mt][nt][1]);
            *(float2*)&out[(size_t)(rowA + 8) * C + c] =
                make_float2(acc[mt][nt][2], acc[mt][nt][3]);
        }
    }
}

// ---------------------------------------------------------------------------
// Causal flash attention: full bf16 3-term, KB=64 key tiles (softmax,
// rescale, syncs and load-issue amortized over 2x keys).
// K smem [64 keys][36w]; V smem [64 hd][36w] (32 data words + pad).
// Loaders: 64 rows x 32 words = 4 x (128 thr x 16B) each — full coverage.
// Stage: Kh@0, Kl@2304, Vh@4608, Vl@6912; total 9216 words (36.9 KB).
// ---------------------------------------------------------------------------
#define QB 64
#define KB 64
#define KSW 36
#define VSW 36
#define AST_KL 2304
#define AST_VH 4608
#define AST_VL 6912
#define ASTAGE 9216

__global__ void __launch_bounds__(128, 2) attn_kernel() {
    extern __shared__ uint32_t sm[];

    const int tid  = threadIdx.x;
    const int lane = tid & 31;
    const int warp = tid >> 5;
    const int grp  = lane >> 2;
    const int tg   = lane & 3;
    const int bh   = blockIdx.y;
    const int b    = bh >> 4, h = bh & 15;
    const int qx   = gridDim.x - 1 - (int)blockIdx.x;   // heavy blocks first
    const int q0   = qx * QB;
    const int r0   = q0 + warp * 16;
    const uint32_t sb = (uint32_t)__cvta_generic_to_shared(sm);
    const size_t vbase = ((size_t)(b * H + h)) * HD * T2;   // word base

    // Q fragments: packed bf16x2 along hd, 4 k16 steps
    uint32_t qfh[4][4], qfl[4][4];
    {
        const uint32_t* QHa = g_qh + ((size_t)(b * T + r0)) * C2 + h * 32;
        const uint32_t* QLa = g_ql + ((size_t)(b * T + r0)) * C2 + h * 32;
        #pragma unroll
        for (int ks = 0; ks < 4; ks++) {
            qfh[ks][0] = QHa[(size_t)grp * C2 + ks * 8 + tg];
            qfh[ks][1] = QHa[(size_t)(grp + 8) * C2 + ks * 8 + tg];
            qfh[ks][2] = QHa[(size_t)grp * C2 + ks * 8 + tg + 4];
            qfh[ks][3] = QHa[(size_t)(grp + 8) * C2 + ks * 8 + tg + 4];
            qfl[ks][0] = QLa[(size_t)grp * C2 + ks * 8 + tg];
            qfl[ks][1] = QLa[(size_t)(grp + 8) * C2 + ks * 8 + tg];
            qfl[ks][2] = QLa[(size_t)grp * C2 + ks * 8 + tg + 4];
            qfl[ks][3] = QLa[(size_t)(grp + 8) * C2 + ks * 8 + tg + 4];
        }
    }

    float out[8][4];
    #pragma unroll
    for (int i = 0; i < 8; i++)
        #pragma unroll
        for (int j = 0; j < 4; j++) out[i][j] = 0.f;
    float m0v = -1e30f, m1v = -1e30f, l0 = 0.f, l1 = 0.f;

    const int nIter = qx + 1;   // 64-key tiles

    // K: 64 rows x 32 words; V: 64 rows x 32 words — 4 iters each.
    #define ATT_ISSUE(stg, k0) do {                                           \
        uint32_t base_ = sb + (stg) * (ASTAGE * 4);                           \
        _Pragma("unroll")                                                     \
        for (int i_ = 0; i_ < 4; i_++) {                                      \
            int idk_ = tid + i_ * 128;                                        \
            int krow_ = idk_ >> 3, kwq_ = (idk_ & 7) << 2;                    \
            size_t koff_ = ((size_t)(b * T + (k0) + krow_)) * C2 + h * 32 + kwq_; \
            cp16(base_ + (krow_ * KSW + kwq_) * 4, &g_kh[koff_]);             \
            cp16(base_ + (AST_KL + krow_ * KSW + kwq_) * 4, &g_kl[koff_]);    \
            size_t voff_ = vbase + (size_t)krow_ * T2 + ((k0) >> 1) + kwq_;   \
            cp16(base_ + (AST_VH + krow_ * VSW + kwq_) * 4, &g_vth[voff_]);   \
            cp16(base_ + (AST_VL + krow_ * VSW + kwq_) * 4, &g_vtl[voff_]);   \
        }                                                                     \
        CP_COMMIT();                                                          \
    } while (0)

    ATT_ISSUE(0, 0);

    for (int t = 0; t < nIter; t++) {
        const int k0 = t * KB;
        CP_WAIT0();
        __syncthreads();
        if (t + 1 < nIter) ATT_ISSUE((t + 1) & 1, (t + 1) * KB);

        if (k0 > r0 + 15) continue;

        const uint32_t* Ksh = sm + (t & 1) * ASTAGE;
        const uint32_t* Ksl = Ksh + AST_KL;
        const uint32_t* Vsh = Ksh + AST_VH;
        const uint32_t* Vsl = Ksh + AST_VL;

        // ---- S = Q K^T (16 x 64), bf16 3-term ----
        float s[8][4];
        #pragma unroll
        for (int nt = 0; nt < 8; nt++)
            #pragma unroll
            for (int j = 0; j < 4; j++) s[nt][j] = 0.f;

        #pragma unroll
        for (int nt = 0; nt < 8; nt++) {
            #pragma unroll
            for (int ks = 0; ks < 4; ks++) {
                uint32_t bh2[2], bl2[2];
                bh2[0] = Ksh[(nt * 8 + grp) * KSW + ks * 8 + tg];
                bh2[1] = Ksh[(nt * 8 + grp) * KSW + ks * 8 + tg + 4];
                bl2[0] = Ksl[(nt * 8 + grp) * KSW + ks * 8 + tg];
                bl2[1] = Ksl[(nt * 8 + grp) * KSW + ks * 8 + tg + 4];
                mma_bf16(s[nt], qfh[ks], bh2);
                mma_bf16(s[nt], qfl[ks], bh2);
                mma_bf16(s[nt], qfh[ks], bl2);
            }
        }

        // ---- scale + causal mask ----
        const int row0 = r0 + grp, row1 = r0 + grp + 8;
        if (k0 + KB - 1 <= r0) {
            #pragma unroll
            for (int nt = 0; nt < 8; nt++)
                #pragma unroll
                for (int j = 0; j < 4; j++) s[nt][j] *= 0.125f;
        } else {
            #pragma unroll
            for (int nt = 0; nt < 8; nt++) {
                int col = k0 + nt * 8 + 2 * tg;
                s[nt][0] = (col     <= row0) ? s[nt][0] * 0.125f : -1e30f;
                s[nt][1] = (col + 1 <= row0) ? s[nt][1] * 0.125f : -1e30f;
                s[nt][2] = (col     <= row1) ? s[nt][2] * 0.125f : -1e30f;
                s[nt][3] = (col + 1 <= row1) ? s[nt][3] * 0.125f : -1e30f;
            }
        }

        // ---- online softmax (once per 64 keys) ----
        float mx0 = s[0][0], mx1 = s[0][2];
        #pragma unroll
        for (int nt = 0; nt < 8; nt++) {
            mx0 = fmaxf(mx0, fmaxf(s[nt][0], s[nt][1]));
            mx1 = fmaxf(mx1, fmaxf(s[nt][2], s[nt][3]));
        }
        mx0 = fmaxf(mx0, __shfl_xor_sync(0xffffffffu, mx0, 1));
        mx0 = fmaxf(mx0, __shfl_xor_sync(0xffffffffu, mx0, 2));
        mx1 = fmaxf(mx1, __shfl_xor_sync(0xffffffffu, mx1, 1));
        mx1 = fmaxf(mx1, __shfl_xor_sync(0xffffffffu, mx1, 2));
        float nm0 = fmaxf(m0v, mx0), nm1 = fmaxf(m1v, mx1);
        float c0 = __expf(m0v - nm0), c1 = __expf(m1v - nm1);

        float sum0 = 0.f, sum1 = 0.f;
        #pragma unroll
        for (int nt = 0; nt < 8; nt++) {
            s[nt][0] = __expf(s[nt][0] - nm0);
            s[nt][1] = __expf(s[nt][1] - nm0);
            s[nt][2] = __expf(s[nt][2] - nm1);
            s[nt][3] = __expf(s[nt][3] - nm1);
            sum0 += s[nt][0] + s[nt][1];
            sum1 += s[nt][2] + s[nt][3];
        }
        sum0 += __shfl_xor_sync(0xffffffffu, sum0, 1);
        sum0 += __shfl_xor_sync(0xffffffffu, sum0, 2);
        sum1 += __shfl_xor_sync(0xffffffffu, sum1, 1);
        sum1 += __shfl_xor_sync(0xffffffffu, sum1, 2);
        l0 = l0 * c0 + sum0;
        l1 = l1 * c1 + sum1;
        m0v = nm0; m1v = nm1;

        #pragma unroll
        for (int i = 0; i < 8; i++) {
            out[i][0] *= c0; out[i][1] *= c0;
            out[i][2] *= c1; out[i][3] *= c1;
        }

        // ---- PV: bf16 3-term, P C-fragments pack directly into A ----
        #pragma unroll
        for (int ks = 0; ks < 4; ks++) {     // key k16 steps (64 keys)
            uint32_t ph[4], pl[4];
            splitpair(s[2 * ks][0],     s[2 * ks][1],     ph[0], pl[0]);
            splitpair(s[2 * ks][2],     s[2 * ks][3],     ph[1], pl[1]);
            splitpair(s[2 * ks + 1][0], s[2 * ks + 1][1], ph[2], pl[2]);
            splitpair(s[2 * ks + 1][2], s[2 * ks + 1][3], ph[3], pl[3]);
            #pragma unroll
            for (int ntv = 0; ntv < 8; ntv++) {
                uint32_t bh2[2], bl2[2];
                bh2[0] = Vsh[(ntv * 8 + grp) * VSW + ks * 8 + tg];
                bh2[1] = Vsh[(ntv * 8 + grp) * VSW + ks * 8 + tg + 4];
                bl2[0] = Vsl[(ntv * 8 + grp) * VSW + ks * 8 + tg];
                bl2[1] = Vsl[(ntv * 8 + grp) * VSW + ks * 8 + tg + 4];
                mma_bf16(out[ntv], ph, bh2);
                mma_bf16(out[ntv], pl, bh2);
                mma_bf16(out[ntv], ph, bl2);
            }
        }
    }

    // normalize + bf16 splitpair + packed store
    float inv0 = 1.f / l0, inv1 = 1.f / l1;
    size_t rA = ((size_t)(b * T + r0 + grp)) * C2 + h * 32;
    size_t rB = ((size_t)(b * T + r0 + grp + 8)) * C2 + h * 32;
    #pragma unroll
    for (int ntv = 0; ntv < 8; ntv++) {
        int cw = ntv * 4 + tg;
        uint32_t hw, lw;
        splitpair(out[ntv][0] * inv0, out[ntv][1] * inv0, hw, lw);
        g_ah[rA + cw] = hw;
        g_al[rA + cw] = lw;
        splitpair(out[ntv][2] * inv1, out[ntv][3] * inv1, hw, lw);
        g_ah[rB + cw] = hw;
        g_al[rB + cw] = lw;
    }
}

// ---------------------------------------------------------------------------
extern "C" void kernel_launch(void* const* d_in, const int* in_sizes, int n_in,
                              void* d_out, int out_size) {
    const float* x    = (const float*)d_in[0];
    const float* Wq   = (const float*)d_in[1];
    const float* Wk   = (const float*)d_in[2];
    const float* Wv   = (const float*)d_in[3];
    const float* Wo   = (const float*)d_in[4];
    const float* cosp = (const float*)d_in[5];
    const float* sinp = (const float*)d_in[6];
    float* out = (float*)d_out;

    static bool attr_done = false;
    if (!attr_done) {
        cudaFuncSetAttribute(qkv_gemm,
            cudaFuncAttributeMaxDynamicSharedMemorySize, 2 * GSTAGE * 4);
        cudaFuncSetAttribute(wo_gemm,
            cudaFuncAttributeMaxDynamicSharedMemorySize, 2 * GSTAGE * 4);
        cudaFuncSetAttribute(attn_kernel,
            cudaFuncAttributeMaxDynamicSharedMemorySize, 2 * ASTAGE * 4);
        attr_done = true;
    }

    int nx4 = M_TOT * C / 4;   // 1M
    int nw4 = C * C / 4;       // 256K
    split5_kernel<<<dim3(nx4 / 256, 5), 256>>>(
        (const float4*)x, (const float4*)Wq, (const float4*)Wk,
        (const float4*)Wv, (const float4*)Wo, nx4, nw4);

    qkv_gemm<<<dim3(24, M_TOT / BM), 256, 2 * GSTAGE * 4>>>(cosp, sinp);

    attn_kernel<<<dim3(T / QB, B * H), 128, 2 * ASTAGE * 4>>>();

    wo_gemm<<<dim3(C / BN, M_TOT / BM), 256, 2 * GSTAGE * 4>>>(out);
}

// round 15
// speedup vs baseline: 6.1910x; 1.0700x over previous
#include <cuda_runtime.h>
#include <cuda_bf16.h>
#include <math.h>
#include <stdint.h>

#define B 2
#define T 2048
#define C 1024
#define H 16
#define HD 64
#define M_TOT (B*T)   // 4096
#define C2 (C/2)      // packed bf16x2 words per row
#define T2 (T/2)

// ---------------- packed bf16x2 split inputs -------------------------------
__device__ __align__(16) uint32_t g_xh[M_TOT*C2], g_xl[M_TOT*C2];
__device__ __align__(16) uint32_t g_wqh[C*C2], g_wql[C*C2];
__device__ __align__(16) uint32_t g_wkh[C*C2], g_wkl[C*C2];
__device__ __align__(16) uint32_t g_wvh[C*C2], g_wvl[C*C2];
__device__ __align__(16) uint32_t g_woh[C*C2], g_wol[C*C2];
// ---------------- Q/K packed bf16x2; V transposed [b,h,hd,t] packed --------
__device__ __align__(16) uint32_t g_qh[M_TOT*C2], g_ql[M_TOT*C2];
__device__ __align__(16) uint32_t g_kh[M_TOT*C2], g_kl[M_TOT*C2];
__device__ __align__(16) uint32_t g_vth[B*H*HD*T2], g_vtl[B*H*HD*T2];
// ---------------- packed bf16x2 attention output ---------------------------
__device__ __align__(16) uint32_t g_ah[M_TOT*C2], g_al[M_TOT*C2];

// ---------------------------------------------------------------------------
// helpers
// ---------------------------------------------------------------------------
__device__ __forceinline__ void mma_bf16(float* d, const uint32_t* a,
                                         const uint32_t* b) {
    asm volatile(
        "mma.sync.aligned.m16n8k16.row.col.f32.bf16.bf16.f32 "
        "{%0,%1,%2,%3}, {%4,%5,%6,%7}, {%8,%9}, {%0,%1,%2,%3};"
        : "+f"(d[0]), "+f"(d[1]), "+f"(d[2]), "+f"(d[3])
        : "r"(a[0]), "r"(a[1]), "r"(a[2]), "r"(a[3]), "r"(b[0]), "r"(b[1]));
}
__device__ __forceinline__ void ldsm_x4(uint32_t* r, uint32_t a) {
    asm volatile(
        "ldmatrix.sync.aligned.m8n8.x4.shared.b16 {%0,%1,%2,%3}, [%4];"
        : "=r"(r[0]), "=r"(r[1]), "=r"(r[2]), "=r"(r[3]) : "r"(a));
}
__device__ __forceinline__ uint32_t packbf2(float x, float y) {
    __nv_bfloat162 t = __floats2bfloat162_rn(x, y);
    return *reinterpret_cast<uint32_t*>(&t);
}
__device__ __forceinline__ void splitpair(float x, float y,
                                          uint32_t& hw, uint32_t& lw) {
    __nv_bfloat16 hx = __float2bfloat16(x);
    __nv_bfloat16 hy = __float2bfloat16(y);
    float rx = x - __bfloat162float(hx);
    float ry = y - __bfloat162float(hy);
    __nv_bfloat162 hp = {hx, hy};
    hw = *reinterpret_cast<uint32_t*>(&hp);
    lw = packbf2(rx, ry);
}
__device__ __forceinline__ void split1(float v, __nv_bfloat16& h,
                                       __nv_bfloat16& l) {
    h = __float2bfloat16(v);
    l = __float2bfloat16(v - __bfloat162float(h));
}
__device__ __forceinline__ void cp16(uint32_t saddr, const void* gptr) {
    asm volatile("cp.async.cg.shared.global [%0], [%1], 16;\n"
                 :: "r"(saddr), "l"(gptr));
}
#define CP_COMMIT() asm volatile("cp.async.commit_group;\n" ::)
#define CP_WAIT0()  asm volatile("cp.async.wait_group 0;\n" ::)

// ---------------------------------------------------------------------------
// fused split kernel: 5 tensors in one launch (grid.y selects tensor)
// ---------------------------------------------------------------------------
__global__ void split5_kernel(const float4* __restrict__ sx,
                              const float4* __restrict__ sq,
                              const float4* __restrict__ sk,
                              const float4* __restrict__ sv,
                              const float4* __restrict__ so,
                              int nx4, int nw4) {
    const float4* s;
    uint2 *dh, *dl;
    int n4;
    switch (blockIdx.y) {
        case 0:  s = sx; dh = (uint2*)g_xh;  dl = (uint2*)g_xl;  n4 = nx4; break;
        case 1:  s = sq; dh = (uint2*)g_wqh; dl = (uint2*)g_wql; n4 = nw4; break;
        case 2:  s = sk; dh = (uint2*)g_wkh; dl = (uint2*)g_wkl; n4 = nw4; break;
        case 3:  s = sv; dh = (uint2*)g_wvh; dl = (uint2*)g_wvl; n4 = nw4; break;
        default: s = so; dh = (uint2*)g_woh; dl = (uint2*)g_wol; n4 = nw4; break;
    }
    int i = blockIdx.x * blockDim.x + threadIdx.x;
    if (i >= n4) return;
    float4 v = s[i];
    uint2 h, l;
    splitpair(v.x, v.y, h.x, l.x);
    splitpair(v.z, v.w, h.y, l.y);
    dh[i] = h;
    dl[i] = l;
}

// ---------------------------------------------------------------------------
// Fused QKV GEMM, bf16 3-term, cp.async double-buffered, LDSM fragments.
// ---------------------------------------------------------------------------
#define BM 128
#define BN 128
#define KW 16
#define KP 20
#define GSTAGE 10240
#define NKIT (C2/KW)

__global__ void __launch_bounds__(256, 2) qkv_gemm(const float* __restrict__ cosp,
                                                   const float* __restrict__ sinp) {
    extern __shared__ uint32_t sm[];
    const int tid = threadIdx.x, lane = tid & 31, warp = tid >> 5;
    const int warpM = warp >> 2, warpN = warp & 3;
    const int grp = lane >> 2, tg = lane & 3;
    const int m0 = blockIdx.y * BM;
    const int nsel = blockIdx.x >> 3;
    const int n0c = (blockIdx.x & 7) * BN;

    const uint32_t* WH = (nsel == 0) ? g_wqh : (nsel == 1) ? g_wkh : g_wvh;
    const uint32_t* WL = (nsel == 0) ? g_wql : (nsel == 1) ? g_wkl : g_wvl;

    const int lrow = tid >> 2;
    const int lwq  = (tid & 3) << 2;
    const uint32_t sb = (uint32_t)__cvta_generic_to_shared(sm);
    // ldmatrix lane addressing (words)
    const int lm = lane >> 3;
    const uint32_t aOffW = (uint32_t)((warpM * 64 + (lm & 1) * 8 + (lane & 7)) * KP
                                      + (lm >> 1) * 4);
    const uint32_t bOffW = (uint32_t)((warpN * 32 + (lm >> 1) * 8 + (lane & 7)) * KP
                                      + (lm & 1) * 4);

    float acc[4][4][4];
    #pragma unroll
    for (int mt = 0; mt < 4; mt++)
        #pragma unroll
        for (int nt = 0; nt < 4; nt++)
            #pragma unroll
            for (int i = 0; i < 4; i++) acc[mt][nt][i] = 0.f;

    #define QKV_ISSUE(stg, k0w) do {                                          \
        uint32_t base_ = sb + (stg) * (GSTAGE * 4);                           \
        size_t rA0_ = (size_t)(m0 + lrow) * C2 + (k0w) + lwq;                 \
        size_t rA1_ = (size_t)(m0 + lrow + 64) * C2 + (k0w) + lwq;            \
        size_t rB0_ = (size_t)(n0c + lrow) * C2 + (k0w) + lwq;                \
        size_t rB1_ = (size_t)(n0c + lrow + 64) * C2 + (k0w) + lwq;           \
        uint32_t dA0_ = base_ + (lrow * KP + lwq) * 4;                        \
        uint32_t dA1_ = base_ + ((lrow + 64) * KP + lwq) * 4;                 \
        cp16(dA0_, &g_xh[rA0_]);  cp16(dA1_, &g_xh[rA1_]);                    \
        cp16(dA0_ + 2560 * 4, &g_xl[rA0_]);                                   \
        cp16(dA1_ + 2560 * 4, &g_xl[rA1_]);                                   \
        uint32_t dB0_ = base_ + (5120 + lrow * KP + lwq) * 4;                 \
        uint32_t dB1_ = base_ + (5120 + (lrow + 64) * KP + lwq) * 4;          \
        cp16(dB0_, &WH[rB0_]);  cp16(dB1_, &WH[rB1_]);                        \
        cp16(dB0_ + 2560 * 4, &WL[rB0_]);                                     \
        cp16(dB1_ + 2560 * 4, &WL[rB1_]);                                     \
        CP_COMMIT();                                                          \
    } while (0)

    QKV_ISSUE(0, 0);

    for (int it = 0; it < NKIT; it++) {
        CP_WAIT0();
        __syncthreads();
        if (it + 1 < NKIT) QKV_ISSUE((it + 1) & 1, (it + 1) * KW);

        const uint32_t stg = sb + (it & 1) * (GSTAGE * 4);

        #pragma unroll
        for (int s8 = 0; s8 < KW; s8 += 8) {
            uint32_t ah[4][4], al[4][4];
            #pragma unroll
            for (int mt = 0; mt < 4; mt++) {
                ldsm_x4(ah[mt], stg + (mt * 16 * KP + s8 + aOffW) * 4);
                ldsm_x4(al[mt], stg + (2560 + mt * 16 * KP + s8 + aOffW) * 4);
            }
            uint32_t bhf[2][4], blf[2][4];
            #pragma unroll
            for (int p = 0; p < 2; p++) {
                ldsm_x4(bhf[p], stg + (5120 + p * 16 * KP + s8 + bOffW) * 4);
                ldsm_x4(blf[p], stg + (7680 + p * 16 * KP + s8 + bOffW) * 4);
            }
            #pragma unroll
            for (int p = 0; p < 2; p++)
                #pragma unroll
                for (int hb = 0; hb < 2; hb++) {
                    int nt = 2 * p + hb;
                    #pragma unroll
                    for (int mt = 0; mt < 4; mt++) {
                        mma_bf16(acc[mt][nt], ah[mt], &bhf[p][2 * hb]);
                        mma_bf16(acc[mt][nt], al[mt], &bhf[p][2 * hb]);
                        mma_bf16(acc[mt][nt], ah[mt], &blf[p][2 * hb]);
                    }
                }
        }
    }

    // epilogue
    uint32_t* QKH = (nsel == 0) ? g_qh : g_kh;
    uint32_t* QKL = (nsel == 0) ? g_ql : g_kl;
    __nv_bfloat16* VTH = (__nv_bfloat16*)g_vth;
    __nv_bfloat16* VTL = (__nv_bfloat16*)g_vtl;
    #pragma unroll
    for (int mt = 0; mt < 4; mt++) {
        int rowA = m0 + warpM * 64 + mt * 16 + grp;
        int rowB = rowA + 8;
        #pragma unroll
        for (int nt = 0; nt < 4; nt++) {
            int c = n0c + warpN * 32 + nt * 8 + 2 * tg;
            float a0 = acc[mt][nt][0], a1 = acc[mt][nt][1];
            float a2 = acc[mt][nt][2], a3 = acc[mt][nt][3];
            if (nsel < 2) {
                int d = (c & 63) >> 1;
                int t0 = rowA & (T - 1), t1 = rowB & (T - 1);
                float c0 = cosp[t0 * 32 + d], s0 = sinp[t0 * 32 + d];
                float c1 = cosp[t1 * 32 + d], s1 = sinp[t1 * 32 + d];
                float o0 = a0 * c0 - a1 * s0, o1 = a0 * s0 + a1 * c0;
                float o2 = a2 * c1 - a3 * s1, o3 = a2 * s1 + a3 * c1;
                uint32_t hw, lw;
                splitpair(o0, o1, hw, lw);
                QKH[(size_t)rowA * C2 + (c >> 1)] = hw;
                QKL[(size_t)rowA * C2 + (c >> 1)] = lw;
                splitpair(o2, o3, hw, lw);
                QKH[(size_t)rowB * C2 + (c >> 1)] = hw;
                QKL[(size_t)rowB * C2 + (c >> 1)] = lw;
            } else {
                int bb = rowA >> 11;
                int hh = c >> 6, hd = c & 63;
                size_t base = ((size_t)(bb * H + hh) * HD + hd) * T;
                int tA = rowA & (T - 1), tB = rowB & (T - 1);
                float vals[4] = {a0, a1, a2, a3};
                size_t idxs[4] = {base + tA, base + T + tA,
                                  base + tB, base + T + tB};
                #pragma unroll
                for (int j = 0; j < 4; j++) {
                    __nv_bfloat16 hv, lv;
                    split1(vals[j], hv, lv);
                    VTH[idxs[j]] = hv;
                    VTL[idxs[j]] = lv;
                }
            }
        }
    }
}

// ---------------------------------------------------------------------------
// Output GEMM: out = att @ Wo^T, LDSM fragments.
// ---------------------------------------------------------------------------
__global__ void __launch_bounds__(256, 2) wo_gemm(float* __restrict__ out) {
    extern __shared__ uint32_t sm[];
    const int tid = threadIdx.x, lane = tid & 31, warp = tid >> 5;
    const int warpM = warp >> 2, warpN = warp & 3;
    const int grp = lane >> 2, tg = lane & 3;
    const int m0 = blockIdx.y * BM;
    const int n0 = blockIdx.x * BN;

    const int lrow = tid >> 2;
    const int lwq  = (tid & 3) << 2;
    const uint32_t sb = (uint32_t)__cvta_generic_to_shared(sm);
    const int lm = lane >> 3;
    const uint32_t aOffW = (uint32_t)((warpM * 64 + (lm & 1) * 8 + (lane & 7)) * KP
                                      + (lm >> 1) * 4);
    const uint32_t bOffW = (uint32_t)((warpN * 32 + (lm >> 1) * 8 + (lane & 7)) * KP
                                      + (lm & 1) * 4);

    float acc[4][4][4];
    #pragma unroll
    for (int mt = 0; mt < 4; mt++)
        #pragma unroll
        for (int nt = 0; nt < 4; nt++)
            #pragma unroll
            for (int i = 0; i < 4; i++) acc[mt][nt][i] = 0.f;

    #define WO_ISSUE(stg, k0w) do {                                           \
        uint32_t base_ = sb + (stg) * (GSTAGE * 4);                           \
        size_t rA0_ = (size_t)(m0 + lrow) * C2 + (k0w) + lwq;                 \
        size_t rA1_ = (size_t)(m0 + lrow + 64) * C2 + (k0w) + lwq;            \
        size_t rB0_ = (size_t)(n0 + lrow) * C2 + (k0w) + lwq;                 \
        size_t rB1_ = (size_t)(n0 + lrow + 64) * C2 + (k0w) + lwq;            \
        uint32_t dA0_ = base_ + (lrow * KP + lwq) * 4;                        \
        uint32_t dA1_ = base_ + ((lrow + 64) * KP + lwq) * 4;                 \
        cp16(dA0_, &g_ah[rA0_]);  cp16(dA1_, &g_ah[rA1_]);                    \
        cp16(dA0_ + 2560 * 4, &g_al[rA0_]);                                   \
        cp16(dA1_ + 2560 * 4, &g_al[rA1_]);                                   \
        uint32_t dB0_ = base_ + (5120 + lrow * KP + lwq) * 4;                 \
        uint32_t dB1_ = base_ + (5120 + (lrow + 64) * KP + lwq) * 4;          \
        cp16(dB0_, &g_woh[rB0_]);  cp16(dB1_, &g_woh[rB1_]);                  \
        cp16(dB0_ + 2560 * 4, &g_wol[rB0_]);                                  \
        cp16(dB1_ + 2560 * 4, &g_wol[rB1_]);                                  \
        CP_COMMIT();                                                          \
    } while (0)

    WO_ISSUE(0, 0);

    for (int it = 0; it < NKIT; it++) {
        CP_WAIT0();
        __syncthreads();
        if (it + 1 < NKIT) WO_ISSUE((it + 1) & 1, (it + 1) * KW);

        const uint32_t stg = sb + (it & 1) * (GSTAGE * 4);

        #pragma unroll
        for (int s8 = 0; s8 < KW; s8 += 8) {
            uint32_t ah[4][4], al[4][4];
            #pragma unroll
            for (int mt = 0; mt < 4; mt++) {
                ldsm_x4(ah[mt], stg + (mt * 16 * KP + s8 + aOffW) * 4);
                ldsm_x4(al[mt], stg + (2560 + mt * 16 * KP + s8 + aOffW) * 4);
            }
            uint32_t bhf[2][4], blf[2][4];
            #pragma unroll
            for (int p = 0; p < 2; p++) {
                ldsm_x4(bhf[p], stg + (5120 + p * 16 * KP + s8 + bOffW) * 4);
                ldsm_x4(blf[p], stg + (7680 + p * 16 * KP + s8 + bOffW) * 4);
            }
            #pragma unroll
            for (int p = 0; p < 2; p++)
                #pragma unroll
                for (int hb = 0; hb < 2; hb++) {
                    int nt = 2 * p + hb;
                    #pragma unroll
                    for (int mt = 0; mt < 4; mt++) {
                        mma_bf16(acc[mt][nt], ah[mt], &bhf[p][2 * hb]);
                        mma_bf16(acc[mt][nt], al[mt], &bhf[p][2 * hb]);
                        mma_bf16(acc[mt][nt], ah[mt], &blf[p][2 * hb]);
                    }
                }
        }
    }

    #pragma unroll
    for (int mt = 0; mt < 4; mt++) {
        int rowA = m0 + warpM * 64 + mt * 16 + grp;
        #pragma unroll
        for (int nt = 0; nt < 4; nt++) {
            int c = n0 + warpN * 32 + nt * 8 + 2 * tg;
            *(float2*)&out[(size_t)rowA * C + c] =
                make_float2(acc[mt][nt][0], acc[mt][nt][1]);
            *(float2*)&out[(size_t)(rowA + 8) * C + c] =
                make_float2(acc[mt][nt][2], acc[mt][nt][3]);
        }
    }
}

// ---------------------------------------------------------------------------
// Causal flash attention: full bf16 3-term, KB=64 tiles, LDSM K/V fragments,
// occupancy 3.
// ---------------------------------------------------------------------------
#define QB 64
#define KB 64
#define KSW 36
#define VSW 36
#define AST_KL 2304
#define AST_VH 4608
#define AST_VL 6912
#define ASTAGE 9216

__global__ void __launch_bounds__(128, 3) attn_kernel() {
    extern __shared__ uint32_t sm[];

    const int tid  = threadIdx.x;
    const int lane = tid & 31;
    const int warp = tid >> 5;
    const int grp  = lane >> 2;
    const int tg   = lane & 3;
    const int bh   = blockIdx.y;
    const int b    = bh >> 4, h = bh & 15;
    const int qx   = gridDim.x - 1 - (int)blockIdx.x;   // heavy blocks first
    const int q0   = qx * QB;
    const int r0   = q0 + warp * 16;
    const uint32_t sb = (uint32_t)__cvta_generic_to_shared(sm);
    const size_t vbase = ((size_t)(b * H + h)) * HD * T2;
    // ldmatrix lane addressing for K/V B-fragments (words)
    const int lm = lane >> 3;
    const uint32_t kOffW = (uint32_t)(((lm >> 1) * 8 + (lane & 7)) * KSW
                                      + (lm & 1) * 4);
    const uint32_t vOffW = (uint32_t)(((lm >> 1) * 8 + (lane & 7)) * VSW
                                      + (lm & 1) * 4);

    uint32_t qfh[4][4], qfl[4][4];
    {
        const uint32_t* QHa = g_qh + ((size_t)(b * T + r0)) * C2 + h * 32;
        const uint32_t* QLa = g_ql + ((size_t)(b * T + r0)) * C2 + h * 32;
        #pragma unroll
        for (int ks = 0; ks < 4; ks++) {
            qfh[ks][0] = QHa[(size_t)grp * C2 + ks * 8 + tg];
            qfh[ks][1] = QHa[(size_t)(grp + 8) * C2 + ks * 8 + tg];
            qfh[ks][2] = QHa[(size_t)grp * C2 + ks * 8 + tg + 4];
            qfh[ks][3] = QHa[(size_t)(grp + 8) * C2 + ks * 8 + tg + 4];
            qfl[ks][0] = QLa[(size_t)grp * C2 + ks * 8 + tg];
            qfl[ks][1] = QLa[(size_t)(grp + 8) * C2 + ks * 8 + tg];
            qfl[ks][2] = QLa[(size_t)grp * C2 + ks * 8 + tg + 4];
            qfl[ks][3] = QLa[(size_t)(grp + 8) * C2 + ks * 8 + tg + 4];
        }
    }

    float out[8][4];
    #pragma unroll
    for (int i = 0; i < 8; i++)
        #pragma unroll
        for (int j = 0; j < 4; j++) out[i][j] = 0.f;
    float m0v = -1e30f, m1v = -1e30f, l0 = 0.f, l1 = 0.f;

    const int nIter = qx + 1;

    #define ATT_ISSUE(stg, k0) do {                                           \
        uint32_t base_ = sb + (stg) * (ASTAGE * 4);                           \
        _Pragma("unroll")                                                     \
        for (int i_ = 0; i_ < 4; i_++) {                                      \
            int idk_ = tid + i_ * 128;                                        \
            int krow_ = idk_ >> 3, kwq_ = (idk_ & 7) << 2;                    \
            size_t koff_ = ((size_t)(b * T + (k0) + krow_)) * C2 + h * 32 + kwq_; \
            cp16(base_ + (krow_ * KSW + kwq_) * 4, &g_kh[koff_]);             \
            cp16(base_ + (AST_KL + krow_ * KSW + kwq_) * 4, &g_kl[koff_]);    \
            size_t voff_ = vbase + (size_t)krow_ * T2 + ((k0) >> 1) + kwq_;   \
            cp16(base_ + (AST_VH + krow_ * VSW + kwq_) * 4, &g_vth[voff_]);   \
            cp16(base_ + (AST_VL + krow_ * VSW + kwq_) * 4, &g_vtl[voff_]);   \
        }                                                                     \
        CP_COMMIT();                                                          \
    } while (0)

    ATT_ISSUE(0, 0);

    for (int t = 0; t < nIter; t++) {
        const int k0 = t * KB;
        CP_WAIT0();
        __syncthreads();
        if (t + 1 < nIter) ATT_ISSUE((t + 1) & 1, (t + 1) * KB);

        if (k0 > r0 + 15) continue;

        const uint32_t stg = sb + (t & 1) * (ASTAGE * 4);

        // ---- S = Q K^T (16 x 64), bf16 3-term, LDSM K fragments ----
        float s[8][4];
        #pragma unroll
        for (int nt = 0; nt < 8; nt++)
            #pragma unroll
            for (int j = 0; j < 4; j++) s[nt][j] = 0.f;

        #pragma unroll
        for (int ks = 0; ks < 4; ks++) {
            uint32_t kh4[4][4], kl4[4][4];
            #pragma unroll
            for (int p = 0; p < 4; p++) {
                ldsm_x4(kh4[p], stg + (p * 16 * KSW + ks * 8 + kOffW) * 4);
                ldsm_x4(kl4[p], stg + (AST_KL * 4) + (p * 16 * KSW + ks * 8 + kOffW) * 4);
            }
            #pragma unroll
            for (int p = 0; p < 4; p++)
                #pragma unroll
                for (int hb = 0; hb < 2; hb++) {
                    int nt = 2 * p + hb;
                    mma_bf16(s[nt], qfh[ks], &kh4[p][2 * hb]);
                    mma_bf16(s[nt], qfl[ks], &kh4[p][2 * hb]);
                    mma_bf16(s[nt], qfh[ks], &kl4[p][2 * hb]);
                }
        }

        // ---- scale + causal mask ----
        const int row0 = r0 + grp, row1 = r0 + grp + 8;
        if (k0 + KB - 1 <= r0) {
            #pragma unroll
            for (int nt = 0; nt < 8; nt++)
                #pragma unroll
                for (int j = 0; j < 4; j++) s[nt][j] *= 0.125f;
        } else {
            #pragma unroll
            for (int nt = 0; nt < 8; nt++) {
                int col = k0 + nt * 8 + 2 * tg;
                s[nt][0] = (col     <= row0) ? s[nt][0] * 0.125f : -1e30f;
                s[nt][1] = (col + 1 <= row0) ? s[nt][1] * 0.125f : -1e30f;
                s[nt][2] = (col     <= row1) ? s[nt][2] * 0.125f : -1e30f;
                s[nt][3] = (col + 1 <= row1) ? s[nt][3] * 0.125f : -1e30f;
            }
        }

        // ---- online softmax ----
        float mx0 = s[0][0], mx1 = s[0][2];
        #pragma unroll
        for (int nt = 0; nt < 8; nt++) {
            mx0 = fmaxf(mx0, fmaxf(s[nt][0], s[nt][1]));
            mx1 = fmaxf(mx1, fmaxf(s[nt][2], s[nt][3]));
        }
        mx0 = fmaxf(mx0, __shfl_xor_sync(0xffffffffu, mx0, 1));
        mx0 = fmaxf(mx0, __shfl_xor_sync(0xffffffffu, mx0, 2));
        mx1 = fmaxf(mx1, __shfl_xor_sync(0xffffffffu, mx1, 1));
        mx1 = fmaxf(mx1, __shfl_xor_sync(0xffffffffu, mx1, 2));
        float nm0 = fmaxf(m0v, mx0), nm1 = fmaxf(m1v, mx1);
        float c0 = __expf(m0v - nm0), c1 = __expf(m1v - nm1);

        float sum0 = 0.f, sum1 = 0.f;
        #pragma unroll
        for (int nt = 0; nt < 8; nt++) {
            s[nt][0] = __expf(s[nt][0] - nm0);
            s[nt][1] = __expf(s[nt][1] - nm0);
            s[nt][2] = __expf(s[nt][2] - nm1);
            s[nt][3] = __expf(s[nt][3] - nm1);
            sum0 += s[nt][0] + s[nt][1];
            sum1 += s[nt][2] + s[nt][3];
        }
        sum0 += __shfl_xor_sync(0xffffffffu, sum0, 1);
        sum0 += __shfl_xor_sync(0xffffffffu, sum0, 2);
        sum1 += __shfl_xor_sync(0xffffffffu, sum1, 1);
        sum1 += __shfl_xor_sync(0xffffffffu, sum1, 2);
        l0 = l0 * c0 + sum0;
        l1 = l1 * c1 + sum1;
        m0v = nm0; m1v = nm1;

        #pragma unroll
        for (int i = 0; i < 8; i++) {
            out[i][0] *= c0; out[i][1] *= c0;
            out[i][2] *= c1; out[i][3] *= c1;
        }

        // ---- PV: bf16 3-term, LDSM V fragments ----
        #pragma unroll
        for (int ks = 0; ks < 4; ks++) {
            uint32_t ph[4], pl[4];
            splitpair(s[2 * ks][0],     s[2 * ks][1],     ph[0], pl[0]);
            splitpair(s[2 * ks][2],     s[2 * ks][3],     ph[1], pl[1]);
            splitpair(s[2 * ks + 1][0], s[2 * ks + 1][1], ph[2], pl[2]);
            splitpair(s[2 * ks + 1][2], s[2 * ks + 1][3], ph[3], pl[3]);
            uint32_t vh4[4][4], vl4[4][4];
            #pragma unroll
            for (int p = 0; p < 4; p++) {
                ldsm_x4(vh4[p], stg + (AST_VH * 4) + (p * 16 * VSW + ks * 8 + vOffW) * 4);
                ldsm_x4(vl4[p], stg + (AST_VL * 4) + (p * 16 * VSW + ks * 8 + vOffW) * 4);
            }
            #pragma unroll
            for (int p = 0; p < 4; p++)
                #pragma unroll
                for (int hb = 0; hb < 2; hb++) {
                    int ntv = 2 * p + hb;
                    mma_bf16(out[ntv], ph, &vh4[p][2 * hb]);
                    mma_bf16(out[ntv], pl, &vh4[p][2 * hb]);
                    mma_bf16(out[ntv], ph, &vl4[p][2 * hb]);
                }
        }
    }

    // normalize + bf16 splitpair + packed store
    float inv0 = 1.f / l0, inv1 = 1.f / l1;
    size_t rA = ((size_t)(b * T + r0 + grp)) * C2 + h * 32;
    size_t rB = ((size_t)(b * T + r0 + grp + 8)) * C2 + h * 32;
    #pragma unroll
    for (int ntv = 0; ntv < 8; ntv++) {
        int cw = ntv * 4 + tg;
        uint32_t hw, lw;
        splitpair(out[ntv][0] * inv0, out[ntv][1] * inv0, hw, lw);
        g_ah[rA + cw] = hw;
        g_al[rA + cw] = lw;
        splitpair(out[ntv][2] * inv1, out[ntv][3] * inv1, hw, lw);
        g_ah[rB + cw] = hw;
        g_al[rB + cw] = lw;
    }
}

// ---------------------------------------------------------------------------
extern "C" void kernel_launch(void* const* d_in, const int* in_sizes, int n_in,
                              void* d_out, int out_size) {
    const float* x    = (const float*)d_in[0];
    const float* Wq   = (const float*)d_in[1];
    const float* Wk   = (const float*)d_in[2];
    const float* Wv   = (const float*)d_in[3];
    const float* Wo   = (const float*)d_in[4];
    const float* cosp = (const float*)d_in[5];
    const float* sinp = (const float*)d_in[6];
    float* out = (float*)d_out;

    static bool attr_done = false;
    if (!attr_done) {
        cudaFuncSetAttribute(qkv_gemm,
            cudaFuncAttributeMaxDynamicSharedMemorySize, 2 * GSTAGE * 4);
        cudaFuncSetAttribute(wo_gemm,
            cudaFuncAttributeMaxDynamicSharedMemorySize, 2 * GSTAGE * 4);
        cudaFuncSetAttribute(attn_kernel,
            cudaFuncAttributeMaxDynamicSharedMemorySize, 2 * ASTAGE * 4);
        attr_done = true;
    }

    int nx4 = M_TOT * C / 4;
    int nw4 = C * C / 4;
    split5_kernel<<<dim3(nx4 / 256, 5), 256>>>(
        (const float4*)x, (const float4*)Wq, (const float4*)Wk,
        (const float4*)Wv, (const float4*)Wo, nx4, nw4);

    qkv_gemm<<<dim3(24, M_TOT / BM), 256, 2 * GSTAGE * 4>>>(cosp, sinp);

    attn_kernel<<<dim3(T / QB, B * H), 128, 2 * ASTAGE * 4>>>();

    wo_gemm<<<dim3(C / BN, M_TOT / BM), 256, 2 * GSTAGE * 4>>>(out);
}